// round 4
// baseline (speedup 1.0000x reference)
#include <cuda_runtime.h>
#include <cstdint>

// ---------------- problem dims ----------------
#define N_NODES 61440
#define NEDGE   491520
#define BATCH   2048
#define TT      30
#define INCH    12
#define FCF     3840     // 128*30
#define FCO     72

typedef unsigned long long ull;

// packed f32x2 FMA: d = a*b + c  (2 fp32 FMAs per lane per issue)
#define FMA2(d, a, b, c) \
    asm("fma.rn.f32x2 %0, %1, %2, %3;" : "=l"(d) : "l"(a), "l"(b), "l"(c))
#define UNPACK2(lo, hi, in) \
    asm("mov.b64 {%0, %1}, %2;" : "=f"(lo), "=f"(hi) : "l"(in))

// ---------------- device scratch ----------------
__device__ float g_deg [N_NODES];
__device__ float g_dinv[N_NODES];
__device__ float g_h   [N_NODES * 12];
__device__ __align__(16) float g_x0  [N_NODES * 12];            // [B][12][30]
__device__ __align__(16) float g_x1  [BATCH * 128 * TT];        // [B][128][30]
__device__ __align__(16) float g_x2  [BATCH * 512 * TT];        // [B][512][30]
__device__ __align__(16) float g_x3  [BATCH * 128 * TT];        // [B][128][30] (relu'd)
__device__ __align__(16) float g_wt0 [12  * 4 * 128];           // [ic][j][oc], j=0..2 conv, j=3 down
__device__ __align__(16) float g_wt1 [128 * 4 * 512];
__device__ __align__(16) float g_wt2 [512 * 4 * 128];
__device__ __align__(16) float g_fcwT[FCF * FCO];               // [f][o]
__device__ int   g_eflag[1];                                    // 1 => edge_index is int32

// ---------------- init / dtype detect ----------------
__global__ void k_init() {
    int i = blockIdx.x * blockDim.x + threadIdx.x;
    if (i < N_NODES * 12) g_x0[i] = 0.0f;
    if (i < N_NODES)      g_deg[i] = 1.0f;     // self-loop
    if (i == 0)           g_eflag[0] = 0;
}

__global__ void k_detect(const long long* __restrict__ ep) {
    int i = blockIdx.x * blockDim.x + threadIdx.x;
    if (i < 2048) {
        long long v = ep[i];
        if (v < 0 || v >= N_NODES) atomicOr(g_eflag, 1);
    }
}

__device__ __forceinline__ void load_edge(const void* ep, int e, int& s, int& d) {
    if (g_eflag[0]) {
        const int* p = (const int*)ep;
        s = p[e]; d = p[NEDGE + e];
    } else {
        const long long* p = (const long long*)ep;
        s = (int)p[e]; d = (int)p[NEDGE + e];
    }
}

// ---------------- weight transposes ----------------
__global__ void k_twt(const float* __restrict__ cw, const float* __restrict__ dw,
                      float* __restrict__ wt, int OC, int IC) {
    int id = blockIdx.x * blockDim.x + threadIdx.x;
    int tot = OC * IC * 4;
    if (id >= tot) return;
    int oc = id % OC;
    int r  = id / OC;
    int j  = r % 4;
    int ic = r / 4;
    wt[id] = (j < 3) ? cw[(oc * IC + ic) * 3 + j] : dw[oc * IC + ic];
}

__global__ void k_tfc(const float* __restrict__ fw, float* __restrict__ wT) {
    int id = blockIdx.x * blockDim.x + threadIdx.x;
    if (id >= FCF * FCO) return;
    int o = id % FCO;
    int f = id / FCO;
    wT[id] = fw[o * FCF + f];
}

// ---------------- GCN ----------------
__global__ void k_deg(const void* __restrict__ ep) {
    int e = blockIdx.x * blockDim.x + threadIdx.x;
    if (e >= NEDGE) return;
    int s, d;
    load_edge(ep, e, s, d);
    atomicAdd(&g_deg[d], 1.0f);
}

__global__ void k_h(const float* __restrict__ x, const float* __restrict__ gw) {
    int n = blockIdx.x * blockDim.x + threadIdx.x;
    if (n >= N_NODES) return;
    const float4* xp = (const float4*)(x + (size_t)n * 12);
    float4 a = xp[0], b = xp[1], c = xp[2];
    float xv[12] = {a.x,a.y,a.z,a.w, b.x,b.y,b.z,b.w, c.x,c.y,c.z,c.w};
    #pragma unroll
    for (int o = 0; o < 12; ++o) {
        float acc = 0.0f;
        #pragma unroll
        for (int i = 0; i < 12; ++i)
            acc = fmaf(xv[i], __ldg(&gw[o * 12 + i]), acc);
        g_h[n * 12 + o] = acc;
    }
    g_dinv[n] = rsqrtf(g_deg[n]);
}

__global__ void k_scatter(const void* __restrict__ ep) {
    int e = blockIdx.x * blockDim.x + threadIdx.x;
    if (e >= NEDGE) return;
    int s, d;
    load_edge(ep, e, s, d);
    float nm = g_dinv[s] * g_dinv[d];
    int base = (d / 30) * (12 * TT) + (d % 30);
    const float4* hp = (const float4*)(g_h + (size_t)s * 12);
    float4 a = hp[0], b = hp[1], c = hp[2];
    float hv[12] = {a.x,a.y,a.z,a.w, b.x,b.y,b.z,b.w, c.x,c.y,c.z,c.w};
    #pragma unroll
    for (int cch = 0; cch < 12; ++cch)
        atomicAdd(&g_x0[base + cch * TT], nm * hv[cch]);
}

__global__ void k_self(const float* __restrict__ gb) {
    int n = blockIdx.x * blockDim.x + threadIdx.x;
    if (n >= N_NODES) return;
    float di = g_dinv[n];
    float nm = di * di;
    int base = (n / 30) * (12 * TT) + (n % 30);
    #pragma unroll
    for (int c = 0; c < 12; ++c)
        g_x0[base + c * TT] += nm * g_h[n * 12 + c] + __ldg(&gb[c]);
}

// ---------------- TCN block, f32x2 packed (channel-pair) version ----------------
// thread <-> PAIR of adjacent output channels; all 30 timesteps accumulated as
// packed f32x2 (chan-pair) registers. Input tile stored pre-duplicated (v,v) in
// smem so the inner loop is LDS.64(broadcast) + FFMA2 only (no packing movs).
template<int IC, int ICC, int DIL, int NPAIR, int OCTOT>
__global__ __launch_bounds__(NPAIR)
void tcn2_kernel(const float* __restrict__ Xin, const float* __restrict__ wt,
                 const float* __restrict__ cb, const float* __restrict__ db,
                 float* __restrict__ Xout) {
    __shared__ float2 xs2[ICC * TT];           // duplicated pairs (v, v)
    int b = blockIdx.x;
    int p = blockIdx.y * NPAIR + threadIdx.x;  // output-channel pair index

    ull accC[TT], accR[TT];
    #pragma unroll
    for (int t = 0; t < TT; ++t) { accC[t] = 0ull; accR[t] = 0ull; }

    #pragma unroll 1
    for (int ch = 0; ch < IC / ICC; ++ch) {
        __syncthreads();
        const float* src = Xin + ((size_t)b * IC + ch * ICC) * TT;
        for (int i = threadIdx.x; i < ICC * TT; i += NPAIR) {
            float v = src[i];
            xs2[i] = make_float2(v, v);
        }
        __syncthreads();
        const ull* xsu = (const ull*)xs2;

        #pragma unroll 2
        for (int icl = 0; icl < ICC; ++icl) {
            const ull* wpu = (const ull*)(wt + ((size_t)(ch * ICC + icl) * 4) * OCTOT);
            ull w0p = __ldg(wpu + p);
            ull w1p = __ldg(wpu + OCTOT / 2 + p);
            ull w2p = __ldg(wpu + OCTOT + p);
            ull wdp = __ldg(wpu + 3 * (OCTOT / 2) + p);
            #pragma unroll
            for (int t = 0; t < TT; ++t) {
                ull xv2 = xsu[icl * TT + t];
                FMA2(accC[t], w2p, xv2, accC[t]);
                if (t + DIL < TT)     FMA2(accC[t + DIL],     w1p, xv2, accC[t + DIL]);
                if (t + 2 * DIL < TT) FMA2(accC[t + 2 * DIL], w0p, xv2, accC[t + 2 * DIL]);
                FMA2(accR[t], wdp, xv2, accR[t]);
            }
        }
    }

    float2 bcp = __ldg((const float2*)cb + p);
    float2 bdp = __ldg((const float2*)db + p);
    float* dst0 = Xout + ((size_t)b * OCTOT + 2 * p) * TT;
    float* dst1 = dst0 + TT;
    #pragma unroll
    for (int t = 0; t < TT; ++t) {
        float c0, c1, r0, r1;
        UNPACK2(c0, c1, accC[t]);
        UNPACK2(r0, r1, accR[t]);
        float o0 = fmaxf(c0 + bcp.x, 0.0f);
        float o1 = fmaxf(c1 + bcp.y, 0.0f);
        dst0[t] = fmaxf(o0 + r0 + bdp.x, 0.0f);
        dst1[t] = fmaxf(o1 + r1 + bdp.y, 0.0f);
    }
}

// ---------------- FC: out[b][o] = sum_f X3[b][f] * fcwT[f][o] + fb[o] ----------------
#define FC_NB 8
#define FC_CH 480
__global__ __launch_bounds__(288)
void fc_kernel(const float* __restrict__ X, const float* __restrict__ wT,
               const float* __restrict__ fb, float* __restrict__ out) {
    __shared__ float xsf[FC_CH * FC_NB];          // [f_local][b]
    __shared__ float red[4 * FC_NB * FCO];        // [q][b][o]
    int o   = threadIdx.x;
    int q   = threadIdx.y;
    int tid = q * FCO + o;
    int b0  = blockIdx.x * FC_NB;

    float acc[FC_NB];
    #pragma unroll
    for (int i = 0; i < FC_NB; ++i) acc[i] = 0.0f;

    #pragma unroll 1
    for (int ch = 0; ch < FCF / FC_CH; ++ch) {
        __syncthreads();
        for (int i = tid; i < FC_CH * FC_NB; i += 288) {
            int bb = i / FC_CH;
            int fl = i % FC_CH;
            xsf[fl * FC_NB + bb] = X[(size_t)(b0 + bb) * FCF + ch * FC_CH + fl];
        }
        __syncthreads();
        #pragma unroll 4
        for (int i = 0; i < FC_CH / 4; ++i) {
            int fl = i * 4 + q;
            float w = __ldg(&wT[(size_t)(ch * FC_CH + fl) * FCO + o]);
            const float4* xp = (const float4*)&xsf[fl * FC_NB];
            float4 xa = xp[0], xb = xp[1];
            acc[0] = fmaf(w, xa.x, acc[0]);
            acc[1] = fmaf(w, xa.y, acc[1]);
            acc[2] = fmaf(w, xa.z, acc[2]);
            acc[3] = fmaf(w, xa.w, acc[3]);
            acc[4] = fmaf(w, xb.x, acc[4]);
            acc[5] = fmaf(w, xb.y, acc[5]);
            acc[6] = fmaf(w, xb.z, acc[6]);
            acc[7] = fmaf(w, xb.w, acc[7]);
        }
    }
    #pragma unroll
    for (int bb = 0; bb < FC_NB; ++bb)
        red[(q * FC_NB + bb) * FCO + o] = acc[bb];
    __syncthreads();
    for (int idx = tid; idx < FC_NB * FCO; idx += 288) {
        int bb = idx / FCO;
        int oo = idx % FCO;
        float s = red[(0 * FC_NB + bb) * FCO + oo]
                + red[(1 * FC_NB + bb) * FCO + oo]
                + red[(2 * FC_NB + bb) * FCO + oo]
                + red[(3 * FC_NB + bb) * FCO + oo];
        out[(size_t)(b0 + bb) * FCO + oo] = s + __ldg(&fb[oo]);
    }
}

// ---------------- launch ----------------
extern "C" void kernel_launch(void* const* d_in, const int* in_sizes, int n_in,
                              void* d_out, int out_size) {
    const float* x       = (const float*)d_in[0];
    const void*  eidx    = d_in[1];
    const float* gcn_w   = (const float*)d_in[2];
    const float* gcn_b   = (const float*)d_in[3];
    const float* conv_w0 = (const float*)d_in[4];
    const float* conv_b0 = (const float*)d_in[5];
    const float* down_w0 = (const float*)d_in[6];
    const float* down_b0 = (const float*)d_in[7];
    const float* conv_w1 = (const float*)d_in[8];
    const float* conv_b1 = (const float*)d_in[9];
    const float* down_w1 = (const float*)d_in[10];
    const float* down_b1 = (const float*)d_in[11];
    const float* conv_w2 = (const float*)d_in[12];
    const float* conv_b2 = (const float*)d_in[13];
    const float* down_w2 = (const float*)d_in[14];
    const float* down_b2 = (const float*)d_in[15];
    const float* fc_w    = (const float*)d_in[16];
    const float* fc_b    = (const float*)d_in[17];
    float* out = (float*)d_out;

    float *p_wt0, *p_wt1, *p_wt2, *p_fcwT;
    cudaGetSymbolAddress((void**)&p_wt0,  g_wt0);
    cudaGetSymbolAddress((void**)&p_wt1,  g_wt1);
    cudaGetSymbolAddress((void**)&p_wt2,  g_wt2);
    cudaGetSymbolAddress((void**)&p_fcwT, g_fcwT);
    float *p_x0, *p_x1, *p_x2, *p_x3;
    cudaGetSymbolAddress((void**)&p_x0, g_x0);
    cudaGetSymbolAddress((void**)&p_x1, g_x1);
    cudaGetSymbolAddress((void**)&p_x2, g_x2);
    cudaGetSymbolAddress((void**)&p_x3, g_x3);

    // init + edge dtype detect
    k_init<<<(N_NODES * 12 + 255) / 256, 256>>>();
    k_detect<<<8, 256>>>((const long long*)eidx);

    // weight prep (independent)
    k_twt<<<(128 * 12 * 4 + 255) / 256, 256>>>(conv_w0, down_w0, p_wt0, 128, 12);
    k_twt<<<(512 * 128 * 4 + 255) / 256, 256>>>(conv_w1, down_w1, p_wt1, 512, 128);
    k_twt<<<(128 * 512 * 4 + 255) / 256, 256>>>(conv_w2, down_w2, p_wt2, 128, 512);
    k_tfc<<<(FCF * FCO + 255) / 256, 256>>>(fc_w, p_fcwT);

    // GCN
    k_deg<<<(NEDGE + 255) / 256, 256>>>(eidx);
    k_h<<<(N_NODES + 127) / 128, 128>>>(x, gcn_w);
    k_scatter<<<(NEDGE + 127) / 128, 128>>>(eidx);
    k_self<<<(N_NODES + 127) / 128, 128>>>(gcn_b);

    // TCN blocks (f32x2 packed, channel-pair per thread)
    tcn2_kernel<12,  12,  1,  64, 128><<<dim3(BATCH, 1),  64>>>(p_x0, p_wt0, conv_b0, down_b0, p_x1);
    tcn2_kernel<128, 128, 3, 256, 512><<<dim3(BATCH, 1), 256>>>(p_x1, p_wt1, conv_b1, down_b1, p_x2);
    tcn2_kernel<512, 128, 9,  64, 128><<<dim3(BATCH, 1),  64>>>(p_x2, p_wt2, conv_b2, down_b2, p_x3);

    // FC
    fc_kernel<<<BATCH / FC_NB, dim3(FCO, 4)>>>(p_x3, p_fcwT, fc_b, out);
}

// round 6
// speedup vs baseline: 1.7321x; 1.7321x over previous
#include <cuda_runtime.h>
#include <cuda_bf16.h>
#include <cstdint>

// ---------------- problem dims ----------------
#define N_NODES 61440
#define NEDGE   491520
#define BATCH   2048
#define TT      30
#define INCH    12
#define FCF     3840
#define FCO     72
#define NTOT    (BATCH * TT)

// ---------------- mma helpers (base PTX ISA: works on compute_103) ----------------
__device__ __forceinline__ uint32_t smem_u32(const void* p) {
    uint32_t a;
    asm("{ .reg .u64 t; cvta.to.shared.u64 t, %1; cvt.u32.u64 %0, t; }" : "=r"(a) : "l"(p));
    return a;
}
#define LDSM_X4(r0, r1, r2, r3, addr) \
    asm volatile("ldmatrix.sync.aligned.m8n8.x4.shared.b16 {%0,%1,%2,%3}, [%4];" \
        : "=r"(r0), "=r"(r1), "=r"(r2), "=r"(r3) : "r"(addr))
#define MMA_BF16(acc, a, b0_, b1_) \
    asm volatile("mma.sync.aligned.m16n8k16.row.col.f32.bf16.bf16.f32 " \
        "{%0,%1,%2,%3}, {%4,%5,%6,%7}, {%8,%9}, {%0,%1,%2,%3};" \
        : "+f"((acc)[0]), "+f"((acc)[1]), "+f"((acc)[2]), "+f"((acc)[3]) \
        : "r"((a)[0]), "r"((a)[1]), "r"((a)[2]), "r"((a)[3]), "r"(b0_), "r"(b1_))
#define CVT_BF16X2(dst, a, b) \
    asm("cvt.rn.bf16x2.f32 %0, %1, %2;" : "=r"(dst) : "f"(b), "f"(a))

// ---------------- device scratch ----------------
__device__ float g_deg [N_NODES];
__device__ float g_dinv[N_NODES];
__device__ float g_h   [N_NODES * 12];
__device__ __align__(16) float g_x0  [N_NODES * 12];
__device__ __align__(16) float g_x1  [BATCH * 128 * TT];
__device__ __align__(16) float g_x2  [BATCH * 512 * TT];
__device__ __align__(16) float g_x3  [BATCH * 128 * TT];
__device__ __align__(16) float g_wt0 [12 * 4 * 128];
__device__ __align__(16) float g_fcwT[FCF * FCO];
__device__ int   g_eflag[1];

// bf16 split weights, [oc][k] with k = j*IC + ic (j-major)
__device__ __align__(16) __nv_bfloat16 g_wc1h[512 * 384];
__device__ __align__(16) __nv_bfloat16 g_wc1l[512 * 384];
__device__ __align__(16) __nv_bfloat16 g_wd1h[512 * 128];
__device__ __align__(16) __nv_bfloat16 g_wd1l[512 * 128];
__device__ __align__(16) __nv_bfloat16 g_wc2h[128 * 1536];
__device__ __align__(16) __nv_bfloat16 g_wc2l[128 * 1536];
__device__ __align__(16) __nv_bfloat16 g_wd2h[128 * 512];
__device__ __align__(16) __nv_bfloat16 g_wd2l[128 * 512];

// ---------------- init / dtype detect ----------------
__global__ void k_init() {
    int i = blockIdx.x * blockDim.x + threadIdx.x;
    if (i < N_NODES * 12) g_x0[i] = 0.0f;
    if (i < N_NODES)      g_deg[i] = 1.0f;
    if (i == 0)           g_eflag[0] = 0;
}
__global__ void k_detect(const long long* __restrict__ ep) {
    int i = blockIdx.x * blockDim.x + threadIdx.x;
    if (i < 2048) {
        long long v = ep[i];
        if (v < 0 || v >= N_NODES) atomicOr(g_eflag, 1);
    }
}
__device__ __forceinline__ void load_edge(const void* ep, int e, int& s, int& d) {
    if (g_eflag[0]) {
        const int* p = (const int*)ep;
        s = p[e]; d = p[NEDGE + e];
    } else {
        const long long* p = (const long long*)ep;
        s = (int)p[e]; d = (int)p[NEDGE + e];
    }
}

// ---------------- weight prep ----------------
__global__ void k_twt(const float* __restrict__ cw, const float* __restrict__ dw,
                      float* __restrict__ wt, int OC, int IC) {
    int id = blockIdx.x * blockDim.x + threadIdx.x;
    int tot = OC * IC * 4;
    if (id >= tot) return;
    int oc = id % OC;
    int r  = id / OC;
    int j  = r % 4;
    int ic = r / 4;
    wt[id] = (j < 3) ? cw[(oc * IC + ic) * 3 + j] : dw[oc * IC + ic];
}
__global__ void k_tfc(const float* __restrict__ fw, float* __restrict__ wT) {
    int id = blockIdx.x * blockDim.x + threadIdx.x;
    if (id >= FCF * FCO) return;
    int o = id % FCO;
    int f = id / FCO;
    wT[id] = fw[o * FCF + f];
}
__global__ void k_wsplit3(const float* __restrict__ w, __nv_bfloat16* __restrict__ hi,
                          __nv_bfloat16* __restrict__ lo, int OC, int IC) {
    int id = blockIdx.x * blockDim.x + threadIdx.x;
    if (id >= OC * IC * 3) return;
    int K  = 3 * IC;
    int oc = id / K;
    int r  = id % K;
    int j  = r / IC;
    int ic = r % IC;
    float v = w[(oc * IC + ic) * 3 + j];
    __nv_bfloat16 h = __float2bfloat16(v);
    hi[id] = h;
    lo[id] = __float2bfloat16(v - __bfloat162float(h));
}
__global__ void k_wsplit1(const float* __restrict__ w, __nv_bfloat16* __restrict__ hi,
                          __nv_bfloat16* __restrict__ lo, int n) {
    int id = blockIdx.x * blockDim.x + threadIdx.x;
    if (id >= n) return;
    float v = w[id];
    __nv_bfloat16 h = __float2bfloat16(v);
    hi[id] = h;
    lo[id] = __float2bfloat16(v - __bfloat162float(h));
}

// ---------------- GCN ----------------
__global__ void k_deg(const void* __restrict__ ep) {
    int e = blockIdx.x * blockDim.x + threadIdx.x;
    if (e >= NEDGE) return;
    int s, d;
    load_edge(ep, e, s, d);
    atomicAdd(&g_deg[d], 1.0f);
}
__global__ void k_h(const float* __restrict__ x, const float* __restrict__ gw) {
    int n = blockIdx.x * blockDim.x + threadIdx.x;
    if (n >= N_NODES) return;
    const float4* xp = (const float4*)(x + (size_t)n * 12);
    float4 a = xp[0], b = xp[1], c = xp[2];
    float xv[12] = {a.x,a.y,a.z,a.w, b.x,b.y,b.z,b.w, c.x,c.y,c.z,c.w};
    #pragma unroll
    for (int o = 0; o < 12; ++o) {
        float acc = 0.0f;
        #pragma unroll
        for (int i = 0; i < 12; ++i)
            acc = fmaf(xv[i], __ldg(&gw[o * 12 + i]), acc);
        g_h[n * 12 + o] = acc;
    }
    g_dinv[n] = rsqrtf(g_deg[n]);
}
__global__ void k_scatter(const void* __restrict__ ep) {
    int e = blockIdx.x * blockDim.x + threadIdx.x;
    if (e >= NEDGE) return;
    int s, d;
    load_edge(ep, e, s, d);
    float nm = g_dinv[s] * g_dinv[d];
    int base = (d / 30) * (12 * TT) + (d % 30);
    const float4* hp = (const float4*)(g_h + (size_t)s * 12);
    float4 a = hp[0], b = hp[1], c = hp[2];
    float hv[12] = {a.x,a.y,a.z,a.w, b.x,b.y,b.z,b.w, c.x,c.y,c.z,c.w};
    #pragma unroll
    for (int cch = 0; cch < 12; ++cch)
        atomicAdd(&g_x0[base + cch * TT], nm * hv[cch]);
}
__global__ void k_self(const float* __restrict__ gb) {
    int n = blockIdx.x * blockDim.x + threadIdx.x;
    if (n >= N_NODES) return;
    float di = g_dinv[n];
    float nm = di * di;
    int base = (n / 30) * (12 * TT) + (n % 30);
    #pragma unroll
    for (int c = 0; c < 12; ++c)
        g_x0[base + c * TT] += nm * g_h[n * 12 + c] + __ldg(&gb[c]);
}

// ---------------- block 0: scalar TCN (IC=12, small) ----------------
template<int IC, int ICC, int DIL, int OCT, int OCTOT>
__global__ __launch_bounds__(OCT)
void tcn_kernel(const float* __restrict__ Xin, const float* __restrict__ wt,
                const float* __restrict__ cb, const float* __restrict__ db,
                float* __restrict__ Xout) {
    __shared__ float xs[ICC * TT];
    int b  = blockIdx.x;
    int oc = blockIdx.y * OCT + threadIdx.x;

    float accC[TT], accR[TT];
    #pragma unroll
    for (int t = 0; t < TT; ++t) { accC[t] = 0.0f; accR[t] = 0.0f; }

    #pragma unroll 1
    for (int ch = 0; ch < IC / ICC; ++ch) {
        __syncthreads();
        const float* src = Xin + ((size_t)b * IC + ch * ICC) * TT;
        for (int i = threadIdx.x; i < ICC * TT; i += OCT) xs[i] = src[i];
        __syncthreads();
        #pragma unroll 2
        for (int icl = 0; icl < ICC; ++icl) {
            const float* wp = wt + ((size_t)(ch * ICC + icl) * 4) * OCTOT + oc;
            float w0 = __ldg(wp);
            float w1 = __ldg(wp + OCTOT);
            float w2 = __ldg(wp + 2 * OCTOT);
            float wd = __ldg(wp + 3 * OCTOT);
            #pragma unroll
            for (int t = 0; t < TT; ++t) {
                float xv = xs[icl * TT + t];
                accC[t] = fmaf(w2, xv, accC[t]);
                if (t + DIL < TT)     accC[t + DIL]     = fmaf(w1, xv, accC[t + DIL]);
                if (t + 2 * DIL < TT) accC[t + 2 * DIL] = fmaf(w0, xv, accC[t + 2 * DIL]);
                accR[t] = fmaf(wd, xv, accR[t]);
            }
        }
    }
    float bc = __ldg(&cb[oc]);
    float bd = __ldg(&db[oc]);
    float* dst = Xout + ((size_t)b * OCTOT + oc) * TT;
    #pragma unroll
    for (int t = 0; t < TT; ++t) {
        float o1 = fmaxf(accC[t] + bc, 0.0f);
        dst[t] = fmaxf(o1 + accR[t] + bd, 0.0f);
    }
}

// ---------------- TCN blocks 1/2: ldmatrix + mma.sync bf16-split GEMM ----------------
// 256 threads = 8 warps (4 M x 2 N); CTA tile 128 oc x 128 n; warp tile 32 x 64.
// conv GEMM K=3*IC (j-major im2col); down GEMM K=IC fused into j==2 chunks
// (same B tile). out = relu(relu(conv+cb) + down + db).
#define TP     72        // smem row pitch in bf16 elems (144B: ldmatrix conflict-free)
#define OFF_AH  0
#define OFF_AL  18432
#define OFF_BH  36864
#define OFF_BL  55296
#define OFF_ADH 73728
#define OFF_ADL 92160
#define OFF_BC  110592
#define OFF_BD  111104
#define OFF_OB  111616
#define SMEM_BYTES 112128

template<int IC, int DIL, int OCTOT>
__global__ __launch_bounds__(256, 1)
void tcn_mma_kernel(const float* __restrict__ Xin,
                    const __nv_bfloat16* __restrict__ Wch, const __nv_bfloat16* __restrict__ Wcl,
                    const __nv_bfloat16* __restrict__ Wdh, const __nv_bfloat16* __restrict__ Wdl,
                    const float* __restrict__ cb, const float* __restrict__ db,
                    float* __restrict__ Xout) {
    extern __shared__ char smem[];
    const uint32_t sb = smem_u32(smem);
    const int tid  = threadIdx.x;
    const int wid  = tid >> 5;
    const int lane = tid & 31;

    constexpr int KC  = 3 * IC;
    constexpr int NCH = KC / 64;    // 64-wide K chunks (conv)
    constexpr int J2  = 2 * IC / 64; // first chunk index with j==2

    const int n0    = blockIdx.x * 128;
    const int mtile = blockIdx.y;

    float* bcS = (float*)(smem + OFF_BC);
    float* bdS = (float*)(smem + OFF_BD);
    int*   obS = (int*)  (smem + OFF_OB);
    if (tid < 128) {
        bcS[tid] = cb[mtile * 128 + tid];
        bdS[tid] = db[mtile * 128 + tid];
        int nc = n0 + tid;
        int b = nc / 30, t = nc - b * 30;
        obS[tid] = b * OCTOT * 30 + t;
    }

    // accumulators: [fm][fn][4]
    float accC[2][8][4], accD[2][8][4];
    #pragma unroll
    for (int i = 0; i < 2; ++i)
        #pragma unroll
        for (int j = 0; j < 8; ++j)
            #pragma unroll
            for (int r = 0; r < 4; ++r) { accC[i][j][r] = 0.0f; accD[i][j][r] = 0.0f; }

    const int warpM = wid & 3;   // 0..3
    const int warpN = wid >> 2;  // 0..1

    // B-fill thread coords
    const int nrow  = tid & 127;
    const int khalf = (tid >> 7) * 32;
    const int ncol  = n0 + nrow;
    const int bb    = ncol / 30;
    const int ttt   = ncol - bb * 30;
    const float* Xb = Xin + (size_t)bb * IC * TT;

    // ldmatrix per-lane addresses (fixed per warp; col varies per ks)
    const int arow = warpM * 32 + (lane & 15);            // + fm*16
    const int acol = (lane >> 4) << 3;                    // + ks*16
    const int brow = warpN * 64 + (lane & 7) + ((lane >> 4) << 3);  // + gn*16
    const int bcol = ((lane >> 3) & 1) << 3;              // + ks*16

    #pragma unroll 1
    for (int ch = 0; ch < NCH; ++ch) {
        const int  k0 = ch * 64;
        const bool dn = (ch >= J2);
        __syncthreads();
        // ---- A fill (conv weights): warp covers a row, lanes cover k ----
        {
            const __nv_bfloat16* Wh = Wch + (size_t)(mtile * 128) * KC + k0;
            const __nv_bfloat16* Wl = Wcl + (size_t)(mtile * 128) * KC + k0;
            #pragma unroll
            for (int r8 = 0; r8 < 16; ++r8) {
                int row = r8 * 8 + wid;
                size_t off = (size_t)row * KC + lane * 2;
                uint32_t vh = *(const uint32_t*)(Wh + off);
                uint32_t vl = *(const uint32_t*)(Wl + off);
                uint32_t so = (uint32_t)(row * TP + lane * 2) * 2;
                *(uint32_t*)(smem + OFF_AH + so) = vh;
                *(uint32_t*)(smem + OFF_AL + so) = vl;
            }
        }
        // ---- A_down fill on j==2 chunks ----
        if (dn) {
            const int kd0 = k0 - 2 * IC;
            const __nv_bfloat16* Wh = Wdh + (size_t)(mtile * 128) * IC + kd0;
            const __nv_bfloat16* Wl = Wdl + (size_t)(mtile * 128) * IC + kd0;
            #pragma unroll
            for (int r8 = 0; r8 < 16; ++r8) {
                int row = r8 * 8 + wid;
                size_t off = (size_t)row * IC + lane * 2;
                uint32_t vh = *(const uint32_t*)(Wh + off);
                uint32_t vl = *(const uint32_t*)(Wl + off);
                uint32_t so = (uint32_t)(row * TP + lane * 2) * 2;
                *(uint32_t*)(smem + OFF_ADH + so) = vh;
                *(uint32_t*)(smem + OFF_ADL + so) = vl;
            }
        }
        // ---- B fill (im2col, hi/lo split) ----
        {
            const int j    = k0 / IC;
            const int ic0  = (k0 % IC) + khalf;
            const int tsrc = ttt - (2 - j) * DIL;
            #pragma unroll 4
            for (int u = 0; u < 16; ++u) {
                int kk = khalf + u * 2;
                float v0 = 0.0f, v1 = 0.0f;
                if (tsrc >= 0) {
                    v0 = Xb[(size_t)(ic0 + u * 2) * TT + tsrc];
                    v1 = Xb[(size_t)(ic0 + u * 2 + 1) * TT + tsrc];
                }
                float h0 = __bfloat162float(__float2bfloat16(v0));
                float h1 = __bfloat162float(__float2bfloat16(v1));
                uint32_t hp, lp;
                CVT_BF16X2(hp, v0, v1);
                CVT_BF16X2(lp, v0 - h0, v1 - h1);
                uint32_t so = (uint32_t)(nrow * TP + kk) * 2;
                *(uint32_t*)(smem + OFF_BH + so) = hp;
                *(uint32_t*)(smem + OFF_BL + so) = lp;
            }
        }
        __syncthreads();

        // ---- MMA: 4 k-steps of 16 ----
        #pragma unroll
        for (int ks = 0; ks < 4; ++ks) {
            uint32_t ah[2][4], al[2][4];
            #pragma unroll
            for (int fm = 0; fm < 2; ++fm) {
                uint32_t ad = sb + OFF_AH + (uint32_t)((arow + fm * 16) * TP + acol + ks * 16) * 2;
                LDSM_X4(ah[fm][0], ah[fm][1], ah[fm][2], ah[fm][3], ad);
                LDSM_X4(al[fm][0], al[fm][1], al[fm][2], al[fm][3], ad + (OFF_AL - OFF_AH));
            }
            uint32_t bh[4][4], bl[4][4];
            #pragma unroll
            for (int gn = 0; gn < 4; ++gn) {
                uint32_t bd_ = sb + OFF_BH + (uint32_t)((brow + gn * 16) * TP + bcol + ks * 16) * 2;
                LDSM_X4(bh[gn][0], bh[gn][1], bh[gn][2], bh[gn][3], bd_);
                LDSM_X4(bl[gn][0], bl[gn][1], bl[gn][2], bl[gn][3], bd_ + (OFF_BL - OFF_BH));
            }
            #pragma unroll
            for (int fm = 0; fm < 2; ++fm)
                #pragma unroll
                for (int gn = 0; gn < 4; ++gn) {
                    MMA_BF16(accC[fm][2 * gn],     ah[fm], bh[gn][0], bh[gn][1]);
                    MMA_BF16(accC[fm][2 * gn + 1], ah[fm], bh[gn][2], bh[gn][3]);
                    MMA_BF16(accC[fm][2 * gn],     ah[fm], bl[gn][0], bl[gn][1]);
                    MMA_BF16(accC[fm][2 * gn + 1], ah[fm], bl[gn][2], bl[gn][3]);
                    MMA_BF16(accC[fm][2 * gn],     al[fm], bh[gn][0], bh[gn][1]);
                    MMA_BF16(accC[fm][2 * gn + 1], al[fm], bh[gn][2], bh[gn][3]);
                }
            if (dn) {
                uint32_t dh[2][4], dl[2][4];
                #pragma unroll
                for (int fm = 0; fm < 2; ++fm) {
                    uint32_t ad = sb + OFF_ADH + (uint32_t)((arow + fm * 16) * TP + acol + ks * 16) * 2;
                    LDSM_X4(dh[fm][0], dh[fm][1], dh[fm][2], dh[fm][3], ad);
                    LDSM_X4(dl[fm][0], dl[fm][1], dl[fm][2], dl[fm][3], ad + (OFF_ADL - OFF_ADH));
                }
                #pragma unroll
                for (int fm = 0; fm < 2; ++fm)
                    #pragma unroll
                    for (int gn = 0; gn < 4; ++gn) {
                        MMA_BF16(accD[fm][2 * gn],     dh[fm], bh[gn][0], bh[gn][1]);
                        MMA_BF16(accD[fm][2 * gn + 1], dh[fm], bh[gn][2], bh[gn][3]);
                        MMA_BF16(accD[fm][2 * gn],     dh[fm], bl[gn][0], bl[gn][1]);
                        MMA_BF16(accD[fm][2 * gn + 1], dh[fm], bl[gn][2], bl[gn][3]);
                        MMA_BF16(accD[fm][2 * gn],     dl[fm], bh[gn][0], bh[gn][1]);
                        MMA_BF16(accD[fm][2 * gn + 1], dl[fm], bh[gn][2], bh[gn][3]);
                    }
            }
        }
    }

    // ---- epilogue: regs -> smem [n][oc] -> coalesced STG ----
    __syncthreads();
    float* resBuf = (float*)smem;  // [128 n][129 pitch]
    #pragma unroll
    for (int fm = 0; fm < 2; ++fm) {
        int mloc = warpM * 32 + fm * 16 + (lane >> 2);
        #pragma unroll
        for (int fn = 0; fn < 8; ++fn) {
            int nloc = warpN * 64 + fn * 8 + ((lane & 3) << 1);
            #pragma unroll
            for (int r = 0; r < 4; ++r) {
                int m = mloc + ((r >> 1) << 3);
                int n = nloc + (r & 1);
                float c = fmaxf(accC[fm][fn][r] + bcS[m], 0.0f);
                float v = fmaxf(c + accD[fm][fn][r] + bdS[m], 0.0f);
                resBuf[n * 129 + m] = v;
            }
        }
    }
    __syncthreads();
    const int ocg0 = mtile * 128;
    #pragma unroll 1
    for (int idx = tid; idx < 128 * 128; idx += 256) {
        int oc = idx >> 7;
        int n  = idx & 127;
        Xout[(size_t)obS[n] + (ocg0 + oc) * 30] = resBuf[n * 129 + oc];
    }
}

// ---------------- FC ----------------
#define FC_NB 8
#define FC_CH 480
__global__ __launch_bounds__(288)
void fc_kernel(const float* __restrict__ X, const float* __restrict__ wT,
               const float* __restrict__ fb, float* __restrict__ out) {
    __shared__ float xsf[FC_CH * FC_NB];
    __shared__ float red[4 * FC_NB * FCO];
    int o   = threadIdx.x;
    int q   = threadIdx.y;
    int tid = q * FCO + o;
    int b0  = blockIdx.x * FC_NB;

    float acc[FC_NB];
    #pragma unroll
    for (int i = 0; i < FC_NB; ++i) acc[i] = 0.0f;

    #pragma unroll 1
    for (int ch = 0; ch < FCF / FC_CH; ++ch) {
        __syncthreads();
        for (int i = tid; i < FC_CH * FC_NB; i += 288) {
            int bb = i / FC_CH;
            int fl = i % FC_CH;
            xsf[fl * FC_NB + bb] = X[(size_t)(b0 + bb) * FCF + ch * FC_CH + fl];
        }
        __syncthreads();
        #pragma unroll 4
        for (int i = 0; i < FC_CH / 4; ++i) {
            int fl = i * 4 + q;
            float w = __ldg(&wT[(size_t)(ch * FC_CH + fl) * FCO + o]);
            const float4* xp = (const float4*)&xsf[fl * FC_NB];
            float4 xa = xp[0], xb = xp[1];
            acc[0] = fmaf(w, xa.x, acc[0]);
            acc[1] = fmaf(w, xa.y, acc[1]);
            acc[2] = fmaf(w, xa.z, acc[2]);
            acc[3] = fmaf(w, xa.w, acc[3]);
            acc[4] = fmaf(w, xb.x, acc[4]);
            acc[5] = fmaf(w, xb.y, acc[5]);
            acc[6] = fmaf(w, xb.z, acc[6]);
            acc[7] = fmaf(w, xb.w, acc[7]);
        }
    }
    #pragma unroll
    for (int bb = 0; bb < FC_NB; ++bb)
        red[(q * FC_NB + bb) * FCO + o] = acc[bb];
    __syncthreads();
    for (int idx = tid; idx < FC_NB * FCO; idx += 288) {
        int bb = idx / FCO;
        int oo = idx % FCO;
        float s = red[(0 * FC_NB + bb) * FCO + oo]
                + red[(1 * FC_NB + bb) * FCO + oo]
                + red[(2 * FC_NB + bb) * FCO + oo]
                + red[(3 * FC_NB + bb) * FCO + oo];
        out[(size_t)(b0 + bb) * FCO + oo] = s + __ldg(&fb[oo]);
    }
}

// ---------------- launch ----------------
extern "C" void kernel_launch(void* const* d_in, const int* in_sizes, int n_in,
                              void* d_out, int out_size) {
    const float* x       = (const float*)d_in[0];
    const void*  eidx    = d_in[1];
    const float* gcn_w   = (const float*)d_in[2];
    const float* gcn_b   = (const float*)d_in[3];
    const float* conv_w0 = (const float*)d_in[4];
    const float* conv_b0 = (const float*)d_in[5];
    const float* down_w0 = (const float*)d_in[6];
    const float* down_b0 = (const float*)d_in[7];
    const float* conv_w1 = (const float*)d_in[8];
    const float* conv_b1 = (const float*)d_in[9];
    const float* down_w1 = (const float*)d_in[10];
    const float* down_b1 = (const float*)d_in[11];
    const float* conv_w2 = (const float*)d_in[12];
    const float* conv_b2 = (const float*)d_in[13];
    const float* down_w2 = (const float*)d_in[14];
    const float* down_b2 = (const float*)d_in[15];
    const float* fc_w    = (const float*)d_in[16];
    const float* fc_b    = (const float*)d_in[17];
    float* out = (float*)d_out;

    float *p_wt0, *p_fcwT, *p_x0, *p_x1, *p_x2, *p_x3;
    cudaGetSymbolAddress((void**)&p_wt0,  g_wt0);
    cudaGetSymbolAddress((void**)&p_fcwT, g_fcwT);
    cudaGetSymbolAddress((void**)&p_x0, g_x0);
    cudaGetSymbolAddress((void**)&p_x1, g_x1);
    cudaGetSymbolAddress((void**)&p_x2, g_x2);
    cudaGetSymbolAddress((void**)&p_x3, g_x3);
    __nv_bfloat16 *wc1h, *wc1l, *wd1h, *wd1l, *wc2h, *wc2l, *wd2h, *wd2l;
    cudaGetSymbolAddress((void**)&wc1h, g_wc1h);
    cudaGetSymbolAddress((void**)&wc1l, g_wc1l);
    cudaGetSymbolAddress((void**)&wd1h, g_wd1h);
    cudaGetSymbolAddress((void**)&wd1l, g_wd1l);
    cudaGetSymbolAddress((void**)&wc2h, g_wc2h);
    cudaGetSymbolAddress((void**)&wc2l, g_wc2l);
    cudaGetSymbolAddress((void**)&wd2h, g_wd2h);
    cudaGetSymbolAddress((void**)&wd2l, g_wd2l);

    cudaFuncSetAttribute(tcn_mma_kernel<128, 3, 512>,
                         cudaFuncAttributeMaxDynamicSharedMemorySize, SMEM_BYTES);
    cudaFuncSetAttribute(tcn_mma_kernel<512, 9, 128>,
                         cudaFuncAttributeMaxDynamicSharedMemorySize, SMEM_BYTES);

    k_init<<<(N_NODES * 12 + 255) / 256, 256>>>();
    k_detect<<<8, 256>>>((const long long*)eidx);

    k_twt<<<(128 * 12 * 4 + 255) / 256, 256>>>(conv_w0, down_w0, p_wt0, 128, 12);
    k_wsplit3<<<(512 * 128 * 3 + 255) / 256, 256>>>(conv_w1, wc1h, wc1l, 512, 128);
    k_wsplit1<<<(512 * 128 + 255) / 256, 256>>>(down_w1, wd1h, wd1l, 512 * 128);
    k_wsplit3<<<(128 * 512 * 3 + 255) / 256, 256>>>(conv_w2, wc2h, wc2l, 128, 512);
    k_wsplit1<<<(128 * 512 + 255) / 256, 256>>>(down_w2, wd2h, wd2l, 128 * 512);
    k_tfc<<<(FCF * FCO + 255) / 256, 256>>>(fc_w, p_fcwT);

    k_deg<<<(NEDGE + 255) / 256, 256>>>(eidx);
    k_h<<<(N_NODES + 127) / 128, 128>>>(x, gcn_w);
    k_scatter<<<(NEDGE + 127) / 128, 128>>>(eidx);
    k_self<<<(N_NODES + 127) / 128, 128>>>(gcn_b);

    tcn_kernel<12, 12, 1, 128, 128><<<dim3(BATCH, 1), 128>>>(p_x0, p_wt0, conv_b0, down_b0, p_x1);
    tcn_mma_kernel<128, 3, 512><<<dim3(NTOT / 128, 4), 256, SMEM_BYTES>>>(
        p_x1, wc1h, wc1l, wd1h, wd1l, conv_b1, down_b1, p_x2);
    tcn_mma_kernel<512, 9, 128><<<dim3(NTOT / 128, 1), 256, SMEM_BYTES>>>(
        p_x2, wc2h, wc2l, wd2h, wd2l, conv_b2, down_b2, p_x3);

    fc_kernel<<<BATCH / FC_NB, dim3(FCO, 4)>>>(p_x3, p_fcwT, fc_b, out);
}

// round 7
// speedup vs baseline: 3.1698x; 1.8300x over previous
#include <cuda_runtime.h>
#include <cuda_fp16.h>
#include <cstdint>

// ---------------- problem dims ----------------
#define N_NODES 61440
#define NEDGE   491520
#define BATCH   2048
#define TT      30
#define INCH    12
#define FCF     3840
#define FCO     72
#define NTOT    (BATCH * TT)

// ---------------- PTX helpers ----------------
__device__ __forceinline__ uint32_t smem_u32(const void* p) {
    uint32_t a;
    asm("{ .reg .u64 t; cvta.to.shared.u64 t, %1; cvt.u32.u64 %0, t; }" : "=r"(a) : "l"(p));
    return a;
}
#define LDSM_X4(r0, r1, r2, r3, addr) \
    asm volatile("ldmatrix.sync.aligned.m8n8.x4.shared.b16 {%0,%1,%2,%3}, [%4];" \
        : "=r"(r0), "=r"(r1), "=r"(r2), "=r"(r3) : "r"(addr))
#define MMA_F16(acc, a, b0_, b1_) \
    asm volatile("mma.sync.aligned.m16n8k16.row.col.f32.f16.f16.f32 " \
        "{%0,%1,%2,%3}, {%4,%5,%6,%7}, {%8,%9}, {%0,%1,%2,%3};" \
        : "+f"((acc)[0]), "+f"((acc)[1]), "+f"((acc)[2]), "+f"((acc)[3]) \
        : "r"((a)[0]), "r"((a)[1]), "r"((a)[2]), "r"((a)[3]), "r"(b0_), "r"(b1_))
#define CP_ASYNC16(dst, src) \
    asm volatile("cp.async.ca.shared.global [%0], [%1], 16;" :: "r"(dst), "l"(src))
#define CP_ASYNC16Z(dst, src, sz) \
    asm volatile("cp.async.ca.shared.global [%0], [%1], 16, %2;" :: "r"(dst), "l"(src), "r"(sz))
#define CP_COMMIT() asm volatile("cp.async.commit_group;" ::: "memory")
#define CP_WAIT1()  asm volatile("cp.async.wait_group 1;" ::: "memory")

// ---------------- device scratch ----------------
__device__ float g_deg [N_NODES];
__device__ float g_dinv[N_NODES];
__device__ float g_h   [N_NODES * 12];
__device__ __align__(16) float  g_x0 [N_NODES * 12];          // [B][12][30] fp32
__device__ __align__(16) __half g_x1h[NTOT * 128];            // [n][128] fp16
__device__ __align__(16) __half g_x2h[NTOT * 512];            // [n][512] fp16
__device__ __align__(16) float  g_x3 [BATCH * 128 * TT];      // [B][128][30] fp32
__device__ __align__(16) float  g_wt0 [12 * 4 * 128];
__device__ __align__(16) float  g_fcwT[FCF * FCO];
__device__ int g_eflag[1];

// fp16 split weights, [oc][k], k = j*IC + ic (j-major)
__device__ __align__(16) __half g_wc1h[512 * 384];
__device__ __align__(16) __half g_wc1l[512 * 384];
__device__ __align__(16) __half g_wd1h[512 * 128];
__device__ __align__(16) __half g_wd1l[512 * 128];
__device__ __align__(16) __half g_wc2h[128 * 1536];
__device__ __align__(16) __half g_wc2l[128 * 1536];
__device__ __align__(16) __half g_wd2h[128 * 512];
__device__ __align__(16) __half g_wd2l[128 * 512];

// ---------------- init / dtype detect ----------------
__global__ void k_init() {
    int i = blockIdx.x * blockDim.x + threadIdx.x;
    if (i < N_NODES * 12) g_x0[i] = 0.0f;
    if (i < N_NODES)      g_deg[i] = 1.0f;
    if (i == 0)           g_eflag[0] = 0;
}
__global__ void k_detect(const long long* __restrict__ ep) {
    int i = blockIdx.x * blockDim.x + threadIdx.x;
    if (i < 2048) {
        long long v = ep[i];
        if (v < 0 || v >= N_NODES) atomicOr(g_eflag, 1);
    }
}
__device__ __forceinline__ void load_edge(const void* ep, int e, int& s, int& d) {
    if (g_eflag[0]) {
        const int* p = (const int*)ep;
        s = p[e]; d = p[NEDGE + e];
    } else {
        const long long* p = (const long long*)ep;
        s = (int)p[e]; d = (int)p[NEDGE + e];
    }
}

// ---------------- weight prep ----------------
__global__ void k_twt(const float* __restrict__ cw, const float* __restrict__ dw,
                      float* __restrict__ wt, int OC, int IC) {
    int id = blockIdx.x * blockDim.x + threadIdx.x;
    int tot = OC * IC * 4;
    if (id >= tot) return;
    int oc = id % OC;
    int r  = id / OC;
    int j  = r % 4;
    int ic = r / 4;
    wt[id] = (j < 3) ? cw[(oc * IC + ic) * 3 + j] : dw[oc * IC + ic];
}
__global__ void k_tfc(const float* __restrict__ fw, float* __restrict__ wT) {
    int id = blockIdx.x * blockDim.x + threadIdx.x;
    if (id >= FCF * FCO) return;
    int o = id % FCO;
    int f = id / FCO;
    wT[id] = fw[o * FCF + f];
}
__global__ void k_wsplit3h(const float* __restrict__ w, __half* __restrict__ hi,
                           __half* __restrict__ lo, int OC, int IC) {
    int id = blockIdx.x * blockDim.x + threadIdx.x;
    if (id >= OC * IC * 3) return;
    int K  = 3 * IC;
    int oc = id / K;
    int r  = id % K;
    int j  = r / IC;
    int ic = r % IC;
    float v = w[(oc * IC + ic) * 3 + j];
    __half h = __float2half_rn(v);
    hi[id] = h;
    lo[id] = __float2half_rn(v - __half2float(h));
}
__global__ void k_wsplit1h(const float* __restrict__ w, __half* __restrict__ hi,
                           __half* __restrict__ lo, int n) {
    int id = blockIdx.x * blockDim.x + threadIdx.x;
    if (id >= n) return;
    float v = w[id];
    __half h = __float2half_rn(v);
    hi[id] = h;
    lo[id] = __float2half_rn(v - __half2float(h));
}

// ---------------- GCN ----------------
__global__ void k_deg(const void* __restrict__ ep) {
    int e = blockIdx.x * blockDim.x + threadIdx.x;
    if (e >= NEDGE) return;
    int s, d;
    load_edge(ep, e, s, d);
    atomicAdd(&g_deg[d], 1.0f);
}
__global__ void k_h(const float* __restrict__ x, const float* __restrict__ gw) {
    int n = blockIdx.x * blockDim.x + threadIdx.x;
    if (n >= N_NODES) return;
    const float4* xp = (const float4*)(x + (size_t)n * 12);
    float4 a = xp[0], b = xp[1], c = xp[2];
    float xv[12] = {a.x,a.y,a.z,a.w, b.x,b.y,b.z,b.w, c.x,c.y,c.z,c.w};
    #pragma unroll
    for (int o = 0; o < 12; ++o) {
        float acc = 0.0f;
        #pragma unroll
        for (int i = 0; i < 12; ++i)
            acc = fmaf(xv[i], __ldg(&gw[o * 12 + i]), acc);
        g_h[n * 12 + o] = acc;
    }
    g_dinv[n] = rsqrtf(g_deg[n]);
}
__global__ void k_scatter(const void* __restrict__ ep) {
    int e = blockIdx.x * blockDim.x + threadIdx.x;
    if (e >= NEDGE) return;
    int s, d;
    load_edge(ep, e, s, d);
    float nm = g_dinv[s] * g_dinv[d];
    int base = (d / 30) * (12 * TT) + (d % 30);
    const float4* hp = (const float4*)(g_h + (size_t)s * 12);
    float4 a = hp[0], b = hp[1], c = hp[2];
    float hv[12] = {a.x,a.y,a.z,a.w, b.x,b.y,b.z,b.w, c.x,c.y,c.z,c.w};
    #pragma unroll
    for (int cch = 0; cch < 12; ++cch)
        atomicAdd(&g_x0[base + cch * TT], nm * hv[cch]);
}
__global__ void k_self(const float* __restrict__ gb) {
    int n = blockIdx.x * blockDim.x + threadIdx.x;
    if (n >= N_NODES) return;
    float di = g_dinv[n];
    float nm = di * di;
    int base = (n / 30) * (12 * TT) + (n % 30);
    #pragma unroll
    for (int c = 0; c < 12; ++c)
        g_x0[base + c * TT] += nm * g_h[n * 12 + c] + __ldg(&gb[c]);
}

// ---------------- block 0: scalar TCN -> fp16 [n][128] output ----------------
__global__ __launch_bounds__(128)
void tcn0_kernel(const float* __restrict__ Xin, const float* __restrict__ wt,
                 const float* __restrict__ cb, const float* __restrict__ db,
                 __half* __restrict__ X1h) {
    __shared__ float xs[12 * TT];
    __shared__ __half st[TT * 128];
    int b  = blockIdx.x;
    int oc = threadIdx.x;

    const float* src = Xin + (size_t)b * 12 * TT;
    for (int i = threadIdx.x; i < 12 * TT; i += 128) xs[i] = src[i];
    __syncthreads();

    float accC[TT], accR[TT];
    #pragma unroll
    for (int t = 0; t < TT; ++t) { accC[t] = 0.0f; accR[t] = 0.0f; }

    #pragma unroll
    for (int ic = 0; ic < 12; ++ic) {
        const float* wp = wt + (size_t)(ic * 4) * 128 + oc;
        float w0 = __ldg(wp);
        float w1 = __ldg(wp + 128);
        float w2 = __ldg(wp + 256);
        float wd = __ldg(wp + 384);
        #pragma unroll
        for (int t = 0; t < TT; ++t) {
            float xv = xs[ic * TT + t];
            accC[t] = fmaf(w2, xv, accC[t]);
            if (t + 1 < TT) accC[t + 1] = fmaf(w1, xv, accC[t + 1]);
            if (t + 2 < TT) accC[t + 2] = fmaf(w0, xv, accC[t + 2]);
            accR[t] = fmaf(wd, xv, accR[t]);
        }
    }
    float bc = __ldg(&cb[oc]);
    float bd = __ldg(&db[oc]);
    #pragma unroll
    for (int t = 0; t < TT; ++t) {
        float o1 = fmaxf(accC[t] + bc, 0.0f);
        st[t * 128 + oc] = __float2half_rn(fmaxf(o1 + accR[t] + bd, 0.0f));
    }
    __syncthreads();
    const uint32_t* sp = (const uint32_t*)st;
    uint32_t* dp = (uint32_t*)(X1h + (size_t)b * TT * 128);
    for (int i = threadIdx.x; i < TT * 64; i += 128) dp[i] = sp[i];
}

// ---------------- TCN blocks 1/2: pipelined fp16 mma GEMM ----------------
// A = conv weights (hi+lo fp16 split), B = fp16 activations [n][IC] (single term).
// conv K=3*IC j-major im2col; down K=IC fused on j==2 chunks (same B tiles).
// 2-stage cp.async pipeline, XOR-swizzled smem tiles (128 rows x 128B).
#define OFF_AH  0
#define OFF_AL  16384
#define OFF_B   32768
#define OFF_ADH 49152
#define OFF_ADL 65536
#define STAGE_B 81920
#define AUX_OFF 163840
#define SMEM_BYTES 165376
#define SWZ(row, c16) (((uint32_t)(row)) * 128u + ((((uint32_t)(c16)) ^ (((uint32_t)(row)) & 7u)) << 4))

template<int IC, int DIL, int OCTOT, bool OUTHALF>
__global__ __launch_bounds__(256, 1)
void tcn_mma_kernel(const __half* __restrict__ Act,
                    const __half* __restrict__ Wch, const __half* __restrict__ Wcl,
                    const __half* __restrict__ Wdh, const __half* __restrict__ Wdl,
                    const float* __restrict__ cb, const float* __restrict__ db,
                    void* __restrict__ XoutV) {
    extern __shared__ char smem[];
    const uint32_t sb = smem_u32(smem);
    const int tid  = threadIdx.x;
    const int wid  = tid >> 5;
    const int lane = tid & 31;

    constexpr int KC  = 3 * IC;
    constexpr int NCH = KC / 64;
    constexpr int J2  = 2 * IC / 64;

    const int n0    = blockIdx.x * 128;
    const int mtile = blockIdx.y;

    float* bcS = (float*)(smem + AUX_OFF);
    float* bdS = (float*)(smem + AUX_OFF + 512);
    int*   obS = (int*)  (smem + AUX_OFF + 1024);
    if (tid < 128) {
        bcS[tid] = cb[mtile * 128 + tid];
        bdS[tid] = db[mtile * 128 + tid];
        if (!OUTHALF) {
            int nc = n0 + tid;
            int b = nc / 30, t = nc - b * 30;
            obS[tid] = b * OCTOT * 30 + t;
        }
    }

    // fill coords
    const int frow = tid >> 3;      // 0..31 (+32*r2)
    const int fc16 = tid & 7;

    auto fill = [&](int ch, int stg) {
        const uint32_t base = sb + stg * STAGE_B;
        const int k0 = ch * 64;
        const int j  = k0 / IC;
        const int ic0 = k0 - j * IC;
        const int shift = (2 - j) * DIL;
        // A conv weights (hi/lo)
        {
            const __half* Wh = Wch + (size_t)(mtile * 128) * KC + k0 + fc16 * 8;
            const __half* Wl = Wcl + (size_t)(mtile * 128) * KC + k0 + fc16 * 8;
            #pragma unroll
            for (int r2 = 0; r2 < 4; ++r2) {
                int row = frow + r2 * 32;
                uint32_t d = base + SWZ(row, fc16);
                CP_ASYNC16(d + OFF_AH, Wh + (size_t)row * KC);
                CP_ASYNC16(d + OFF_AL, Wl + (size_t)row * KC);
            }
        }
        // B activations (single fp16)
        {
            #pragma unroll
            for (int r2 = 0; r2 < 4; ++r2) {
                int row  = frow + r2 * 32;
                int ncol = n0 + row;
                int bb   = ncol / 30;
                int tt   = ncol - bb * 30;
                int tsrc = tt - shift;
                uint32_t sz = (tsrc >= 0) ? 16u : 0u;
                int ts = tsrc >= 0 ? tsrc : 0;
                const __half* s = Act + ((size_t)(bb * 30 + ts) * IC + ic0 + fc16 * 8);
                CP_ASYNC16Z(base + OFF_B + SWZ(row, fc16), s, sz);
            }
        }
        // A down weights on j==2 chunks
        if (ch >= J2) {
            const int kd0 = k0 - 2 * IC;
            const __half* Wh = Wdh + (size_t)(mtile * 128) * IC + kd0 + fc16 * 8;
            const __half* Wl = Wdl + (size_t)(mtile * 128) * IC + kd0 + fc16 * 8;
            #pragma unroll
            for (int r2 = 0; r2 < 4; ++r2) {
                int row = frow + r2 * 32;
                uint32_t d = base + SWZ(row, fc16);
                CP_ASYNC16(d + OFF_ADH, Wh + (size_t)row * IC);
                CP_ASYNC16(d + OFF_ADL, Wl + (size_t)row * IC);
            }
        }
    };

    // accumulators
    float accC[2][8][4], accD[2][8][4];
    #pragma unroll
    for (int i = 0; i < 2; ++i)
        #pragma unroll
        for (int j = 0; j < 8; ++j)
            #pragma unroll
            for (int r = 0; r < 4; ++r) { accC[i][j][r] = 0.0f; accD[i][j][r] = 0.0f; }

    const int warpM = wid & 3;
    const int warpN = wid >> 2;
    // ldmatrix lane coords
    const int arL = lane & 15;          // A row within 16
    const int acL = lane >> 4;          // A c16 offset (0/1)
    const int brL = (lane & 7) + ((lane >> 4) << 3);  // B row within 16
    const int bcL = (lane >> 3) & 1;    // B c16 offset

    fill(0, 0);
    CP_COMMIT();

    #pragma unroll 1
    for (int ch = 0; ch < NCH; ++ch) {
        if (ch + 1 < NCH) fill(ch + 1, (ch + 1) & 1);
        CP_COMMIT();
        CP_WAIT1();
        __syncthreads();

        const uint32_t base = sb + (ch & 1) * STAGE_B;
        const bool dn = (ch >= J2);

        #pragma unroll
        for (int ks = 0; ks < 4; ++ks) {
            uint32_t ah[2][4], al[2][4];
            #pragma unroll
            for (int fm = 0; fm < 2; ++fm) {
                int r = warpM * 32 + fm * 16 + arL;
                uint32_t ad = base + SWZ(r, ks * 2 + acL);
                LDSM_X4(ah[fm][0], ah[fm][1], ah[fm][2], ah[fm][3], ad + OFF_AH);
                LDSM_X4(al[fm][0], al[fm][1], al[fm][2], al[fm][3], ad + OFF_AL);
            }
            uint32_t bq[4][4];
            #pragma unroll
            for (int gn = 0; gn < 4; ++gn) {
                int r = warpN * 64 + gn * 16 + brL;
                uint32_t bd_ = base + OFF_B + SWZ(r, ks * 2 + bcL);
                LDSM_X4(bq[gn][0], bq[gn][1], bq[gn][2], bq[gn][3], bd_);
            }
            #pragma unroll
            for (int fm = 0; fm < 2; ++fm)
                #pragma unroll
                for (int gn = 0; gn < 4; ++gn) {
                    MMA_F16(accC[fm][2 * gn],     ah[fm], bq[gn][0], bq[gn][1]);
                    MMA_F16(accC[fm][2 * gn + 1], ah[fm], bq[gn][2], bq[gn][3]);
                    MMA_F16(accC[fm][2 * gn],     al[fm], bq[gn][0], bq[gn][1]);
                    MMA_F16(accC[fm][2 * gn + 1], al[fm], bq[gn][2], bq[gn][3]);
                }
            if (dn) {
                uint32_t dh[2][4], dl[2][4];
                #pragma unroll
                for (int fm = 0; fm < 2; ++fm) {
                    int r = warpM * 32 + fm * 16 + arL;
                    uint32_t ad = base + SWZ(r, ks * 2 + acL);
                    LDSM_X4(dh[fm][0], dh[fm][1], dh[fm][2], dh[fm][3], ad + OFF_ADH);
                    LDSM_X4(dl[fm][0], dl[fm][1], dl[fm][2], dl[fm][3], ad + OFF_ADL);
                }
                #pragma unroll
                for (int fm = 0; fm < 2; ++fm)
                    #pragma unroll
                    for (int gn = 0; gn < 4; ++gn) {
                        MMA_F16(accD[fm][2 * gn],     dh[fm], bq[gn][0], bq[gn][1]);
                        MMA_F16(accD[fm][2 * gn + 1], dh[fm], bq[gn][2], bq[gn][3]);
                        MMA_F16(accD[fm][2 * gn],     dl[fm], bq[gn][0], bq[gn][1]);
                        MMA_F16(accD[fm][2 * gn + 1], dl[fm], bq[gn][2], bq[gn][3]);
                    }
            }
        }
        __syncthreads();
    }

    // ---- epilogue ----
    float* resBuf = (float*)smem;  // [128 n][129 pitch]
    #pragma unroll
    for (int fm = 0; fm < 2; ++fm) {
        int mloc = warpM * 32 + fm * 16 + (lane >> 2);
        #pragma unroll
        for (int fn = 0; fn < 8; ++fn) {
            int nloc = warpN * 64 + fn * 8 + ((lane & 3) << 1);
            #pragma unroll
            for (int r = 0; r < 4; ++r) {
                int m = mloc + ((r >> 1) << 3);
                int n = nloc + (r & 1);
                float c = fmaxf(accC[fm][fn][r] + bcS[m], 0.0f);
                float v = fmaxf(c + accD[fm][fn][r] + bdS[m], 0.0f);
                resBuf[n * 129 + m] = v;
            }
        }
    }
    __syncthreads();
    const int ocg0 = mtile * 128;
    if (OUTHALF) {
        __half* Xo = (__half*)XoutV;
        #pragma unroll 1
        for (int idx = tid; idx < 128 * 64; idx += 256) {
            int n = idx >> 6, op = idx & 63;
            __half2 h = __floats2half2_rn(resBuf[n * 129 + 2 * op], resBuf[n * 129 + 2 * op + 1]);
            *(__half2*)(Xo + ((size_t)(n0 + n) * OCTOT + ocg0 + 2 * op)) = h;
        }
    } else {
        float* Xo = (float*)XoutV;
        #pragma unroll 1
        for (int idx = tid; idx < 128 * 128; idx += 256) {
            int oc = idx >> 7;
            int n  = idx & 127;
            Xo[(size_t)obS[n] + (ocg0 + oc) * 30] = resBuf[n * 129 + oc];
        }
    }
}

// ---------------- FC ----------------
#define FC_NB 8
#define FC_CH 480
__global__ __launch_bounds__(288)
void fc_kernel(const float* __restrict__ X, const float* __restrict__ wT,
               const float* __restrict__ fb, float* __restrict__ out) {
    __shared__ float xsf[FC_CH * FC_NB];
    __shared__ float red[4 * FC_NB * FCO];
    int o   = threadIdx.x;
    int q   = threadIdx.y;
    int tid = q * FCO + o;
    int b0  = blockIdx.x * FC_NB;

    float acc[FC_NB];
    #pragma unroll
    for (int i = 0; i < FC_NB; ++i) acc[i] = 0.0f;

    #pragma unroll 1
    for (int ch = 0; ch < FCF / FC_CH; ++ch) {
        __syncthreads();
        for (int i = tid; i < FC_CH * FC_NB; i += 288) {
            int bb = i / FC_CH;
            int fl = i % FC_CH;
            xsf[fl * FC_NB + bb] = X[(size_t)(b0 + bb) * FCF + ch * FC_CH + fl];
        }
        __syncthreads();
        #pragma unroll 4
        for (int i = 0; i < FC_CH / 4; ++i) {
            int fl = i * 4 + q;
            float w = __ldg(&wT[(size_t)(ch * FC_CH + fl) * FCO + o]);
            const float4* xp = (const float4*)&xsf[fl * FC_NB];
            float4 xa = xp[0], xb = xp[1];
            acc[0] = fmaf(w, xa.x, acc[0]);
            acc[1] = fmaf(w, xa.y, acc[1]);
            acc[2] = fmaf(w, xa.z, acc[2]);
            acc[3] = fmaf(w, xa.w, acc[3]);
            acc[4] = fmaf(w, xb.x, acc[4]);
            acc[5] = fmaf(w, xb.y, acc[5]);
            acc[6] = fmaf(w, xb.z, acc[6]);
            acc[7] = fmaf(w, xb.w, acc[7]);
        }
    }
    #pragma unroll
    for (int bb = 0; bb < FC_NB; ++bb)
        red[(q * FC_NB + bb) * FCO + o] = acc[bb];
    __syncthreads();
    for (int idx = tid; idx < FC_NB * FCO; idx += 288) {
        int bb = idx / FCO;
        int oo = idx % FCO;
        float s = red[(0 * FC_NB + bb) * FCO + oo]
                + red[(1 * FC_NB + bb) * FCO + oo]
                + red[(2 * FC_NB + bb) * FCO + oo]
                + red[(3 * FC_NB + bb) * FCO + oo];
        out[(size_t)(b0 + bb) * FCO + oo] = s + __ldg(&fb[oo]);
    }
}

// ---------------- launch ----------------
extern "C" void kernel_launch(void* const* d_in, const int* in_sizes, int n_in,
                              void* d_out, int out_size) {
    const float* x       = (const float*)d_in[0];
    const void*  eidx    = d_in[1];
    const float* gcn_w   = (const float*)d_in[2];
    const float* gcn_b   = (const float*)d_in[3];
    const float* conv_w0 = (const float*)d_in[4];
    const float* conv_b0 = (const float*)d_in[5];
    const float* down_w0 = (const float*)d_in[6];
    const float* down_b0 = (const float*)d_in[7];
    const float* conv_w1 = (const float*)d_in[8];
    const float* conv_b1 = (const float*)d_in[9];
    const float* down_w1 = (const float*)d_in[10];
    const float* down_b1 = (const float*)d_in[11];
    const float* conv_w2 = (const float*)d_in[12];
    const float* conv_b2 = (const float*)d_in[13];
    const float* down_w2 = (const float*)d_in[14];
    const float* down_b2 = (const float*)d_in[15];
    const float* fc_w    = (const float*)d_in[16];
    const float* fc_b    = (const float*)d_in[17];
    float* out = (float*)d_out;

    float *p_wt0, *p_fcwT, *p_x0, *p_x3;
    cudaGetSymbolAddress((void**)&p_wt0,  g_wt0);
    cudaGetSymbolAddress((void**)&p_fcwT, g_fcwT);
    cudaGetSymbolAddress((void**)&p_x0, g_x0);
    cudaGetSymbolAddress((void**)&p_x3, g_x3);
    __half *p_x1h, *p_x2h;
    cudaGetSymbolAddress((void**)&p_x1h, g_x1h);
    cudaGetSymbolAddress((void**)&p_x2h, g_x2h);
    __half *wc1h, *wc1l, *wd1h, *wd1l, *wc2h, *wc2l, *wd2h, *wd2l;
    cudaGetSymbolAddress((void**)&wc1h, g_wc1h);
    cudaGetSymbolAddress((void**)&wc1l, g_wc1l);
    cudaGetSymbolAddress((void**)&wd1h, g_wd1h);
    cudaGetSymbolAddress((void**)&wd1l, g_wd1l);
    cudaGetSymbolAddress((void**)&wc2h, g_wc2h);
    cudaGetSymbolAddress((void**)&wc2l, g_wc2l);
    cudaGetSymbolAddress((void**)&wd2h, g_wd2h);
    cudaGetSymbolAddress((void**)&wd2l, g_wd2l);

    cudaFuncSetAttribute(tcn_mma_kernel<128, 3, 512, true>,
                         cudaFuncAttributeMaxDynamicSharedMemorySize, SMEM_BYTES);
    cudaFuncSetAttribute(tcn_mma_kernel<512, 9, 128, false>,
                         cudaFuncAttributeMaxDynamicSharedMemorySize, SMEM_BYTES);

    k_init<<<(N_NODES * 12 + 255) / 256, 256>>>();
    k_detect<<<8, 256>>>((const long long*)eidx);

    k_twt<<<(128 * 12 * 4 + 255) / 256, 256>>>(conv_w0, down_w0, p_wt0, 128, 12);
    k_wsplit3h<<<(512 * 128 * 3 + 255) / 256, 256>>>(conv_w1, wc1h, wc1l, 512, 128);
    k_wsplit1h<<<(512 * 128 + 255) / 256, 256>>>(down_w1, wd1h, wd1l, 512 * 128);
    k_wsplit3h<<<(128 * 512 * 3 + 255) / 256, 256>>>(conv_w2, wc2h, wc2l, 128, 512);
    k_wsplit1h<<<(128 * 512 + 255) / 256, 256>>>(down_w2, wd2h, wd2l, 128 * 512);
    k_tfc<<<(FCF * FCO + 255) / 256, 256>>>(fc_w, p_fcwT);

    k_deg<<<(NEDGE + 255) / 256, 256>>>(eidx);
    k_h<<<(N_NODES + 127) / 128, 128>>>(x, gcn_w);
    k_scatter<<<(NEDGE + 127) / 128, 128>>>(eidx);
    k_self<<<(N_NODES + 127) / 128, 128>>>(gcn_b);

    tcn0_kernel<<<BATCH, 128>>>(p_x0, p_wt0, conv_b0, down_b0, p_x1h);
    tcn_mma_kernel<128, 3, 512, true><<<dim3(NTOT / 128, 4), 256, SMEM_BYTES>>>(
        p_x1h, wc1h, wc1l, wd1h, wd1l, conv_b1, down_b1, p_x2h);
    tcn_mma_kernel<512, 9, 128, false><<<dim3(NTOT / 128, 1), 256, SMEM_BYTES>>>(
        p_x2h, wc2h, wc2l, wd2h, wd2l, conv_b2, down_b2, p_x3);

    fc_kernel<<<BATCH / FC_NB, dim3(FCO, 4)>>>(p_x3, p_fcwT, fc_b, out);
}

// round 8
// speedup vs baseline: 4.0269x; 1.2704x over previous
#include <cuda_runtime.h>
#include <cuda_fp16.h>
#include <cstdint>

// ---------------- problem dims ----------------
#define N_NODES 61440
#define NEDGE   491520
#define BATCH   2048
#define TT      30
#define INCH    12
#define FCF     3840
#define FCO     72
#define NTOT    (BATCH * TT)

// ---------------- PTX helpers ----------------
__device__ __forceinline__ uint32_t smem_u32(const void* p) {
    uint32_t a;
    asm("{ .reg .u64 t; cvta.to.shared.u64 t, %1; cvt.u32.u64 %0, t; }" : "=r"(a) : "l"(p));
    return a;
}
#define LDSM_X4(r0, r1, r2, r3, addr) \
    asm volatile("ldmatrix.sync.aligned.m8n8.x4.shared.b16 {%0,%1,%2,%3}, [%4];" \
        : "=r"(r0), "=r"(r1), "=r"(r2), "=r"(r3) : "r"(addr))
#define MMA_F16(acc, a, b0_, b1_) \
    asm volatile("mma.sync.aligned.m16n8k16.row.col.f32.f16.f16.f32 " \
        "{%0,%1,%2,%3}, {%4,%5,%6,%7}, {%8,%9}, {%0,%1,%2,%3};" \
        : "+f"((acc)[0]), "+f"((acc)[1]), "+f"((acc)[2]), "+f"((acc)[3]) \
        : "r"((a)[0]), "r"((a)[1]), "r"((a)[2]), "r"((a)[3]), "r"(b0_), "r"(b1_))
#define CP_ASYNC16(dst, src) \
    asm volatile("cp.async.ca.shared.global [%0], [%1], 16;" :: "r"(dst), "l"(src))
#define CP_ASYNC16Z(dst, src, sz) \
    asm volatile("cp.async.ca.shared.global [%0], [%1], 16, %2;" :: "r"(dst), "l"(src), "r"(sz))
#define CP_COMMIT() asm volatile("cp.async.commit_group;" ::: "memory")
#define CP_WAIT1()  asm volatile("cp.async.wait_group 1;" ::: "memory")

// ---------------- device scratch ----------------
__device__ float g_deg [N_NODES];
__device__ float g_dinv[N_NODES];
__device__ float g_h   [N_NODES * 12];
__device__ __align__(16) float  g_x0 [N_NODES * 12];          // [B][12][30] fp32
__device__ __align__(16) __half g_x1h[NTOT * 128];            // [n][128] fp16
__device__ __align__(16) __half g_x2h[NTOT * 512];            // [n][512] fp16
__device__ __align__(16) float  g_x3 [BATCH * 128 * TT];      // [B][128][30] fp32
__device__ __align__(16) float  g_wt0 [12 * 4 * 128];
__device__ __align__(16) float  g_fcwT[FCF * FCO];
__device__ int g_eflag[1];

// fp16 weights, [oc][k], k = j*IC + ic (j-major)
__device__ __align__(16) __half g_wc1[512 * 384];
__device__ __align__(16) __half g_wd1[512 * 128];
__device__ __align__(16) __half g_wc2[128 * 1536];
__device__ __align__(16) __half g_wd2[128 * 512];

// ---------------- init / dtype detect ----------------
__global__ void k_init() {
    int i = blockIdx.x * blockDim.x + threadIdx.x;
    if (i < N_NODES * 12) g_x0[i] = 0.0f;
    if (i < N_NODES)      g_deg[i] = 1.0f;
    if (i == 0)           g_eflag[0] = 0;
}
__global__ void k_detect(const long long* __restrict__ ep) {
    int i = blockIdx.x * blockDim.x + threadIdx.x;
    if (i < 2048) {
        long long v = ep[i];
        if (v < 0 || v >= N_NODES) atomicOr(g_eflag, 1);
    }
}
__device__ __forceinline__ void load_edge(const void* ep, int e, int& s, int& d) {
    if (g_eflag[0]) {
        const int* p = (const int*)ep;
        s = p[e]; d = p[NEDGE + e];
    } else {
        const long long* p = (const long long*)ep;
        s = (int)p[e]; d = (int)p[NEDGE + e];
    }
}

// ---------------- weight prep ----------------
__global__ void k_twt(const float* __restrict__ cw, const float* __restrict__ dw,
                      float* __restrict__ wt, int OC, int IC) {
    int id = blockIdx.x * blockDim.x + threadIdx.x;
    int tot = OC * IC * 4;
    if (id >= tot) return;
    int oc = id % OC;
    int r  = id / OC;
    int j  = r % 4;
    int ic = r / 4;
    wt[id] = (j < 3) ? cw[(oc * IC + ic) * 3 + j] : dw[oc * IC + ic];
}
__global__ void k_tfc(const float* __restrict__ fw, float* __restrict__ wT) {
    int id = blockIdx.x * blockDim.x + threadIdx.x;
    if (id >= FCF * FCO) return;
    int o = id % FCO;
    int f = id / FCO;
    wT[id] = fw[o * FCF + f];
}
__global__ void k_wconv3h(const float* __restrict__ w, __half* __restrict__ h, int OC, int IC) {
    int id = blockIdx.x * blockDim.x + threadIdx.x;
    if (id >= OC * IC * 3) return;
    int K  = 3 * IC;
    int oc = id / K;
    int r  = id % K;
    int j  = r / IC;
    int ic = r % IC;
    h[id] = __float2half_rn(w[(oc * IC + ic) * 3 + j]);
}
__global__ void k_wconv1h(const float* __restrict__ w, __half* __restrict__ h, int n) {
    int id = blockIdx.x * blockDim.x + threadIdx.x;
    if (id >= n) return;
    h[id] = __float2half_rn(w[id]);
}

// ---------------- GCN ----------------
__global__ void k_deg(const void* __restrict__ ep) {
    int e = blockIdx.x * blockDim.x + threadIdx.x;
    if (e >= NEDGE) return;
    int s, d;
    load_edge(ep, e, s, d);
    atomicAdd(&g_deg[d], 1.0f);
}
__global__ void k_h(const float* __restrict__ x, const float* __restrict__ gw) {
    int n = blockIdx.x * blockDim.x + threadIdx.x;
    if (n >= N_NODES) return;
    const float4* xp = (const float4*)(x + (size_t)n * 12);
    float4 a = xp[0], b = xp[1], c = xp[2];
    float xv[12] = {a.x,a.y,a.z,a.w, b.x,b.y,b.z,b.w, c.x,c.y,c.z,c.w};
    #pragma unroll
    for (int o = 0; o < 12; ++o) {
        float acc = 0.0f;
        #pragma unroll
        for (int i = 0; i < 12; ++i)
            acc = fmaf(xv[i], __ldg(&gw[o * 12 + i]), acc);
        g_h[n * 12 + o] = acc;
    }
    g_dinv[n] = rsqrtf(g_deg[n]);
}
__global__ void k_scatter(const void* __restrict__ ep) {
    int e = blockIdx.x * blockDim.x + threadIdx.x;
    if (e >= NEDGE) return;
    int s, d;
    load_edge(ep, e, s, d);
    float nm = g_dinv[s] * g_dinv[d];
    int base = (d / 30) * (12 * TT) + (d % 30);
    const float4* hp = (const float4*)(g_h + (size_t)s * 12);
    float4 a = hp[0], b = hp[1], c = hp[2];
    float hv[12] = {a.x,a.y,a.z,a.w, b.x,b.y,b.z,b.w, c.x,c.y,c.z,c.w};
    #pragma unroll
    for (int cch = 0; cch < 12; ++cch)
        atomicAdd(&g_x0[base + cch * TT], nm * hv[cch]);
}
__global__ void k_self(const float* __restrict__ gb) {
    int n = blockIdx.x * blockDim.x + threadIdx.x;
    if (n >= N_NODES) return;
    float di = g_dinv[n];
    float nm = di * di;
    int base = (n / 30) * (12 * TT) + (n % 30);
    #pragma unroll
    for (int c = 0; c < 12; ++c)
        g_x0[base + c * TT] += nm * g_h[n * 12 + c] + __ldg(&gb[c]);
}

// ---------------- block 0: scalar TCN -> fp16 [n][128] output ----------------
__global__ __launch_bounds__(128)
void tcn0_kernel(const float* __restrict__ Xin, const float* __restrict__ wt,
                 const float* __restrict__ cb, const float* __restrict__ db,
                 __half* __restrict__ X1h) {
    __shared__ float xs[12 * TT];
    __shared__ __half st[TT * 128];
    int b  = blockIdx.x;
    int oc = threadIdx.x;

    const float* src = Xin + (size_t)b * 12 * TT;
    for (int i = threadIdx.x; i < 12 * TT; i += 128) xs[i] = src[i];
    __syncthreads();

    float accC[TT], accR[TT];
    #pragma unroll
    for (int t = 0; t < TT; ++t) { accC[t] = 0.0f; accR[t] = 0.0f; }

    #pragma unroll
    for (int ic = 0; ic < 12; ++ic) {
        const float* wp = wt + (size_t)(ic * 4) * 128 + oc;
        float w0 = __ldg(wp);
        float w1 = __ldg(wp + 128);
        float w2 = __ldg(wp + 256);
        float wd = __ldg(wp + 384);
        #pragma unroll
        for (int t = 0; t < TT; ++t) {
            float xv = xs[ic * TT + t];
            accC[t] = fmaf(w2, xv, accC[t]);
            if (t + 1 < TT) accC[t + 1] = fmaf(w1, xv, accC[t + 1]);
            if (t + 2 < TT) accC[t + 2] = fmaf(w0, xv, accC[t + 2]);
            accR[t] = fmaf(wd, xv, accR[t]);
        }
    }
    float bc = __ldg(&cb[oc]);
    float bd = __ldg(&db[oc]);
    #pragma unroll
    for (int t = 0; t < TT; ++t) {
        float o1 = fmaxf(accC[t] + bc, 0.0f);
        st[t * 128 + oc] = __float2half_rn(fmaxf(o1 + accR[t] + bd, 0.0f));
    }
    __syncthreads();
    const uint32_t* sp = (const uint32_t*)st;
    uint32_t* dp = (uint32_t*)(X1h + (size_t)b * TT * 128);
    for (int i = threadIdx.x; i < TT * 64; i += 128) dp[i] = sp[i];
}

// ---------------- TCN blocks 1/2: pipelined fp16 mma GEMM (single-term) ----------------
// A = conv weights fp16, B = fp16 activations [n][IC].
// conv K=3*IC j-major im2col; down K=IC fused on j==2 chunks (same B tiles).
// 2-stage cp.async pipeline, XOR-swizzled smem tiles (128 rows x 128B).
#define OFF_A   0
#define OFF_B   16384
#define OFF_AD  32768
#define STAGE_B 49152
#define AUX_OFF 98304
#define SMEM_BYTES 99840
#define SWZ(row, c16) (((uint32_t)(row)) * 128u + ((((uint32_t)(c16)) ^ (((uint32_t)(row)) & 7u)) << 4))

template<int IC, int DIL, int OCTOT, bool OUTHALF>
__global__ __launch_bounds__(256, 1)
void tcn_mma_kernel(const __half* __restrict__ Act,
                    const __half* __restrict__ Wc, const __half* __restrict__ Wd,
                    const float* __restrict__ cb, const float* __restrict__ db,
                    void* __restrict__ XoutV) {
    extern __shared__ char smem[];
    const uint32_t sb = smem_u32(smem);
    const int tid  = threadIdx.x;
    const int wid  = tid >> 5;
    const int lane = tid & 31;

    constexpr int KC  = 3 * IC;
    constexpr int NCH = KC / 64;
    constexpr int J2  = 2 * IC / 64;

    const int n0    = blockIdx.x * 128;
    const int mtile = blockIdx.y;

    float* bcS = (float*)(smem + AUX_OFF);
    float* bdS = (float*)(smem + AUX_OFF + 512);
    int*   obS = (int*)  (smem + AUX_OFF + 1024);
    if (tid < 128) {
        bcS[tid] = cb[mtile * 128 + tid];
        bdS[tid] = db[mtile * 128 + tid];
        if (!OUTHALF) {
            int nc = n0 + tid;
            int b = nc / 30, t = nc - b * 30;
            obS[tid] = b * OCTOT * 30 + t;
        }
    }

    // fill coords
    const int frow = tid >> 3;      // 0..31 (+32*r2)
    const int fc16 = tid & 7;

    auto fill = [&](int ch, int stg) {
        const uint32_t base = sb + stg * STAGE_B;
        const int k0 = ch * 64;
        const int j  = k0 / IC;
        const int ic0 = k0 - j * IC;
        const int shift = (2 - j) * DIL;
        // A conv weights
        {
            const __half* Wp = Wc + (size_t)(mtile * 128) * KC + k0 + fc16 * 8;
            #pragma unroll
            for (int r2 = 0; r2 < 4; ++r2) {
                int row = frow + r2 * 32;
                CP_ASYNC16(base + OFF_A + SWZ(row, fc16), Wp + (size_t)row * KC);
            }
        }
        // B activations
        {
            #pragma unroll
            for (int r2 = 0; r2 < 4; ++r2) {
                int row  = frow + r2 * 32;
                int ncol = n0 + row;
                int bb   = ncol / 30;
                int tt   = ncol - bb * 30;
                int tsrc = tt - shift;
                uint32_t sz = (tsrc >= 0) ? 16u : 0u;
                int ts = tsrc >= 0 ? tsrc : 0;
                const __half* s = Act + ((size_t)(bb * 30 + ts) * IC + ic0 + fc16 * 8);
                CP_ASYNC16Z(base + OFF_B + SWZ(row, fc16), s, sz);
            }
        }
        // A down weights on j==2 chunks
        if (ch >= J2) {
            const int kd0 = k0 - 2 * IC;
            const __half* Wp = Wd + (size_t)(mtile * 128) * IC + kd0 + fc16 * 8;
            #pragma unroll
            for (int r2 = 0; r2 < 4; ++r2) {
                int row = frow + r2 * 32;
                CP_ASYNC16(base + OFF_AD + SWZ(row, fc16), Wp + (size_t)row * IC);
            }
        }
    };

    // accumulators
    float accC[2][8][4], accD[2][8][4];
    #pragma unroll
    for (int i = 0; i < 2; ++i)
        #pragma unroll
        for (int j = 0; j < 8; ++j)
            #pragma unroll
            for (int r = 0; r < 4; ++r) { accC[i][j][r] = 0.0f; accD[i][j][r] = 0.0f; }

    const int warpM = wid & 3;
    const int warpN = wid >> 2;
    const int arL = lane & 15;
    const int acL = lane >> 4;
    const int brL = (lane & 7) + ((lane >> 4) << 3);
    const int bcL = (lane >> 3) & 1;

    fill(0, 0);
    CP_COMMIT();

    #pragma unroll 1
    for (int ch = 0; ch < NCH; ++ch) {
        if (ch + 1 < NCH) fill(ch + 1, (ch + 1) & 1);
        CP_COMMIT();
        CP_WAIT1();
        __syncthreads();

        const uint32_t base = sb + (ch & 1) * STAGE_B;
        const bool dn = (ch >= J2);

        #pragma unroll
        for (int ks = 0; ks < 4; ++ks) {
            uint32_t aq[2][4];
            #pragma unroll
            for (int fm = 0; fm < 2; ++fm) {
                int r = warpM * 32 + fm * 16 + arL;
                uint32_t ad = base + OFF_A + SWZ(r, ks * 2 + acL);
                LDSM_X4(aq[fm][0], aq[fm][1], aq[fm][2], aq[fm][3], ad);
            }
            uint32_t bq[4][4];
            #pragma unroll
            for (int gn = 0; gn < 4; ++gn) {
                int r = warpN * 64 + gn * 16 + brL;
                uint32_t bd_ = base + OFF_B + SWZ(r, ks * 2 + bcL);
                LDSM_X4(bq[gn][0], bq[gn][1], bq[gn][2], bq[gn][3], bd_);
            }
            #pragma unroll
            for (int fm = 0; fm < 2; ++fm)
                #pragma unroll
                for (int gn = 0; gn < 4; ++gn) {
                    MMA_F16(accC[fm][2 * gn],     aq[fm], bq[gn][0], bq[gn][1]);
                    MMA_F16(accC[fm][2 * gn + 1], aq[fm], bq[gn][2], bq[gn][3]);
                }
            if (dn) {
                uint32_t dq[2][4];
                #pragma unroll
                for (int fm = 0; fm < 2; ++fm) {
                    int r = warpM * 32 + fm * 16 + arL;
                    uint32_t ad = base + OFF_AD + SWZ(r, ks * 2 + acL);
                    LDSM_X4(dq[fm][0], dq[fm][1], dq[fm][2], dq[fm][3], ad);
                }
                #pragma unroll
                for (int fm = 0; fm < 2; ++fm)
                    #pragma unroll
                    for (int gn = 0; gn < 4; ++gn) {
                        MMA_F16(accD[fm][2 * gn],     dq[fm], bq[gn][0], bq[gn][1]);
                        MMA_F16(accD[fm][2 * gn + 1], dq[fm], bq[gn][2], bq[gn][3]);
                    }
            }
        }
        __syncthreads();
    }

    // ---- epilogue ----
    float* resBuf = (float*)smem;  // [128 n][129 pitch]
    #pragma unroll
    for (int fm = 0; fm < 2; ++fm) {
        int mloc = warpM * 32 + fm * 16 + (lane >> 2);
        #pragma unroll
        for (int fn = 0; fn < 8; ++fn) {
            int nloc = warpN * 64 + fn * 8 + ((lane & 3) << 1);
            #pragma unroll
            for (int r = 0; r < 4; ++r) {
                int m = mloc + ((r >> 1) << 3);
                int n = nloc + (r & 1);
                float c = fmaxf(accC[fm][fn][r] + bcS[m], 0.0f);
                float v = fmaxf(c + accD[fm][fn][r] + bdS[m], 0.0f);
                resBuf[n * 129 + m] = v;
            }
        }
    }
    __syncthreads();
    const int ocg0 = mtile * 128;
    if (OUTHALF) {
        __half* Xo = (__half*)XoutV;
        #pragma unroll 1
        for (int idx = tid; idx < 128 * 64; idx += 256) {
            int n = idx >> 6, op = idx & 63;
            __half2 h = __floats2half2_rn(resBuf[n * 129 + 2 * op], resBuf[n * 129 + 2 * op + 1]);
            *(__half2*)(Xo + ((size_t)(n0 + n) * OCTOT + ocg0 + 2 * op)) = h;
        }
    } else {
        float* Xo = (float*)XoutV;
        #pragma unroll 1
        for (int idx = tid; idx < 128 * 128; idx += 256) {
            int oc = idx >> 7;
            int n  = idx & 127;
            Xo[(size_t)obS[n] + (ocg0 + oc) * 30] = resBuf[n * 129 + oc];
        }
    }
}

// ---------------- FC ----------------
#define FC_NB 8
#define FC_CH 480
__global__ __launch_bounds__(288)
void fc_kernel(const float* __restrict__ X, const float* __restrict__ wT,
               const float* __restrict__ fb, float* __restrict__ out) {
    __shared__ float xsf[FC_CH * FC_NB];
    __shared__ float red[4 * FC_NB * FCO];
    int o   = threadIdx.x;
    int q   = threadIdx.y;
    int tid = q * FCO + o;
    int b0  = blockIdx.x * FC_NB;

    float acc[FC_NB];
    #pragma unroll
    for (int i = 0; i < FC_NB; ++i) acc[i] = 0.0f;

    #pragma unroll 1
    for (int ch = 0; ch < FCF / FC_CH; ++ch) {
        __syncthreads();
        for (int i = tid; i < FC_CH * FC_NB; i += 288) {
            int bb = i / FC_CH;
            int fl = i % FC_CH;
            xsf[fl * FC_NB + bb] = X[(size_t)(b0 + bb) * FCF + ch * FC_CH + fl];
        }
        __syncthreads();
        #pragma unroll 4
        for (int i = 0; i < FC_CH / 4; ++i) {
            int fl = i * 4 + q;
            float w = __ldg(&wT[(size_t)(ch * FC_CH + fl) * FCO + o]);
            const float4* xp = (const float4*)&xsf[fl * FC_NB];
            float4 xa = xp[0], xb = xp[1];
            acc[0] = fmaf(w, xa.x, acc[0]);
            acc[1] = fmaf(w, xa.y, acc[1]);
            acc[2] = fmaf(w, xa.z, acc[2]);
            acc[3] = fmaf(w, xa.w, acc[3]);
            acc[4] = fmaf(w, xb.x, acc[4]);
            acc[5] = fmaf(w, xb.y, acc[5]);
            acc[6] = fmaf(w, xb.z, acc[6]);
            acc[7] = fmaf(w, xb.w, acc[7]);
        }
    }
    #pragma unroll
    for (int bb = 0; bb < FC_NB; ++bb)
        red[(q * FC_NB + bb) * FCO + o] = acc[bb];
    __syncthreads();
    for (int idx = tid; idx < FC_NB * FCO; idx += 288) {
        int bb = idx / FCO;
        int oo = idx % FCO;
        float s = red[(0 * FC_NB + bb) * FCO + oo]
                + red[(1 * FC_NB + bb) * FCO + oo]
                + red[(2 * FC_NB + bb) * FCO + oo]
                + red[(3 * FC_NB + bb) * FCO + oo];
        out[(size_t)(b0 + bb) * FCO + oo] = s + __ldg(&fb[oo]);
    }
}

// ---------------- launch ----------------
extern "C" void kernel_launch(void* const* d_in, const int* in_sizes, int n_in,
                              void* d_out, int out_size) {
    const float* x       = (const float*)d_in[0];
    const void*  eidx    = d_in[1];
    const float* gcn_w   = (const float*)d_in[2];
    const float* gcn_b   = (const float*)d_in[3];
    const float* conv_w0 = (const float*)d_in[4];
    const float* conv_b0 = (const float*)d_in[5];
    const float* down_w0 = (const float*)d_in[6];
    const float* down_b0 = (const float*)d_in[7];
    const float* conv_w1 = (const float*)d_in[8];
    const float* conv_b1 = (const float*)d_in[9];
    const float* down_w1 = (const float*)d_in[10];
    const float* down_b1 = (const float*)d_in[11];
    const float* conv_w2 = (const float*)d_in[12];
    const float* conv_b2 = (const float*)d_in[13];
    const float* down_w2 = (const float*)d_in[14];
    const float* down_b2 = (const float*)d_in[15];
    const float* fc_w    = (const float*)d_in[16];
    const float* fc_b    = (const float*)d_in[17];
    float* out = (float*)d_out;

    float *p_wt0, *p_fcwT, *p_x0, *p_x3;
    cudaGetSymbolAddress((void**)&p_wt0,  g_wt0);
    cudaGetSymbolAddress((void**)&p_fcwT, g_fcwT);
    cudaGetSymbolAddress((void**)&p_x0, g_x0);
    cudaGetSymbolAddress((void**)&p_x3, g_x3);
    __half *p_x1h, *p_x2h;
    cudaGetSymbolAddress((void**)&p_x1h, g_x1h);
    cudaGetSymbolAddress((void**)&p_x2h, g_x2h);
    __half *wc1, *wd1, *wc2, *wd2;
    cudaGetSymbolAddress((void**)&wc1, g_wc1);
    cudaGetSymbolAddress((void**)&wd1, g_wd1);
    cudaGetSymbolAddress((void**)&wc2, g_wc2);
    cudaGetSymbolAddress((void**)&wd2, g_wd2);

    cudaFuncSetAttribute(tcn_mma_kernel<128, 3, 512, true>,
                         cudaFuncAttributeMaxDynamicSharedMemorySize, SMEM_BYTES);
    cudaFuncSetAttribute(tcn_mma_kernel<512, 9, 128, false>,
                         cudaFuncAttributeMaxDynamicSharedMemorySize, SMEM_BYTES);

    k_init<<<(N_NODES * 12 + 255) / 256, 256>>>();
    k_detect<<<8, 256>>>((const long long*)eidx);

    k_twt<<<(128 * 12 * 4 + 255) / 256, 256>>>(conv_w0, down_w0, p_wt0, 128, 12);
    k_wconv3h<<<(512 * 128 * 3 + 255) / 256, 256>>>(conv_w1, wc1, 512, 128);
    k_wconv1h<<<(512 * 128 + 255) / 256, 256>>>(down_w1, wd1, 512 * 128);
    k_wconv3h<<<(128 * 512 * 3 + 255) / 256, 256>>>(conv_w2, wc2, 128, 512);
    k_wconv1h<<<(128 * 512 + 255) / 256, 256>>>(down_w2, wd2, 128 * 512);
    k_tfc<<<(FCF * FCO + 255) / 256, 256>>>(fc_w, p_fcwT);

    k_deg<<<(NEDGE + 255) / 256, 256>>>(eidx);
    k_h<<<(N_NODES + 127) / 128, 128>>>(x, gcn_w);
    k_scatter<<<(NEDGE + 127) / 128, 128>>>(eidx);
    k_self<<<(N_NODES + 127) / 128, 128>>>(gcn_b);

    tcn0_kernel<<<BATCH, 128>>>(p_x0, p_wt0, conv_b0, down_b0, p_x1h);
    tcn_mma_kernel<128, 3, 512, true><<<dim3(NTOT / 128, 4), 256, SMEM_BYTES>>>(
        p_x1h, wc1, wd1, conv_b1, down_b1, p_x2h);
    tcn_mma_kernel<512, 9, 128, false><<<dim3(NTOT / 128, 1), 256, SMEM_BYTES>>>(
        p_x2h, wc2, wd2, conv_b2, down_b2, p_x3);

    fc_kernel<<<BATCH / FC_NB, dim3(FCO, 4)>>>(p_x3, p_fcwT, fc_b, out);
}

// round 9
// speedup vs baseline: 4.2938x; 1.0663x over previous
#include <cuda_runtime.h>
#include <cuda_fp16.h>
#include <cstdint>

// ---------------- problem dims ----------------
#define N_NODES 61440
#define NEDGE   491520
#define BATCH   2048
#define TT      30
#define INCH    12
#define FCF     3840
#define FCO     72
#define NTOT    (BATCH * TT)

// ---------------- PTX helpers ----------------
__device__ __forceinline__ uint32_t smem_u32(const void* p) {
    uint32_t a;
    asm("{ .reg .u64 t; cvta.to.shared.u64 t, %1; cvt.u32.u64 %0, t; }" : "=r"(a) : "l"(p));
    return a;
}
#define LDSM_X4(r0, r1, r2, r3, addr) \
    asm volatile("ldmatrix.sync.aligned.m8n8.x4.shared.b16 {%0,%1,%2,%3}, [%4];" \
        : "=r"(r0), "=r"(r1), "=r"(r2), "=r"(r3) : "r"(addr))
#define MMA_F16(acc, a, b0_, b1_) \
    asm volatile("mma.sync.aligned.m16n8k16.row.col.f32.f16.f16.f32 " \
        "{%0,%1,%2,%3}, {%4,%5,%6,%7}, {%8,%9}, {%0,%1,%2,%3};" \
        : "+f"((acc)[0]), "+f"((acc)[1]), "+f"((acc)[2]), "+f"((acc)[3]) \
        : "r"((a)[0]), "r"((a)[1]), "r"((a)[2]), "r"((a)[3]), "r"(b0_), "r"(b1_))
#define CP_ASYNC16(dst, src) \
    asm volatile("cp.async.cg.shared.global [%0], [%1], 16;" :: "r"(dst), "l"(src))
#define CP_ASYNC16Z(dst, src, sz) \
    asm volatile("cp.async.cg.shared.global [%0], [%1], 16, %2;" :: "r"(dst), "l"(src), "r"(sz))
#define CP_COMMIT() asm volatile("cp.async.commit_group;" ::: "memory")
#define CP_WAIT2()  asm volatile("cp.async.wait_group 2;" ::: "memory")

// ---------------- device scratch ----------------
__device__ float g_deg [N_NODES];
__device__ float g_dinv[N_NODES];
__device__ float g_h   [N_NODES * 12];
__device__ __align__(16) float  g_x0 [N_NODES * 12];          // [B][12][30] fp32
__device__ __align__(16) __half g_x1h[NTOT * 128];            // [n][128] fp16
__device__ __align__(16) __half g_x2h[NTOT * 512];            // [n][512] fp16
__device__ __align__(16) __half g_x3h[NTOT * 128];            // [n][128] fp16
__device__ __align__(16) float  g_wt0 [12 * 4 * 128];
__device__ __align__(16) float  g_fcwT[FCF * FCO];            // [k'][o], k' = t*128+oc
__device__ int g_eflag[1];

// fp16 weights, [oc][k], k = j*IC + ic (j-major)
__device__ __align__(16) __half g_wc1[512 * 384];
__device__ __align__(16) __half g_wd1[512 * 128];
__device__ __align__(16) __half g_wc2[128 * 1536];
__device__ __align__(16) __half g_wd2[128 * 512];

// ---------------- init / dtype detect ----------------
__global__ void k_init() {
    int i = blockIdx.x * blockDim.x + threadIdx.x;
    if (i < N_NODES * 12) g_x0[i] = 0.0f;
    if (i < N_NODES)      g_deg[i] = 1.0f;
    if (i == 0)           g_eflag[0] = 0;
}
__global__ void k_detect(const long long* __restrict__ ep) {
    int i = blockIdx.x * blockDim.x + threadIdx.x;
    if (i < 2048) {
        long long v = ep[i];
        if (v < 0 || v >= N_NODES) atomicOr(g_eflag, 1);
    }
}
__device__ __forceinline__ void load_edge(const void* ep, int e, int& s, int& d) {
    if (g_eflag[0]) {
        const int* p = (const int*)ep;
        s = p[e]; d = p[NEDGE + e];
    } else {
        const long long* p = (const long long*)ep;
        s = (int)p[e]; d = (int)p[NEDGE + e];
    }
}

// ---------------- fused weight prep (single launch) ----------------
#define S0 6144
#define S1 (S0 + 196608)
#define S2 (S1 + 65536)
#define S3 (S2 + 196608)
#define S4 (S3 + 65536)
#define S5 (S4 + 276480)
__global__ void k_prep(const float* __restrict__ cw0, const float* __restrict__ dw0,
                       const float* __restrict__ cw1, const float* __restrict__ dw1,
                       const float* __restrict__ cw2, const float* __restrict__ dw2,
                       const float* __restrict__ fw) {
    int id = blockIdx.x * blockDim.x + threadIdx.x;
    if (id < S0) {
        // wt0: [ic][j][oc] fp32, j=0..2 conv, 3=down
        int oc = id % 128;
        int r  = id / 128;
        int j  = r % 4;
        int ic = r / 4;
        g_wt0[id] = (j < 3) ? cw0[(oc * 12 + ic) * 3 + j] : dw0[oc * 12 + ic];
    } else if (id < S1) {
        int t = id - S0;  // wc1: OC=512, IC=128
        int oc = t / 384, r = t % 384, j = r / 128, ic = r % 128;
        g_wc1[t] = __float2half_rn(cw1[(oc * 128 + ic) * 3 + j]);
    } else if (id < S2) {
        int t = id - S1;  // wd1
        g_wd1[t] = __float2half_rn(dw1[t]);
    } else if (id < S3) {
        int t = id - S2;  // wc2: OC=128, IC=512
        int oc = t / 1536, r = t % 1536, j = r / 512, ic = r % 512;
        g_wc2[t] = __float2half_rn(cw2[(oc * 512 + ic) * 3 + j]);
    } else if (id < S4) {
        int t = id - S3;  // wd2
        g_wd2[t] = __float2half_rn(dw2[t]);
    } else if (id < S5) {
        int t = id - S4;  // fcwT: [k'][o], k' = tt*128+oc ; src f = oc*30+tt
        int o  = t % FCO;
        int kp = t / FCO;
        int oc = kp % 128;
        int tt = kp / 128;
        g_fcwT[t] = fw[o * FCF + oc * 30 + tt];
    }
}

// ---------------- GCN ----------------
__global__ void k_deg(const void* __restrict__ ep) {
    int e = blockIdx.x * blockDim.x + threadIdx.x;
    if (e >= NEDGE) return;
    int s, d;
    load_edge(ep, e, s, d);
    atomicAdd(&g_deg[d], 1.0f);
}
__global__ void k_h(const float* __restrict__ x, const float* __restrict__ gw) {
    int n = blockIdx.x * blockDim.x + threadIdx.x;
    if (n >= N_NODES) return;
    const float4* xp = (const float4*)(x + (size_t)n * 12);
    float4 a = xp[0], b = xp[1], c = xp[2];
    float xv[12] = {a.x,a.y,a.z,a.w, b.x,b.y,b.z,b.w, c.x,c.y,c.z,c.w};
    #pragma unroll
    for (int o = 0; o < 12; ++o) {
        float acc = 0.0f;
        #pragma unroll
        for (int i = 0; i < 12; ++i)
            acc = fmaf(xv[i], __ldg(&gw[o * 12 + i]), acc);
        g_h[n * 12 + o] = acc;
    }
    g_dinv[n] = rsqrtf(g_deg[n]);
}
__global__ void k_scatter(const void* __restrict__ ep) {
    int e = blockIdx.x * blockDim.x + threadIdx.x;
    if (e >= NEDGE) return;
    int s, d;
    load_edge(ep, e, s, d);
    float nm = g_dinv[s] * g_dinv[d];
    int base = (d / 30) * (12 * TT) + (d % 30);
    const float4* hp = (const float4*)(g_h + (size_t)s * 12);
    float4 a = hp[0], b = hp[1], c = hp[2];
    float hv[12] = {a.x,a.y,a.z,a.w, b.x,b.y,b.z,b.w, c.x,c.y,c.z,c.w};
    #pragma unroll
    for (int cch = 0; cch < 12; ++cch)
        atomicAdd(&g_x0[base + cch * TT], nm * hv[cch]);
}
__global__ void k_self(const float* __restrict__ gb) {
    int n = blockIdx.x * blockDim.x + threadIdx.x;
    if (n >= N_NODES) return;
    float di = g_dinv[n];
    float nm = di * di;
    int base = (n / 30) * (12 * TT) + (n % 30);
    #pragma unroll
    for (int c = 0; c < 12; ++c)
        g_x0[base + c * TT] += nm * g_h[n * 12 + c] + __ldg(&gb[c]);
}

// ---------------- block 0: scalar TCN -> fp16 [n][128] output ----------------
__global__ __launch_bounds__(128)
void tcn0_kernel(const float* __restrict__ Xin, const float* __restrict__ wt,
                 const float* __restrict__ cb, const float* __restrict__ db,
                 __half* __restrict__ X1h) {
    __shared__ float xs[12 * TT];
    __shared__ __half st[TT * 128];
    int b  = blockIdx.x;
    int oc = threadIdx.x;

    const float* src = Xin + (size_t)b * 12 * TT;
    for (int i = threadIdx.x; i < 12 * TT; i += 128) xs[i] = src[i];
    __syncthreads();

    float accC[TT], accR[TT];
    #pragma unroll
    for (int t = 0; t < TT; ++t) { accC[t] = 0.0f; accR[t] = 0.0f; }

    #pragma unroll
    for (int ic = 0; ic < 12; ++ic) {
        const float* wp = wt + (size_t)(ic * 4) * 128 + oc;
        float w0 = __ldg(wp);
        float w1 = __ldg(wp + 128);
        float w2 = __ldg(wp + 256);
        float wd = __ldg(wp + 384);
        #pragma unroll
        for (int t = 0; t < TT; ++t) {
            float xv = xs[ic * TT + t];
            accC[t] = fmaf(w2, xv, accC[t]);
            if (t + 1 < TT) accC[t + 1] = fmaf(w1, xv, accC[t + 1]);
            if (t + 2 < TT) accC[t + 2] = fmaf(w0, xv, accC[t + 2]);
            accR[t] = fmaf(wd, xv, accR[t]);
        }
    }
    float bc = __ldg(&cb[oc]);
    float bd = __ldg(&db[oc]);
    #pragma unroll
    for (int t = 0; t < TT; ++t) {
        float o1 = fmaxf(accC[t] + bc, 0.0f);
        st[t * 128 + oc] = __float2half_rn(fmaxf(o1 + accR[t] + bd, 0.0f));
    }
    __syncthreads();
    const uint32_t* sp = (const uint32_t*)st;
    uint32_t* dp = (uint32_t*)(X1h + (size_t)b * TT * 128);
    for (int i = threadIdx.x; i < TT * 64; i += 128) dp[i] = sp[i];
}

// ---------------- TCN blocks 1/2: 3-stage pipelined fp16 mma GEMM ----------------
// A = conv weights fp16, B = fp16 activations [n][IC].
// conv K=3*IC j-major im2col; down K=IC fused on j==2 chunks (same B tiles).
// 3-stage cp.async pipeline, XOR-swizzled smem tiles. Output fp16 [n][OCTOT].
#define OFF_A   0
#define OFF_B   16384
#define OFF_AD  32768
#define STAGE_B 49152
#define AUX_OFF (3 * STAGE_B)
#define SMEM_BYTES (AUX_OFF + 1024)
#define SWZ(row, c16) (((uint32_t)(row)) * 128u + ((((uint32_t)(c16)) ^ (((uint32_t)(row)) & 7u)) << 4))

template<int IC, int DIL, int OCTOT>
__global__ __launch_bounds__(256, 1)
void tcn_mma_kernel(const __half* __restrict__ Act,
                    const __half* __restrict__ Wc, const __half* __restrict__ Wd,
                    const float* __restrict__ cb, const float* __restrict__ db,
                    __half* __restrict__ Xout) {
    extern __shared__ char smem[];
    const uint32_t sb = smem_u32(smem);
    const int tid  = threadIdx.x;
    const int wid  = tid >> 5;
    const int lane = tid & 31;

    constexpr int KC  = 3 * IC;
    constexpr int NCH = KC / 64;
    constexpr int J2  = 2 * IC / 64;

    const int n0    = blockIdx.x * 128;
    const int mtile = blockIdx.y;

    float* bcS = (float*)(smem + AUX_OFF);
    float* bdS = (float*)(smem + AUX_OFF + 512);
    if (tid < 128) {
        bcS[tid] = cb[mtile * 128 + tid];
        bdS[tid] = db[mtile * 128 + tid];
    }

    const int frow = tid >> 3;      // 0..31 (+32*r2)
    const int fc16 = tid & 7;

    auto fill = [&](int ch, int stg) {
        const uint32_t base = sb + stg * STAGE_B;
        const int k0 = ch * 64;
        const int j  = k0 / IC;
        const int ic0 = k0 - j * IC;
        const int shift = (2 - j) * DIL;
        {
            const __half* Wp = Wc + (size_t)(mtile * 128) * KC + k0 + fc16 * 8;
            #pragma unroll
            for (int r2 = 0; r2 < 4; ++r2) {
                int row = frow + r2 * 32;
                CP_ASYNC16(base + OFF_A + SWZ(row, fc16), Wp + (size_t)row * KC);
            }
        }
        {
            #pragma unroll
            for (int r2 = 0; r2 < 4; ++r2) {
                int row  = frow + r2 * 32;
                int ncol = n0 + row;
                int bb   = ncol / 30;
                int tt   = ncol - bb * 30;
                int tsrc = tt - shift;
                uint32_t sz = (tsrc >= 0) ? 16u : 0u;
                int ts = tsrc >= 0 ? tsrc : 0;
                const __half* s = Act + ((size_t)(bb * 30 + ts) * IC + ic0 + fc16 * 8);
                CP_ASYNC16Z(base + OFF_B + SWZ(row, fc16), s, sz);
            }
        }
        if (ch >= J2) {
            const int kd0 = k0 - 2 * IC;
            const __half* Wp = Wd + (size_t)(mtile * 128) * IC + kd0 + fc16 * 8;
            #pragma unroll
            for (int r2 = 0; r2 < 4; ++r2) {
                int row = frow + r2 * 32;
                CP_ASYNC16(base + OFF_AD + SWZ(row, fc16), Wp + (size_t)row * IC);
            }
        }
    };

    float accC[2][8][4], accD[2][8][4];
    #pragma unroll
    for (int i = 0; i < 2; ++i)
        #pragma unroll
        for (int j = 0; j < 8; ++j)
            #pragma unroll
            for (int r = 0; r < 4; ++r) { accC[i][j][r] = 0.0f; accD[i][j][r] = 0.0f; }

    const int warpM = wid & 3;
    const int warpN = wid >> 2;
    const int arL = lane & 15;
    const int acL = lane >> 4;
    const int brL = (lane & 7) + ((lane >> 4) << 3);
    const int bcL = (lane >> 3) & 1;

    fill(0, 0);
    CP_COMMIT();
    if (NCH > 1) fill(1, 1);
    CP_COMMIT();

    int stg = 0;
    #pragma unroll 1
    for (int ch = 0; ch < NCH; ++ch) {
        if (ch + 2 < NCH) {
            int s2 = stg + 2; if (s2 >= 3) s2 -= 3;
            fill(ch + 2, s2);
        }
        CP_COMMIT();
        CP_WAIT2();
        __syncthreads();

        const uint32_t base = sb + stg * STAGE_B;
        const bool dn = (ch >= J2);

        #pragma unroll
        for (int ks = 0; ks < 4; ++ks) {
            uint32_t aq[2][4];
            #pragma unroll
            for (int fm = 0; fm < 2; ++fm) {
                int r = warpM * 32 + fm * 16 + arL;
                uint32_t ad = base + OFF_A + SWZ(r, ks * 2 + acL);
                LDSM_X4(aq[fm][0], aq[fm][1], aq[fm][2], aq[fm][3], ad);
            }
            uint32_t bq[4][4];
            #pragma unroll
            for (int gn = 0; gn < 4; ++gn) {
                int r = warpN * 64 + gn * 16 + brL;
                uint32_t bd_ = base + OFF_B + SWZ(r, ks * 2 + bcL);
                LDSM_X4(bq[gn][0], bq[gn][1], bq[gn][2], bq[gn][3], bd_);
            }
            #pragma unroll
            for (int fm = 0; fm < 2; ++fm)
                #pragma unroll
                for (int gn = 0; gn < 4; ++gn) {
                    MMA_F16(accC[fm][2 * gn],     aq[fm], bq[gn][0], bq[gn][1]);
                    MMA_F16(accC[fm][2 * gn + 1], aq[fm], bq[gn][2], bq[gn][3]);
                }
            if (dn) {
                uint32_t dq[2][4];
                #pragma unroll
                for (int fm = 0; fm < 2; ++fm) {
                    int r = warpM * 32 + fm * 16 + arL;
                    uint32_t ad = base + OFF_AD + SWZ(r, ks * 2 + acL);
                    LDSM_X4(dq[fm][0], dq[fm][1], dq[fm][2], dq[fm][3], ad);
                }
                #pragma unroll
                for (int fm = 0; fm < 2; ++fm)
                    #pragma unroll
                    for (int gn = 0; gn < 4; ++gn) {
                        MMA_F16(accD[fm][2 * gn],     dq[fm], bq[gn][0], bq[gn][1]);
                        MMA_F16(accD[fm][2 * gn + 1], dq[fm], bq[gn][2], bq[gn][3]);
                    }
            }
        }
        __syncthreads();
        if (++stg == 3) stg = 0;
    }

    // ---- epilogue: regs -> smem [n][oc] -> coalesced fp16 STG ----
    float* resBuf = (float*)smem;  // [128 n][129 pitch]
    #pragma unroll
    for (int fm = 0; fm < 2; ++fm) {
        int mloc = warpM * 32 + fm * 16 + (lane >> 2);
        #pragma unroll
        for (int fn = 0; fn < 8; ++fn) {
            int nloc = warpN * 64 + fn * 8 + ((lane & 3) << 1);
            #pragma unroll
            for (int r = 0; r < 4; ++r) {
                int m = mloc + ((r >> 1) << 3);
                int n = nloc + (r & 1);
                float c = fmaxf(accC[fm][fn][r] + bcS[m], 0.0f);
                float v = fmaxf(c + accD[fm][fn][r] + bdS[m], 0.0f);
                resBuf[n * 129 + m] = v;
            }
        }
    }
    __syncthreads();
    const int ocg0 = mtile * 128;
    #pragma unroll 1
    for (int idx = tid; idx < 128 * 64; idx += 256) {
        int n = idx >> 6, op = idx & 63;
        __half2 h = __floats2half2_rn(resBuf[n * 129 + 2 * op], resBuf[n * 129 + 2 * op + 1]);
        *(__half2*)(Xout + ((size_t)(n0 + n) * OCTOT + ocg0 + 2 * op)) = h;
    }
}

// ---------------- FC (fp16 input, k' = t*128+oc ordering) ----------------
#define FC_NB 8
#define FC_CH 480
__global__ __launch_bounds__(288)
void fc_kernel(const __half* __restrict__ X, const float* __restrict__ wT,
               const float* __restrict__ fb, float* __restrict__ out) {
    __shared__ float xsf[FC_CH * FC_NB];
    __shared__ float red[4 * FC_NB * FCO];
    int o   = threadIdx.x;
    int q   = threadIdx.y;
    int tid = q * FCO + o;
    int b0  = blockIdx.x * FC_NB;

    float acc[FC_NB];
    #pragma unroll
    for (int i = 0; i < FC_NB; ++i) acc[i] = 0.0f;

    #pragma unroll 1
    for (int ch = 0; ch < FCF / FC_CH; ++ch) {
        __syncthreads();
        for (int i = tid; i < FC_CH * FC_NB; i += 288) {
            int bb = i / FC_CH;
            int fl = i % FC_CH;
            xsf[fl * FC_NB + bb] =
                __half2float(X[(size_t)(b0 + bb) * FCF + ch * FC_CH + fl]);
        }
        __syncthreads();
        #pragma unroll 4
        for (int i = 0; i < FC_CH / 4; ++i) {
            int fl = i * 4 + q;
            float w = __ldg(&wT[(size_t)(ch * FC_CH + fl) * FCO + o]);
            const float4* xp = (const float4*)&xsf[fl * FC_NB];
            float4 xa = xp[0], xb = xp[1];
            acc[0] = fmaf(w, xa.x, acc[0]);
            acc[1] = fmaf(w, xa.y, acc[1]);
            acc[2] = fmaf(w, xa.z, acc[2]);
            acc[3] = fmaf(w, xa.w, acc[3]);
            acc[4] = fmaf(w, xb.x, acc[4]);
            acc[5] = fmaf(w, xb.y, acc[5]);
            acc[6] = fmaf(w, xb.z, acc[6]);
            acc[7] = fmaf(w, xb.w, acc[7]);
        }
    }
    #pragma unroll
    for (int bb = 0; bb < FC_NB; ++bb)
        red[(q * FC_NB + bb) * FCO + o] = acc[bb];
    __syncthreads();
    for (int idx = tid; idx < FC_NB * FCO; idx += 288) {
        int bb = idx / FCO;
        int oo = idx % FCO;
        float s = red[(0 * FC_NB + bb) * FCO + oo]
                + red[(1 * FC_NB + bb) * FCO + oo]
                + red[(2 * FC_NB + bb) * FCO + oo]
                + red[(3 * FC_NB + bb) * FCO + oo];
        out[(size_t)(b0 + bb) * FCO + oo] = s + __ldg(&fb[oo]);
    }
}

// ---------------- launch ----------------
extern "C" void kernel_launch(void* const* d_in, const int* in_sizes, int n_in,
                              void* d_out, int out_size) {
    const float* x       = (const float*)d_in[0];
    const void*  eidx    = d_in[1];
    const float* gcn_w   = (const float*)d_in[2];
    const float* gcn_b   = (const float*)d_in[3];
    const float* conv_w0 = (const float*)d_in[4];
    const float* conv_b0 = (const float*)d_in[5];
    const float* down_w0 = (const float*)d_in[6];
    const float* down_b0 = (const float*)d_in[7];
    const float* conv_w1 = (const float*)d_in[8];
    const float* conv_b1 = (const float*)d_in[9];
    const float* down_w1 = (const float*)d_in[10];
    const float* down_b1 = (const float*)d_in[11];
    const float* conv_w2 = (const float*)d_in[12];
    const float* conv_b2 = (const float*)d_in[13];
    const float* down_w2 = (const float*)d_in[14];
    const float* down_b2 = (const float*)d_in[15];
    const float* fc_w    = (const float*)d_in[16];
    const float* fc_b    = (const float*)d_in[17];
    float* out = (float*)d_out;

    float *p_wt0, *p_fcwT, *p_x0;
    cudaGetSymbolAddress((void**)&p_wt0,  g_wt0);
    cudaGetSymbolAddress((void**)&p_fcwT, g_fcwT);
    cudaGetSymbolAddress((void**)&p_x0, g_x0);
    __half *p_x1h, *p_x2h, *p_x3h;
    cudaGetSymbolAddress((void**)&p_x1h, g_x1h);
    cudaGetSymbolAddress((void**)&p_x2h, g_x2h);
    cudaGetSymbolAddress((void**)&p_x3h, g_x3h);
    __half *wc1, *wd1, *wc2, *wd2;
    cudaGetSymbolAddress((void**)&wc1, g_wc1);
    cudaGetSymbolAddress((void**)&wd1, g_wd1);
    cudaGetSymbolAddress((void**)&wc2, g_wc2);
    cudaGetSymbolAddress((void**)&wd2, g_wd2);

    cudaFuncSetAttribute(tcn_mma_kernel<128, 3, 512>,
                         cudaFuncAttributeMaxDynamicSharedMemorySize, SMEM_BYTES);
    cudaFuncSetAttribute(tcn_mma_kernel<512, 9, 128>,
                         cudaFuncAttributeMaxDynamicSharedMemorySize, SMEM_BYTES);

    k_init<<<(N_NODES * 12 + 255) / 256, 256>>>();
    k_detect<<<8, 256>>>((const long long*)eidx);

    k_prep<<<(S5 + 255) / 256, 256>>>(conv_w0, down_w0, conv_w1, down_w1,
                                      conv_w2, down_w2, fc_w);

    k_deg<<<(NEDGE + 255) / 256, 256>>>(eidx);
    k_h<<<(N_NODES + 127) / 128, 128>>>(x, gcn_w);
    k_scatter<<<(NEDGE + 127) / 128, 128>>>(eidx);
    k_self<<<(N_NODES + 127) / 128, 128>>>(gcn_b);

    tcn0_kernel<<<BATCH, 128>>>(p_x0, p_wt0, conv_b0, down_b0, p_x1h);
    tcn_mma_kernel<128, 3, 512><<<dim3(NTOT / 128, 4), 256, SMEM_BYTES>>>(
        p_x1h, wc1, wd1, conv_b1, down_b1, p_x2h);
    tcn_mma_kernel<512, 9, 128><<<dim3(NTOT / 128, 1), 256, SMEM_BYTES>>>(
        p_x2h, wc2, wd2, conv_b2, down_b2, p_x3h);

    fc_kernel<<<BATCH / FC_NB, dim3(FCO, 4)>>>(p_x3h, p_fcwT, fc_b, out);
}

// round 10
// speedup vs baseline: 5.9402x; 1.3835x over previous
#include <cuda_runtime.h>
#include <cuda_fp16.h>
#include <cstdint>

// ---------------- problem dims ----------------
#define N_NODES 61440
#define NEDGE   491520
#define BATCH   2048
#define TT      30
#define INCH    12
#define FCF     3840
#define FCO     72
#define NTOT    (BATCH * TT)

// ---------------- PTX helpers ----------------
__device__ __forceinline__ uint32_t smem_u32(const void* p) {
    uint32_t a;
    asm("{ .reg .u64 t; cvta.to.shared.u64 t, %1; cvt.u32.u64 %0, t; }" : "=r"(a) : "l"(p));
    return a;
}
#define LDSM_X4(r0, r1, r2, r3, addr) \
    asm volatile("ldmatrix.sync.aligned.m8n8.x4.shared.b16 {%0,%1,%2,%3}, [%4];" \
        : "=r"(r0), "=r"(r1), "=r"(r2), "=r"(r3) : "r"(addr))
#define MMA_F16(acc, a, b0_, b1_) \
    asm volatile("mma.sync.aligned.m16n8k16.row.col.f32.f16.f16.f32 " \
        "{%0,%1,%2,%3}, {%4,%5,%6,%7}, {%8,%9}, {%0,%1,%2,%3};" \
        : "+f"((acc)[0]), "+f"((acc)[1]), "+f"((acc)[2]), "+f"((acc)[3]) \
        : "r"((a)[0]), "r"((a)[1]), "r"((a)[2]), "r"((a)[3]), "r"(b0_), "r"(b1_))
#define CP_ASYNC16(dst, src) \
    asm volatile("cp.async.cg.shared.global [%0], [%1], 16;" :: "r"(dst), "l"(src))
#define CP_ASYNC16Z(dst, src, sz) \
    asm volatile("cp.async.cg.shared.global [%0], [%1], 16, %2;" :: "r"(dst), "l"(src), "r"(sz))
#define CP_COMMIT() asm volatile("cp.async.commit_group;" ::: "memory")
#define CP_WAIT2()  asm volatile("cp.async.wait_group 2;" ::: "memory")
#define CP_WAIT0()  asm volatile("cp.async.wait_group 0;" ::: "memory")
#define SWZ(row, c16) (((uint32_t)(row)) * 128u + ((((uint32_t)(c16)) ^ (((uint32_t)(row)) & 7u)) << 4))

// ---------------- device scratch ----------------
__device__ float g_deg [N_NODES];
__device__ float g_dinv[N_NODES];
__device__ float g_h   [N_NODES * 12];
__device__ __align__(16) float  g_x0 [N_NODES * 12];          // [B][12][30] fp32
__device__ __align__(16) __half g_x1h[NTOT * 128];            // [n][128] fp16
__device__ __align__(16) __half g_x2h[NTOT * 512];            // [n][512] fp16
__device__ __align__(16) __half g_x3h[NTOT * 128];            // [n][128] fp16  (== [b][k'], k'=t*128+oc)
__device__ __align__(16) float  g_wt0 [12 * 4 * 128];
__device__ __align__(16) __half g_fcwh[80 * FCF];             // fp16 [80 rows (72 valid)][k'=t*128+oc]
__device__ int g_eflag[1];

// fp16 weights, [oc][k], k = j*IC + ic (j-major)
__device__ __align__(16) __half g_wc1[512 * 384];
__device__ __align__(16) __half g_wd1[512 * 128];
__device__ __align__(16) __half g_wc2[128 * 1536];
__device__ __align__(16) __half g_wd2[128 * 512];

// ---------------- init / dtype detect ----------------
__global__ void k_init() {
    int i = blockIdx.x * blockDim.x + threadIdx.x;
    if (i < N_NODES * 12) g_x0[i] = 0.0f;
    if (i < N_NODES)      g_deg[i] = 1.0f;
    if (i == 0)           g_eflag[0] = 0;
}
__global__ void k_detect(const long long* __restrict__ ep) {
    int i = blockIdx.x * blockDim.x + threadIdx.x;
    if (i < 2048) {
        long long v = ep[i];
        if (v < 0 || v >= N_NODES) atomicOr(g_eflag, 1);
    }
}
__device__ __forceinline__ void load_edge(const void* ep, int e, int& s, int& d) {
    if (g_eflag[0]) {
        const int* p = (const int*)ep;
        s = p[e]; d = p[NEDGE + e];
    } else {
        const long long* p = (const long long*)ep;
        s = (int)p[e]; d = (int)p[NEDGE + e];
    }
}
__global__ void k_initout(const float* __restrict__ fb, float* __restrict__ out) {
    int i = blockIdx.x * blockDim.x + threadIdx.x;
    if (i < BATCH * FCO) out[i] = fb[i % FCO];
}

// ---------------- fused weight prep (single launch) ----------------
#define S0 6144
#define S1 (S0 + 196608)
#define S2 (S1 + 65536)
#define S3 (S2 + 196608)
#define S4 (S3 + 65536)
#define S5 (S4 + 80 * FCF)
__global__ void k_prep(const float* __restrict__ cw0, const float* __restrict__ dw0,
                       const float* __restrict__ cw1, const float* __restrict__ dw1,
                       const float* __restrict__ cw2, const float* __restrict__ dw2,
                       const float* __restrict__ fw) {
    int id = blockIdx.x * blockDim.x + threadIdx.x;
    if (id < S0) {
        int oc = id % 128;
        int r  = id / 128;
        int j  = r % 4;
        int ic = r / 4;
        g_wt0[id] = (j < 3) ? cw0[(oc * 12 + ic) * 3 + j] : dw0[oc * 12 + ic];
    } else if (id < S1) {
        int t = id - S0;
        int oc = t / 384, r = t % 384, j = r / 128, ic = r % 128;
        g_wc1[t] = __float2half_rn(cw1[(oc * 128 + ic) * 3 + j]);
    } else if (id < S2) {
        int t = id - S1;
        g_wd1[t] = __float2half_rn(dw1[t]);
    } else if (id < S3) {
        int t = id - S2;
        int oc = t / 1536, r = t % 1536, j = r / 512, ic = r % 512;
        g_wc2[t] = __float2half_rn(cw2[(oc * 512 + ic) * 3 + j]);
    } else if (id < S4) {
        int t = id - S3;
        g_wd2[t] = __float2half_rn(dw2[t]);
    } else if (id < S5) {
        int t  = id - S4;       // [o_row][k'], k' = tt*128 + oc; src f = oc*30 + tt
        int kp = t % FCF;
        int o  = t / FCF;
        int oc = kp % 128;
        int tt = kp / 128;
        g_fcwh[t] = (o < FCO) ? __float2half_rn(fw[o * FCF + oc * 30 + tt])
                              : __half(0.0f);
    }
}

// ---------------- GCN ----------------
__global__ void k_deg(const void* __restrict__ ep) {
    int e = blockIdx.x * blockDim.x + threadIdx.x;
    if (e >= NEDGE) return;
    int s, d;
    load_edge(ep, e, s, d);
    atomicAdd(&g_deg[d], 1.0f);
}
__global__ void k_h(const float* __restrict__ x, const float* __restrict__ gw) {
    int n = blockIdx.x * blockDim.x + threadIdx.x;
    if (n >= N_NODES) return;
    const float4* xp = (const float4*)(x + (size_t)n * 12);
    float4 a = xp[0], b = xp[1], c = xp[2];
    float xv[12] = {a.x,a.y,a.z,a.w, b.x,b.y,b.z,b.w, c.x,c.y,c.z,c.w};
    #pragma unroll
    for (int o = 0; o < 12; ++o) {
        float acc = 0.0f;
        #pragma unroll
        for (int i = 0; i < 12; ++i)
            acc = fmaf(xv[i], __ldg(&gw[o * 12 + i]), acc);
        g_h[n * 12 + o] = acc;
    }
    g_dinv[n] = rsqrtf(g_deg[n]);
}
__global__ void k_scatter(const void* __restrict__ ep) {
    int e = blockIdx.x * blockDim.x + threadIdx.x;
    if (e >= NEDGE) return;
    int s, d;
    load_edge(ep, e, s, d);
    float nm = g_dinv[s] * g_dinv[d];
    int base = (d / 30) * (12 * TT) + (d % 30);
    const float4* hp = (const float4*)(g_h + (size_t)s * 12);
    float4 a = hp[0], b = hp[1], c = hp[2];
    float hv[12] = {a.x,a.y,a.z,a.w, b.x,b.y,b.z,b.w, c.x,c.y,c.z,c.w};
    #pragma unroll
    for (int cch = 0; cch < 12; ++cch)
        atomicAdd(&g_x0[base + cch * TT], nm * hv[cch]);
}

// ---------------- block 0: scalar TCN (self-loop fused) -> fp16 [n][128] ----------------
__global__ __launch_bounds__(128)
void tcn0_kernel(const float* __restrict__ Xin, const float* __restrict__ wt,
                 const float* __restrict__ gb,
                 const float* __restrict__ cb, const float* __restrict__ db,
                 __half* __restrict__ X1h) {
    __shared__ float xs[12 * TT];
    __shared__ __half st[TT * 128];
    int b  = blockIdx.x;
    int oc = threadIdx.x;

    const float* src = Xin + (size_t)b * 12 * TT;
    for (int i = threadIdx.x; i < 12 * TT; i += 128) {
        int ic = i / TT, t = i - ic * TT;
        int node = b * TT + t;
        float di = g_dinv[node];
        xs[i] = src[i] + di * di * g_h[node * 12 + ic] + __ldg(&gb[ic]);
    }
    __syncthreads();

    float accC[TT], accR[TT];
    #pragma unroll
    for (int t = 0; t < TT; ++t) { accC[t] = 0.0f; accR[t] = 0.0f; }

    #pragma unroll
    for (int ic = 0; ic < 12; ++ic) {
        const float* wp = wt + (size_t)(ic * 4) * 128 + oc;
        float w0 = __ldg(wp);
        float w1 = __ldg(wp + 128);
        float w2 = __ldg(wp + 256);
        float wd = __ldg(wp + 384);
        #pragma unroll
        for (int t = 0; t < TT; ++t) {
            float xv = xs[ic * TT + t];
            accC[t] = fmaf(w2, xv, accC[t]);
            if (t + 1 < TT) accC[t + 1] = fmaf(w1, xv, accC[t + 1]);
            if (t + 2 < TT) accC[t + 2] = fmaf(w0, xv, accC[t + 2]);
            accR[t] = fmaf(wd, xv, accR[t]);
        }
    }
    float bc = __ldg(&cb[oc]);
    float bd = __ldg(&db[oc]);
    #pragma unroll
    for (int t = 0; t < TT; ++t) {
        float o1 = fmaxf(accC[t] + bc, 0.0f);
        st[t * 128 + oc] = __float2half_rn(fmaxf(o1 + accR[t] + bd, 0.0f));
    }
    __syncthreads();
    const uint32_t* sp = (const uint32_t*)st;
    uint32_t* dp = (uint32_t*)(X1h + (size_t)b * TT * 128);
    for (int i = threadIdx.x; i < TT * 64; i += 128) dp[i] = sp[i];
}

// ---------------- TCN blocks 1/2: 3-stage pipelined fp16 mma GEMM ----------------
// CTA tile: 128 oc x NT n. 8 warps = 4M x 2N; warp tile 32m x NT/2 n.
template<int IC, int DIL, int OCTOT, int NT>
__global__ __launch_bounds__(256, 1)
void tcn_mma_kernel(const __half* __restrict__ Act,
                    const __half* __restrict__ Wc, const __half* __restrict__ Wd,
                    const float* __restrict__ cb, const float* __restrict__ db,
                    __half* __restrict__ Xout) {
    extern __shared__ char smem[];
    const uint32_t sb = smem_u32(smem);
    const int tid  = threadIdx.x;
    const int wid  = tid >> 5;
    const int lane = tid & 31;

    constexpr int KC  = 3 * IC;
    constexpr int NCH = KC / 64;
    constexpr int J2  = 2 * IC / 64;
    constexpr int GN  = NT / 32;          // gn tiles per warp (16 n each)
    constexpr int FN  = NT / 16;          // acc fn count
    constexpr uint32_t OFF_B  = 16384;
    constexpr uint32_t OFF_AD = 16384 + NT * 128;
    constexpr uint32_t STAGE  = OFF_AD + 16384;
    const uint32_t AUX = 3 * STAGE;

    const int n0    = blockIdx.x * NT;
    const int mtile = blockIdx.y;

    float* bcS = (float*)(smem + AUX);
    float* bdS = (float*)(smem + AUX + 512);
    if (tid < 128) {
        bcS[tid] = cb[mtile * 128 + tid];
        bdS[tid] = db[mtile * 128 + tid];
    }

    const int frow = tid >> 3;
    const int fc16 = tid & 7;

    auto fill = [&](int ch, int stg) {
        const uint32_t base = sb + stg * STAGE;
        const int k0 = ch * 64;
        const int j  = k0 / IC;
        const int ic0 = k0 - j * IC;
        const int shift = (2 - j) * DIL;
        {
            const __half* Wp = Wc + (size_t)(mtile * 128) * KC + k0 + fc16 * 8;
            #pragma unroll
            for (int r2 = 0; r2 < 4; ++r2) {
                int row = frow + r2 * 32;
                CP_ASYNC16(base + SWZ(row, fc16), Wp + (size_t)row * KC);
            }
        }
        {
            #pragma unroll
            for (int r2 = 0; r2 < NT / 32; ++r2) {
                int row  = frow + r2 * 32;
                int ncol = n0 + row;
                int bb   = ncol / 30;
                int tt   = ncol - bb * 30;
                int tsrc = tt - shift;
                uint32_t sz = (tsrc >= 0) ? 16u : 0u;
                int ts = tsrc >= 0 ? tsrc : 0;
                const __half* s = Act + ((size_t)(bb * 30 + ts) * IC + ic0 + fc16 * 8);
                CP_ASYNC16Z(base + OFF_B + SWZ(row, fc16), s, sz);
            }
        }
        if (ch >= J2) {
            const int kd0 = k0 - 2 * IC;
            const __half* Wp = Wd + (size_t)(mtile * 128) * IC + kd0 + fc16 * 8;
            #pragma unroll
            for (int r2 = 0; r2 < 4; ++r2) {
                int row = frow + r2 * 32;
                CP_ASYNC16(base + OFF_AD + SWZ(row, fc16), Wp + (size_t)row * IC);
            }
        }
    };

    float accC[2][FN][4], accD[2][FN][4];
    #pragma unroll
    for (int i = 0; i < 2; ++i)
        #pragma unroll
        for (int j = 0; j < FN; ++j)
            #pragma unroll
            for (int r = 0; r < 4; ++r) { accC[i][j][r] = 0.0f; accD[i][j][r] = 0.0f; }

    const int warpM = wid & 3;
    const int warpN = wid >> 2;
    const int arL = lane & 15;
    const int acL = lane >> 4;
    const int brL = (lane & 7) + ((lane >> 4) << 3);
    const int bcL = (lane >> 3) & 1;

    fill(0, 0);
    CP_COMMIT();
    if (NCH > 1) fill(1, 1);
    CP_COMMIT();

    int stg = 0;
    #pragma unroll 1
    for (int ch = 0; ch < NCH; ++ch) {
        if (ch + 2 < NCH) {
            int s2 = stg + 2; if (s2 >= 3) s2 -= 3;
            fill(ch + 2, s2);
        }
        CP_COMMIT();
        CP_WAIT2();
        __syncthreads();

        const uint32_t base = sb + stg * STAGE;
        const bool dn = (ch >= J2);

        #pragma unroll
        for (int ks = 0; ks < 4; ++ks) {
            uint32_t aq[2][4];
            #pragma unroll
            for (int fm = 0; fm < 2; ++fm) {
                int r = warpM * 32 + fm * 16 + arL;
                uint32_t ad = base + SWZ(r, ks * 2 + acL);
                LDSM_X4(aq[fm][0], aq[fm][1], aq[fm][2], aq[fm][3], ad);
            }
            uint32_t bq[GN][4];
            #pragma unroll
            for (int gn = 0; gn < GN; ++gn) {
                int r = warpN * (NT / 2) + gn * 16 + brL;
                uint32_t bd_ = base + OFF_B + SWZ(r, ks * 2 + bcL);
                LDSM_X4(bq[gn][0], bq[gn][1], bq[gn][2], bq[gn][3], bd_);
            }
            #pragma unroll
            for (int fm = 0; fm < 2; ++fm)
                #pragma unroll
                for (int gn = 0; gn < GN; ++gn) {
                    MMA_F16(accC[fm][2 * gn],     aq[fm], bq[gn][0], bq[gn][1]);
                    MMA_F16(accC[fm][2 * gn + 1], aq[fm], bq[gn][2], bq[gn][3]);
                }
            if (dn) {
                uint32_t dq[2][4];
                #pragma unroll
                for (int fm = 0; fm < 2; ++fm) {
                    int r = warpM * 32 + fm * 16 + arL;
                    uint32_t ad = base + OFF_AD + SWZ(r, ks * 2 + acL);
                    LDSM_X4(dq[fm][0], dq[fm][1], dq[fm][2], dq[fm][3], ad);
                }
                #pragma unroll
                for (int fm = 0; fm < 2; ++fm)
                    #pragma unroll
                    for (int gn = 0; gn < GN; ++gn) {
                        MMA_F16(accD[fm][2 * gn],     dq[fm], bq[gn][0], bq[gn][1]);
                        MMA_F16(accD[fm][2 * gn + 1], dq[fm], bq[gn][2], bq[gn][3]);
                    }
            }
        }
        __syncthreads();
        if (++stg == 3) stg = 0;
    }

    // ---- epilogue: regs -> smem [n][oc] -> coalesced fp16 STG ----
    float* resBuf = (float*)smem;  // [NT n][129 pitch]
    #pragma unroll
    for (int fm = 0; fm < 2; ++fm) {
        int mloc = warpM * 32 + fm * 16 + (lane >> 2);
        #pragma unroll
        for (int fn = 0; fn < FN; ++fn) {
            int nloc = warpN * (NT / 2) + fn * 8 + ((lane & 3) << 1);
            #pragma unroll
            for (int r = 0; r < 4; ++r) {
                int m = mloc + ((r >> 1) << 3);
                int n = nloc + (r & 1);
                float c = fmaxf(accC[fm][fn][r] + bcS[m], 0.0f);
                float v = fmaxf(c + accD[fm][fn][r] + bdS[m], 0.0f);
                resBuf[n * 129 + m] = v;
            }
        }
    }
    __syncthreads();
    const int ocg0 = mtile * 128;
    #pragma unroll 1
    for (int idx = tid; idx < NT * 64; idx += 256) {
        int n = idx >> 6, op = idx & 63;
        __half2 h = __floats2half2_rn(resBuf[n * 129 + 2 * op], resBuf[n * 129 + 2 * op + 1]);
        *(__half2*)(Xout + ((size_t)(n0 + n) * OCTOT + ocg0 + 2 * op)) = h;
    }
}

// ---------------- FC via fp16 MMA: out[b][o] += sum_k' X3h[b][k'] * fcwh[o][k'] ----------------
// grid (16 ntile, 12 kseg); 320 threads = 10 warps (5M x 2N). K-seg = 320 (5 chunks of 64).
#define FC_KSEG 320
__global__ __launch_bounds__(320)
void fc_mma_kernel(const __half* __restrict__ X, const __half* __restrict__ W,
                   float* __restrict__ out) {
    extern __shared__ char smem[];
    const uint32_t sb = smem_u32(smem);
    const uint32_t OFF_BX = 80 * 128;   // A: 80 rows x 128B = 10240
    const int tid  = threadIdx.x;
    const int wid  = tid >> 5;
    const int lane = tid & 31;

    const int n0 = blockIdx.x * 128;
    const int kbase = blockIdx.y * FC_KSEG;

    const int warpM = wid % 5;
    const int warpN = wid / 5;
    const int arL = lane & 15;
    const int acL = lane >> 4;
    const int brL = (lane & 7) + ((lane >> 4) << 3);
    const int bcL = (lane >> 3) & 1;

    float acc[8][4];
    #pragma unroll
    for (int j = 0; j < 8; ++j)
        #pragma unroll
        for (int r = 0; r < 4; ++r) acc[j][r] = 0.0f;

    #pragma unroll 1
    for (int ch = 0; ch < 5; ++ch) {
        const int k0 = kbase + ch * 64;
        __syncthreads();
        // A fill: 80 rows x 8 c16
        for (int s = tid; s < 80 * 8; s += 320) {
            int row = s >> 3, c16 = s & 7;
            CP_ASYNC16(sb + SWZ(row, c16), W + (size_t)row * FCF + k0 + c16 * 8);
        }
        // B fill: 128 rows x 8 c16
        for (int s = tid; s < 128 * 8; s += 320) {
            int row = s >> 3, c16 = s & 7;
            CP_ASYNC16(sb + OFF_BX + SWZ(row, c16),
                       X + (size_t)(n0 + row) * FCF + k0 + c16 * 8);
        }
        CP_COMMIT();
        CP_WAIT0();
        __syncthreads();

        #pragma unroll
        for (int ks = 0; ks < 4; ++ks) {
            uint32_t aq[4];
            {
                int r = warpM * 16 + arL;
                uint32_t ad = sb + SWZ(r, ks * 2 + acL);
                LDSM_X4(aq[0], aq[1], aq[2], aq[3], ad);
            }
            uint32_t bq[4][4];
            #pragma unroll
            for (int gn = 0; gn < 4; ++gn) {
                int r = warpN * 64 + gn * 16 + brL;
                uint32_t bd_ = sb + OFF_BX + SWZ(r, ks * 2 + bcL);
                LDSM_X4(bq[gn][0], bq[gn][1], bq[gn][2], bq[gn][3], bd_);
            }
            #pragma unroll
            for (int gn = 0; gn < 4; ++gn) {
                MMA_F16(acc[2 * gn],     aq, bq[gn][0], bq[gn][1]);
                MMA_F16(acc[2 * gn + 1], aq, bq[gn][2], bq[gn][3]);
            }
        }
    }

    // epilogue: atomic add partial sums into out[b][o]
    #pragma unroll
    for (int fn = 0; fn < 8; ++fn) {
        int nloc = warpN * 64 + fn * 8 + ((lane & 3) << 1);
        #pragma unroll
        for (int r = 0; r < 4; ++r) {
            int m = warpM * 16 + (lane >> 2) + ((r >> 1) << 3);
            int n = nloc + (r & 1);
            if (m < FCO)
                atomicAdd(&out[(size_t)(n0 + n) * FCO + m], acc[fn][r]);
        }
    }
}

// ---------------- launch ----------------
extern "C" void kernel_launch(void* const* d_in, const int* in_sizes, int n_in,
                              void* d_out, int out_size) {
    const float* x       = (const float*)d_in[0];
    const void*  eidx    = d_in[1];
    const float* gcn_w   = (const float*)d_in[2];
    const float* gcn_b   = (const float*)d_in[3];
    const float* conv_w0 = (const float*)d_in[4];
    const float* conv_b0 = (const float*)d_in[5];
    const float* down_w0 = (const float*)d_in[6];
    const float* down_b0 = (const float*)d_in[7];
    const float* conv_w1 = (const float*)d_in[8];
    const float* conv_b1 = (const float*)d_in[9];
    const float* down_w1 = (const float*)d_in[10];
    const float* down_b1 = (const float*)d_in[11];
    const float* conv_w2 = (const float*)d_in[12];
    const float* conv_b2 = (const float*)d_in[13];
    const float* down_w2 = (const float*)d_in[14];
    const float* down_b2 = (const float*)d_in[15];
    const float* fc_w    = (const float*)d_in[16];
    const float* fc_b    = (const float*)d_in[17];
    float* out = (float*)d_out;

    float *p_wt0, *p_x0;
    cudaGetSymbolAddress((void**)&p_wt0, g_wt0);
    cudaGetSymbolAddress((void**)&p_x0, g_x0);
    __half *p_x1h, *p_x2h, *p_x3h, *p_fcwh;
    cudaGetSymbolAddress((void**)&p_x1h, g_x1h);
    cudaGetSymbolAddress((void**)&p_x2h, g_x2h);
    cudaGetSymbolAddress((void**)&p_x3h, g_x3h);
    cudaGetSymbolAddress((void**)&p_fcwh, g_fcwh);
    __half *wc1, *wd1, *wc2, *wd2;
    cudaGetSymbolAddress((void**)&wc1, g_wc1);
    cudaGetSymbolAddress((void**)&wd1, g_wd1);
    cudaGetSymbolAddress((void**)&wc2, g_wc2);
    cudaGetSymbolAddress((void**)&wd2, g_wd2);

    // smem sizes
    const int SM1 = 3 * (16384 + 128 * 128 + 16384) + 1024;  // NT=128
    const int SM2 = 3 * (16384 + 64 * 128 + 16384) + 1024;   // NT=64
    const int SMF = 80 * 128 + 128 * 128;
    cudaFuncSetAttribute(tcn_mma_kernel<128, 3, 512, 128>,
                         cudaFuncAttributeMaxDynamicSharedMemorySize, SM1);
    cudaFuncSetAttribute(tcn_mma_kernel<512, 9, 128, 64>,
                         cudaFuncAttributeMaxDynamicSharedMemorySize, SM2);
    cudaFuncSetAttribute(fc_mma_kernel,
                         cudaFuncAttributeMaxDynamicSharedMemorySize, SMF);

    k_init<<<(N_NODES * 12 + 255) / 256, 256>>>();
    k_detect<<<8, 256>>>((const long long*)eidx);
    k_initout<<<(BATCH * FCO + 255) / 256, 256>>>(fc_b, out);

    k_prep<<<(S5 + 255) / 256, 256>>>(conv_w0, down_w0, conv_w1, down_w1,
                                      conv_w2, down_w2, fc_w);

    k_deg<<<(NEDGE + 255) / 256, 256>>>(eidx);
    k_h<<<(N_NODES + 127) / 128, 128>>>(x, gcn_w);
    k_scatter<<<(NEDGE + 127) / 128, 128>>>(eidx);

    tcn0_kernel<<<BATCH, 128>>>(p_x0, p_wt0, gcn_b, conv_b0, down_b0, p_x1h);
    tcn_mma_kernel<128, 3, 512, 128><<<dim3(NTOT / 128, 4), 256, SM1>>>(
        p_x1h, wc1, wd1, conv_b1, down_b1, p_x2h);
    tcn_mma_kernel<512, 9, 128, 64><<<dim3(NTOT / 64, 1), 256, SM2>>>(
        p_x2h, wc2, wd2, conv_b2, down_b2, p_x3h);

    fc_mma_kernel<<<dim3(BATCH / 128, FCF / FC_KSEG), 320, SMF>>>(p_x3h, p_fcwh, out);
}

// round 11
// speedup vs baseline: 6.4648x; 1.0883x over previous
#include <cuda_runtime.h>
#include <cuda_fp16.h>
#include <cstdint>

// ---------------- problem dims ----------------
#define N_NODES 61440
#define NEDGE   491520
#define BATCH   2048
#define TT      30
#define INCH    12
#define FCF     3840
#define FCO     72
#define NTOT    (BATCH * TT)

// ---------------- PTX helpers ----------------
__device__ __forceinline__ uint32_t smem_u32(const void* p) {
    uint32_t a;
    asm("{ .reg .u64 t; cvta.to.shared.u64 t, %1; cvt.u32.u64 %0, t; }" : "=r"(a) : "l"(p));
    return a;
}
#define LDSM_X4(r0, r1, r2, r3, addr) \
    asm volatile("ldmatrix.sync.aligned.m8n8.x4.shared.b16 {%0,%1,%2,%3}, [%4];" \
        : "=r"(r0), "=r"(r1), "=r"(r2), "=r"(r3) : "r"(addr))
#define MMA_F16(acc, a, b0_, b1_) \
    asm volatile("mma.sync.aligned.m16n8k16.row.col.f32.f16.f16.f32 " \
        "{%0,%1,%2,%3}, {%4,%5,%6,%7}, {%8,%9}, {%0,%1,%2,%3};" \
        : "+f"((acc)[0]), "+f"((acc)[1]), "+f"((acc)[2]), "+f"((acc)[3]) \
        : "r"((a)[0]), "r"((a)[1]), "r"((a)[2]), "r"((a)[3]), "r"(b0_), "r"(b1_))
#define CP_ASYNC16(dst, src) \
    asm volatile("cp.async.cg.shared.global [%0], [%1], 16;" :: "r"(dst), "l"(src))
#define CP_ASYNC16Z(dst, src, sz) \
    asm volatile("cp.async.cg.shared.global [%0], [%1], 16, %2;" :: "r"(dst), "l"(src), "r"(sz))
#define CP_COMMIT() asm volatile("cp.async.commit_group;" ::: "memory")
#define CP_WAIT2()  asm volatile("cp.async.wait_group 2;" ::: "memory")
#define CP_WAIT0()  asm volatile("cp.async.wait_group 0;" ::: "memory")
#define SWZ(row, c16) (((uint32_t)(row)) * 128u + ((((uint32_t)(c16)) ^ (((uint32_t)(row)) & 7u)) << 4))
#define RED_V4(ptr, a, b, c, d) \
    asm volatile("red.global.add.v4.f32 [%0], {%1, %2, %3, %4};" \
        :: "l"(ptr), "f"(a), "f"(b), "f"(c), "f"(d) : "memory")

// ---------------- device scratch ----------------
__device__ float g_deg [N_NODES];
__device__ float g_dinv[N_NODES];
__device__ __align__(16) float  g_h  [N_NODES * 12];          // [node][12]
__device__ __align__(16) float  g_x0 [N_NODES * 12];          // [node][12] (channel-contig!)
__device__ __align__(16) __half g_x1h[NTOT * 128];            // [n][128] fp16
__device__ __align__(16) __half g_x2h[NTOT * 512];            // [n][512] fp16
__device__ __align__(16) __half g_x3h[NTOT * 128];            // [n][128] fp16 (== [b][k'], k'=t*128+oc)
__device__ __align__(16) float  g_wt0 [12 * 4 * 128];
__device__ __align__(16) __half g_fcwh[80 * FCF];             // fp16 [80 rows (72 valid)][k']
__device__ int g_eflag[1];                                    // idempotent OR, never reset

// fp16 weights, [oc][k], k = j*IC + ic (j-major)
__device__ __align__(16) __half g_wc1[512 * 384];
__device__ __align__(16) __half g_wd1[512 * 128];
__device__ __align__(16) __half g_wc2[128 * 1536];
__device__ __align__(16) __half g_wd2[128 * 512];

__device__ __forceinline__ void load_edge(const void* ep, int e, int& s, int& d) {
    if (g_eflag[0]) {
        const int* p = (const int*)ep;
        s = p[e]; d = p[NEDGE + e];
    } else {
        const long long* p = (const long long*)ep;
        s = (int)p[e]; d = (int)p[NEDGE + e];
    }
}

// ---------------- fused init + detect + out-bias + weight prep (ONE launch) ----------------
#define P0 (N_NODES * 12)                 // x0 zero (+ deg=1 for i<N_NODES)
#define P1 (P0 + BATCH * FCO)             // out bias init
#define P2 (P1 + 2048)                    // dtype detect
#define Q0 (P2 + 6144)                    // wt0
#define Q1 (Q0 + 196608)                  // wc1
#define Q2 (Q1 + 65536)                   // wd1
#define Q3 (Q2 + 196608)                  // wc2
#define Q4 (Q3 + 65536)                   // wd2
#define Q5 (Q4 + 80 * FCF)                // fcwh
__global__ void k_setup(const void* __restrict__ ep,
                        const float* __restrict__ fb, float* __restrict__ out,
                        const float* __restrict__ cw0, const float* __restrict__ dw0,
                        const float* __restrict__ cw1, const float* __restrict__ dw1,
                        const float* __restrict__ cw2, const float* __restrict__ dw2,
                        const float* __restrict__ fw) {
    int id = blockIdx.x * blockDim.x + threadIdx.x;
    if (id < P0) {
        g_x0[id] = 0.0f;
        if (id < N_NODES) g_deg[id] = 1.0f;
    } else if (id < P1) {
        int i = id - P0;
        out[i] = fb[i % FCO];
    } else if (id < P2) {
        int i = id - P1;
        long long v = ((const long long*)ep)[i];
        if (v < 0 || v >= N_NODES) atomicOr(g_eflag, 1);
    } else if (id < Q0) {
        int t = id - P2;
        int oc = t % 128;
        int r  = t / 128;
        int j  = r % 4;
        int ic = r / 4;
        g_wt0[t] = (j < 3) ? cw0[(oc * 12 + ic) * 3 + j] : dw0[oc * 12 + ic];
    } else if (id < Q1) {
        int t = id - Q0;
        int oc = t / 384, r = t % 384, j = r / 128, ic = r % 128;
        g_wc1[t] = __float2half_rn(cw1[(oc * 128 + ic) * 3 + j]);
    } else if (id < Q2) {
        int t = id - Q1;
        g_wd1[t] = __float2half_rn(dw1[t]);
    } else if (id < Q3) {
        int t = id - Q2;
        int oc = t / 1536, r = t % 1536, j = r / 512, ic = r % 512;
        g_wc2[t] = __float2half_rn(cw2[(oc * 512 + ic) * 3 + j]);
    } else if (id < Q4) {
        int t = id - Q3;
        g_wd2[t] = __float2half_rn(dw2[t]);
    } else if (id < Q5) {
        int t  = id - Q4;       // [o_row][k'], k' = tt*128 + oc; src f = oc*30 + tt
        int kp = t % FCF;
        int o  = t / FCF;
        int oc = kp % 128;
        int tt = kp / 128;
        g_fcwh[t] = (o < FCO) ? __float2half_rn(fw[o * FCF + oc * 30 + tt])
                              : __half(0.0f);
    }
}

// ---------------- GCN ----------------
__global__ void k_deg(const void* __restrict__ ep) {
    int t = blockIdx.x * blockDim.x + threadIdx.x;
    if (t * 4 >= NEDGE) return;
    int d0, d1, d2, d3;
    if (g_eflag[0]) {
        const int4* p = (const int4*)((const int*)ep + NEDGE);
        int4 v = p[t];
        d0 = v.x; d1 = v.y; d2 = v.z; d3 = v.w;
    } else {
        const longlong2* p = (const longlong2*)((const long long*)ep + NEDGE);
        longlong2 a = p[2 * t], b = p[2 * t + 1];
        d0 = (int)a.x; d1 = (int)a.y; d2 = (int)b.x; d3 = (int)b.y;
    }
    atomicAdd(&g_deg[d0], 1.0f);
    atomicAdd(&g_deg[d1], 1.0f);
    atomicAdd(&g_deg[d2], 1.0f);
    atomicAdd(&g_deg[d3], 1.0f);
}
__global__ void k_h(const float* __restrict__ x, const float* __restrict__ gw) {
    int n = blockIdx.x * blockDim.x + threadIdx.x;
    if (n >= N_NODES) return;
    const float4* xp = (const float4*)(x + (size_t)n * 12);
    float4 a = xp[0], b = xp[1], c = xp[2];
    float xv[12] = {a.x,a.y,a.z,a.w, b.x,b.y,b.z,b.w, c.x,c.y,c.z,c.w};
    #pragma unroll
    for (int o = 0; o < 12; ++o) {
        float acc = 0.0f;
        #pragma unroll
        for (int i = 0; i < 12; ++i)
            acc = fmaf(xv[i], __ldg(&gw[o * 12 + i]), acc);
        g_h[n * 12 + o] = acc;
    }
    g_dinv[n] = rsqrtf(g_deg[n]);
}
__global__ void k_scatter(const void* __restrict__ ep) {
    int e = blockIdx.x * blockDim.x + threadIdx.x;
    if (e >= NEDGE) return;
    int s, d;
    load_edge(ep, e, s, d);
    float nm = g_dinv[s] * g_dinv[d];
    const float4* hp = (const float4*)(g_h + (size_t)s * 12);
    float4 a = hp[0], b = hp[1], c = hp[2];
    float* base = g_x0 + (size_t)d * 12;
    RED_V4(base,     nm * a.x, nm * a.y, nm * a.z, nm * a.w);
    RED_V4(base + 4, nm * b.x, nm * b.y, nm * b.z, nm * b.w);
    RED_V4(base + 8, nm * c.x, nm * c.y, nm * c.z, nm * c.w);
}

// ---------------- block 0: scalar TCN (self-loop fused) -> fp16 [n][128] ----------------
__global__ __launch_bounds__(128)
void tcn0_kernel(const float* __restrict__ Xin, const float* __restrict__ wt,
                 const float* __restrict__ gb,
                 const float* __restrict__ cb, const float* __restrict__ db,
                 __half* __restrict__ X1h) {
    __shared__ float xs[12 * TT];
    __shared__ __half st[TT * 128];
    int b  = blockIdx.x;
    int oc = threadIdx.x;

    // x0 is [node][12]; fuse GCN self-loop + gcn bias, transpose into xs[ic][t]
    if (threadIdx.x < 90) {
        int nd = threadIdx.x / 3, q = threadIdx.x - nd * 3;
        int node = b * TT + nd;
        float di = g_dinv[node];
        float nm = di * di;
        float4 xv = ((const float4*)(Xin + (size_t)node * 12))[q];
        float4 hv = ((const float4*)(g_h + (size_t)node * 12))[q];
        const float* xf = (const float*)&xv;
        const float* hf = (const float*)&hv;
        #pragma unroll
        for (int c = 0; c < 4; ++c) {
            int ic = q * 4 + c;
            xs[ic * TT + nd] = xf[c] + nm * hf[c] + __ldg(&gb[ic]);
        }
    }
    __syncthreads();

    float accC[TT], accR[TT];
    #pragma unroll
    for (int t = 0; t < TT; ++t) { accC[t] = 0.0f; accR[t] = 0.0f; }

    #pragma unroll
    for (int ic = 0; ic < 12; ++ic) {
        const float* wp = wt + (size_t)(ic * 4) * 128 + oc;
        float w0 = __ldg(wp);
        float w1 = __ldg(wp + 128);
        float w2 = __ldg(wp + 256);
        float wd = __ldg(wp + 384);
        #pragma unroll
        for (int t = 0; t < TT; ++t) {
            float xv = xs[ic * TT + t];
            accC[t] = fmaf(w2, xv, accC[t]);
            if (t + 1 < TT) accC[t + 1] = fmaf(w1, xv, accC[t + 1]);
            if (t + 2 < TT) accC[t + 2] = fmaf(w0, xv, accC[t + 2]);
            accR[t] = fmaf(wd, xv, accR[t]);
        }
    }
    float bc = __ldg(&cb[oc]);
    float bd = __ldg(&db[oc]);
    #pragma unroll
    for (int t = 0; t < TT; ++t) {
        float o1 = fmaxf(accC[t] + bc, 0.0f);
        st[t * 128 + oc] = __float2half_rn(fmaxf(o1 + accR[t] + bd, 0.0f));
    }
    __syncthreads();
    const uint32_t* sp = (const uint32_t*)st;
    uint32_t* dp = (uint32_t*)(X1h + (size_t)b * TT * 128);
    for (int i = threadIdx.x; i < TT * 64; i += 128) dp[i] = sp[i];
}

// ---------------- TCN blocks 1/2: 3-stage pipelined fp16 mma GEMM ----------------
template<int IC, int DIL, int OCTOT, int NT>
__global__ __launch_bounds__(256, 1)
void tcn_mma_kernel(const __half* __restrict__ Act,
                    const __half* __restrict__ Wc, const __half* __restrict__ Wd,
                    const float* __restrict__ cb, const float* __restrict__ db,
                    __half* __restrict__ Xout) {
    extern __shared__ char smem[];
    const uint32_t sb = smem_u32(smem);
    const int tid  = threadIdx.x;
    const int wid  = tid >> 5;
    const int lane = tid & 31;

    constexpr int KC  = 3 * IC;
    constexpr int NCH = KC / 64;
    constexpr int J2  = 2 * IC / 64;
    constexpr int GN  = NT / 32;
    constexpr int FN  = NT / 16;
    constexpr uint32_t OFF_B  = 16384;
    constexpr uint32_t OFF_AD = 16384 + NT * 128;
    constexpr uint32_t STAGE  = OFF_AD + 16384;
    const uint32_t AUX = 3 * STAGE;

    const int n0    = blockIdx.x * NT;
    const int mtile = blockIdx.y;

    float* bcS = (float*)(smem + AUX);
    float* bdS = (float*)(smem + AUX + 512);
    if (tid < 128) {
        bcS[tid] = cb[mtile * 128 + tid];
        bdS[tid] = db[mtile * 128 + tid];
    }

    const int frow = tid >> 3;
    const int fc16 = tid & 7;

    auto fill = [&](int ch, int stg) {
        const uint32_t base = sb + stg * STAGE;
        const int k0 = ch * 64;
        const int j  = k0 / IC;
        const int ic0 = k0 - j * IC;
        const int shift = (2 - j) * DIL;
        {
            const __half* Wp = Wc + (size_t)(mtile * 128) * KC + k0 + fc16 * 8;
            #pragma unroll
            for (int r2 = 0; r2 < 4; ++r2) {
                int row = frow + r2 * 32;
                CP_ASYNC16(base + SWZ(row, fc16), Wp + (size_t)row * KC);
            }
        }
        {
            #pragma unroll
            for (int r2 = 0; r2 < NT / 32; ++r2) {
                int row  = frow + r2 * 32;
                int ncol = n0 + row;
                int bb   = ncol / 30;
                int tt   = ncol - bb * 30;
                int tsrc = tt - shift;
                uint32_t sz = (tsrc >= 0) ? 16u : 0u;
                int ts = tsrc >= 0 ? tsrc : 0;
                const __half* s = Act + ((size_t)(bb * 30 + ts) * IC + ic0 + fc16 * 8);
                CP_ASYNC16Z(base + OFF_B + SWZ(row, fc16), s, sz);
            }
        }
        if (ch >= J2) {
            const int kd0 = k0 - 2 * IC;
            const __half* Wp = Wd + (size_t)(mtile * 128) * IC + kd0 + fc16 * 8;
            #pragma unroll
            for (int r2 = 0; r2 < 4; ++r2) {
                int row = frow + r2 * 32;
                CP_ASYNC16(base + OFF_AD + SWZ(row, fc16), Wp + (size_t)row * IC);
            }
        }
    };

    float accC[2][FN][4], accD[2][FN][4];
    #pragma unroll
    for (int i = 0; i < 2; ++i)
        #pragma unroll
        for (int j = 0; j < FN; ++j)
            #pragma unroll
            for (int r = 0; r < 4; ++r) { accC[i][j][r] = 0.0f; accD[i][j][r] = 0.0f; }

    const int warpM = wid & 3;
    const int warpN = wid >> 2;
    const int arL = lane & 15;
    const int acL = lane >> 4;
    const int brL = (lane & 7) + ((lane >> 4) << 3);
    const int bcL = (lane >> 3) & 1;

    fill(0, 0);
    CP_COMMIT();
    if (NCH > 1) fill(1, 1);
    CP_COMMIT();

    int stg = 0;
    #pragma unroll 1
    for (int ch = 0; ch < NCH; ++ch) {
        if (ch + 2 < NCH) {
            int s2 = stg + 2; if (s2 >= 3) s2 -= 3;
            fill(ch + 2, s2);
        }
        CP_COMMIT();
        CP_WAIT2();
        __syncthreads();

        const uint32_t base = sb + stg * STAGE;
        const bool dn = (ch >= J2);

        #pragma unroll
        for (int ks = 0; ks < 4; ++ks) {
            uint32_t aq[2][4];
            #pragma unroll
            for (int fm = 0; fm < 2; ++fm) {
                int r = warpM * 32 + fm * 16 + arL;
                uint32_t ad = base + SWZ(r, ks * 2 + acL);
                LDSM_X4(aq[fm][0], aq[fm][1], aq[fm][2], aq[fm][3], ad);
            }
            uint32_t bq[GN][4];
            #pragma unroll
            for (int gn = 0; gn < GN; ++gn) {
                int r = warpN * (NT / 2) + gn * 16 + brL;
                uint32_t bd_ = base + OFF_B + SWZ(r, ks * 2 + bcL);
                LDSM_X4(bq[gn][0], bq[gn][1], bq[gn][2], bq[gn][3], bd_);
            }
            #pragma unroll
            for (int fm = 0; fm < 2; ++fm)
                #pragma unroll
                for (int gn = 0; gn < GN; ++gn) {
                    MMA_F16(accC[fm][2 * gn],     aq[fm], bq[gn][0], bq[gn][1]);
                    MMA_F16(accC[fm][2 * gn + 1], aq[fm], bq[gn][2], bq[gn][3]);
                }
            if (dn) {
                uint32_t dq[2][4];
                #pragma unroll
                for (int fm = 0; fm < 2; ++fm) {
                    int r = warpM * 32 + fm * 16 + arL;
                    uint32_t ad = base + OFF_AD + SWZ(r, ks * 2 + acL);
                    LDSM_X4(dq[fm][0], dq[fm][1], dq[fm][2], dq[fm][3], ad);
                }
                #pragma unroll
                for (int fm = 0; fm < 2; ++fm)
                    #pragma unroll
                    for (int gn = 0; gn < GN; ++gn) {
                        MMA_F16(accD[fm][2 * gn],     dq[fm], bq[gn][0], bq[gn][1]);
                        MMA_F16(accD[fm][2 * gn + 1], dq[fm], bq[gn][2], bq[gn][3]);
                    }
            }
        }
        __syncthreads();
        if (++stg == 3) stg = 0;
    }

    // ---- epilogue: regs -> smem [n][oc] -> coalesced fp16 STG ----
    float* resBuf = (float*)smem;  // [NT n][129 pitch]
    #pragma unroll
    for (int fm = 0; fm < 2; ++fm) {
        int mloc = warpM * 32 + fm * 16 + (lane >> 2);
        #pragma unroll
        for (int fn = 0; fn < FN; ++fn) {
            int nloc = warpN * (NT / 2) + fn * 8 + ((lane & 3) << 1);
            #pragma unroll
            for (int r = 0; r < 4; ++r) {
                int m = mloc + ((r >> 1) << 3);
                int n = nloc + (r & 1);
                float c = fmaxf(accC[fm][fn][r] + bcS[m], 0.0f);
                float v = fmaxf(c + accD[fm][fn][r] + bdS[m], 0.0f);
                resBuf[n * 129 + m] = v;
            }
        }
    }
    __syncthreads();
    const int ocg0 = mtile * 128;
    #pragma unroll 1
    for (int idx = tid; idx < NT * 64; idx += 256) {
        int n = idx >> 6, op = idx & 63;
        __half2 h = __floats2half2_rn(resBuf[n * 129 + 2 * op], resBuf[n * 129 + 2 * op + 1]);
        *(__half2*)(Xout + ((size_t)(n0 + n) * OCTOT + ocg0 + 2 * op)) = h;
    }
}

// ---------------- FC via fp16 MMA ----------------
#define FC_KSEG 320
__global__ __launch_bounds__(320)
void fc_mma_kernel(const __half* __restrict__ X, const __half* __restrict__ W,
                   float* __restrict__ out) {
    extern __shared__ char smem[];
    const uint32_t sb = smem_u32(smem);
    const uint32_t OFF_BX = 80 * 128;
    const int tid  = threadIdx.x;
    const int wid  = tid >> 5;
    const int lane = tid & 31;

    const int n0 = blockIdx.x * 128;
    const int kbase = blockIdx.y * FC_KSEG;

    const int warpM = wid % 5;
    const int warpN = wid / 5;
    const int arL = lane & 15;
    const int acL = lane >> 4;
    const int brL = (lane & 7) + ((lane >> 4) << 3);
    const int bcL = (lane >> 3) & 1;

    float acc[8][4];
    #pragma unroll
    for (int j = 0; j < 8; ++j)
        #pragma unroll
        for (int r = 0; r < 4; ++r) acc[j][r] = 0.0f;

    #pragma unroll 1
    for (int ch = 0; ch < 5; ++ch) {
        const int k0 = kbase + ch * 64;
        __syncthreads();
        for (int s = tid; s < 80 * 8; s += 320) {
            int row = s >> 3, c16 = s & 7;
            CP_ASYNC16(sb + SWZ(row, c16), W + (size_t)row * FCF + k0 + c16 * 8);
        }
        for (int s = tid; s < 128 * 8; s += 320) {
            int row = s >> 3, c16 = s & 7;
            CP_ASYNC16(sb + OFF_BX + SWZ(row, c16),
                       X + (size_t)(n0 + row) * FCF + k0 + c16 * 8);
        }
        CP_COMMIT();
        CP_WAIT0();
        __syncthreads();

        #pragma unroll
        for (int ks = 0; ks < 4; ++ks) {
            uint32_t aq[4];
            {
                int r = warpM * 16 + arL;
                uint32_t ad = sb + SWZ(r, ks * 2 + acL);
                LDSM_X4(aq[0], aq[1], aq[2], aq[3], ad);
            }
            uint32_t bq[4][4];
            #pragma unroll
            for (int gn = 0; gn < 4; ++gn) {
                int r = warpN * 64 + gn * 16 + brL;
                uint32_t bd_ = sb + OFF_BX + SWZ(r, ks * 2 + bcL);
                LDSM_X4(bq[gn][0], bq[gn][1], bq[gn][2], bq[gn][3], bd_);
            }
            #pragma unroll
            for (int gn = 0; gn < 4; ++gn) {
                MMA_F16(acc[2 * gn],     aq, bq[gn][0], bq[gn][1]);
                MMA_F16(acc[2 * gn + 1], aq, bq[gn][2], bq[gn][3]);
            }
        }
    }

    #pragma unroll
    for (int fn = 0; fn < 8; ++fn) {
        int nloc = warpN * 64 + fn * 8 + ((lane & 3) << 1);
        #pragma unroll
        for (int r = 0; r < 4; ++r) {
            int m = warpM * 16 + (lane >> 2) + ((r >> 1) << 3);
            int n = nloc + (r & 1);
            if (m < FCO)
                atomicAdd(&out[(size_t)(n0 + n) * FCO + m], acc[fn][r]);
        }
    }
}

// ---------------- launch ----------------
extern "C" void kernel_launch(void* const* d_in, const int* in_sizes, int n_in,
                              void* d_out, int out_size) {
    const float* x       = (const float*)d_in[0];
    const void*  eidx    = d_in[1];
    const float* gcn_w   = (const float*)d_in[2];
    const float* gcn_b   = (const float*)d_in[3];
    const float* conv_w0 = (const float*)d_in[4];
    const float* conv_b0 = (const float*)d_in[5];
    const float* down_w0 = (const float*)d_in[6];
    const float* down_b0 = (const float*)d_in[7];
    const float* conv_w1 = (const float*)d_in[8];
    const float* conv_b1 = (const float*)d_in[9];
    const float* down_w1 = (const float*)d_in[10];
    const float* down_b1 = (const float*)d_in[11];
    const float* conv_w2 = (const float*)d_in[12];
    const float* conv_b2 = (const float*)d_in[13];
    const float* down_w2 = (const float*)d_in[14];
    const float* down_b2 = (const float*)d_in[15];
    const float* fc_w    = (const float*)d_in[16];
    const float* fc_b    = (const float*)d_in[17];
    float* out = (float*)d_out;

    float *p_wt0, *p_x0;
    cudaGetSymbolAddress((void**)&p_wt0, g_wt0);
    cudaGetSymbolAddress((void**)&p_x0, g_x0);
    __half *p_x1h, *p_x2h, *p_x3h, *p_fcwh;
    cudaGetSymbolAddress((void**)&p_x1h, g_x1h);
    cudaGetSymbolAddress((void**)&p_x2h, g_x2h);
    cudaGetSymbolAddress((void**)&p_x3h, g_x3h);
    cudaGetSymbolAddress((void**)&p_fcwh, g_fcwh);
    __half *wc1, *wd1, *wc2, *wd2;
    cudaGetSymbolAddress((void**)&wc1, g_wc1);
    cudaGetSymbolAddress((void**)&wd1, g_wd1);
    cudaGetSymbolAddress((void**)&wc2, g_wc2);
    cudaGetSymbolAddress((void**)&wd2, g_wd2);

    const int SM1 = 3 * (16384 + 128 * 128 + 16384) + 1024;  // NT=128
    const int SM2 = 3 * (16384 + 64 * 128 + 16384) + 1024;   // NT=64
    const int SMF = 80 * 128 + 128 * 128;
    cudaFuncSetAttribute(tcn_mma_kernel<128, 3, 512, 128>,
                         cudaFuncAttributeMaxDynamicSharedMemorySize, SM1);
    cudaFuncSetAttribute(tcn_mma_kernel<512, 9, 128, 64>,
                         cudaFuncAttributeMaxDynamicSharedMemorySize, SM2);
    cudaFuncSetAttribute(fc_mma_kernel,
                         cudaFuncAttributeMaxDynamicSharedMemorySize, SMF);

    // one fused setup launch (init + detect + out bias + all weight prep)
    k_setup<<<(Q5 + 255) / 256, 256>>>(eidx, fc_b, out,
                                       conv_w0, down_w0, conv_w1, down_w1,
                                       conv_w2, down_w2, fc_w);

    k_deg<<<(NEDGE / 4 + 255) / 256, 256>>>(eidx);
    k_h<<<(N_NODES + 127) / 128, 128>>>(x, gcn_w);
    k_scatter<<<(NEDGE + 255) / 256, 256>>>(eidx);

    tcn0_kernel<<<BATCH, 128>>>(p_x0, p_wt0, gcn_b, conv_b0, down_b0, p_x1h);
    tcn_mma_kernel<128, 3, 512, 128><<<dim3(NTOT / 128, 4), 256, SM1>>>(
        p_x1h, wc1, wd1, conv_b1, down_b1, p_x2h);
    tcn_mma_kernel<512, 9, 128, 64><<<dim3(NTOT / 64, 1), 256, SM2>>>(
        p_x2h, wc2, wd2, conv_b2, down_b2, p_x3h);

    fc_mma_kernel<<<dim3(BATCH / 128, FCF / FC_KSEG), 320, SMF>>>(p_x3h, p_fcwh, out);
}

// round 13
// speedup vs baseline: 6.5070x; 1.0065x over previous
#include <cuda_runtime.h>
#include <cuda_fp16.h>
#include <cstdint>

// ---------------- problem dims ----------------
#define N_NODES 61440
#define NEDGE   491520
#define BATCH   2048
#define TT      30
#define INCH    12
#define FCF     3840
#define FCO     72
#define NTOT    (BATCH * TT)

// ---------------- PTX helpers ----------------
__device__ __forceinline__ uint32_t smem_u32(const void* p) {
    uint32_t a;
    asm("{ .reg .u64 t; cvta.to.shared.u64 t, %1; cvt.u32.u64 %0, t; }" : "=r"(a) : "l"(p));
    return a;
}
#define LDSM_X4(r0, r1, r2, r3, addr) \
    asm volatile("ldmatrix.sync.aligned.m8n8.x4.shared.b16 {%0,%1,%2,%3}, [%4];" \
        : "=r"(r0), "=r"(r1), "=r"(r2), "=r"(r3) : "r"(addr))
#define MMA_F16(acc, a, b0_, b1_) \
    asm volatile("mma.sync.aligned.m16n8k16.row.col.f32.f16.f16.f32 " \
        "{%0,%1,%2,%3}, {%4,%5,%6,%7}, {%8,%9}, {%0,%1,%2,%3};" \
        : "+f"((acc)[0]), "+f"((acc)[1]), "+f"((acc)[2]), "+f"((acc)[3]) \
        : "r"((a)[0]), "r"((a)[1]), "r"((a)[2]), "r"((a)[3]), "r"(b0_), "r"(b1_))
#define CP_ASYNC16(dst, src) \
    asm volatile("cp.async.cg.shared.global [%0], [%1], 16;" :: "r"(dst), "l"(src))
#define CP_ASYNC16Z(dst, src, sz) \
    asm volatile("cp.async.cg.shared.global [%0], [%1], 16, %2;" :: "r"(dst), "l"(src), "r"(sz))
#define CP_COMMIT() asm volatile("cp.async.commit_group;" ::: "memory")
#define CP_WAIT2()  asm volatile("cp.async.wait_group 2;" ::: "memory")
#define CP_WAIT0()  asm volatile("cp.async.wait_group 0;" ::: "memory")
#define SWZ(row, c16) (((uint32_t)(row)) * 128u + ((((uint32_t)(c16)) ^ (((uint32_t)(row)) & 7u)) << 4))
#define RED_V4(ptr, a, b, c, d) \
    asm volatile("red.global.add.v4.f32 [%0], {%1, %2, %3, %4};" \
        :: "l"(ptr), "f"(a), "f"(b), "f"(c), "f"(d) : "memory")

// ---------------- device scratch ----------------
__device__ float g_deg [N_NODES];
__device__ __align__(16) float  g_h  [N_NODES * 12];          // [node][12]
__device__ __align__(16) float  g_x0 [N_NODES * 12];          // [node][12] = sum dinv_s*h_s
__device__ __align__(16) __half g_x1h[NTOT * 128];            // [n][128] fp16
__device__ __align__(16) __half g_x2h[NTOT * 512];            // [n][512] fp16
__device__ __align__(16) __half g_x3h[NTOT * 128];            // [n][128] fp16 (== [b][k'], k'=t*128+oc)
__device__ __align__(16) float  g_wt0 [12 * 4 * 128];
__device__ __align__(16) __half g_fcwh[80 * FCF];             // fp16 [80 rows (72 valid)][k']
__device__ int g_eflag[1];                                    // idempotent OR, never reset

// fp16 weights, [oc][k], k = j*IC + ic (j-major)
__device__ __align__(16) __half g_wc1[512 * 384];
__device__ __align__(16) __half g_wd1[512 * 128];
__device__ __align__(16) __half g_wc2[128 * 1536];
__device__ __align__(16) __half g_wd2[128 * 512];

__device__ __forceinline__ void load_edge(const void* ep, int e, int& s, int& d) {
    if (g_eflag[0]) {
        const int* p = (const int*)ep;
        s = p[e]; d = p[NEDGE + e];
    } else {
        const long long* p = (const long long*)ep;
        s = (int)p[e]; d = (int)p[NEDGE + e];
    }
}

// ---------------- fused init + detect + out-bias + weight prep + GCN-h (ONE launch) ----------------
#define P0 (N_NODES * 12)                 // x0 zero (+ deg=1 for i<N_NODES)
#define P1 (P0 + BATCH * FCO)             // out bias init
#define P2 (P1 + 2048)                    // dtype detect
#define Q0 (P2 + 6144)                    // wt0
#define Q1 (Q0 + 196608)                  // wc1
#define Q2 (Q1 + 65536)                   // wd1
#define Q3 (Q2 + 196608)                  // wc2
#define Q4 (Q3 + 65536)                   // wd2
#define Q5 (Q4 + 80 * FCF)                // fcwh
#define Q6 (Q5 + N_NODES)                 // h = x @ gcn_w^T
__global__ void k_setup(const void* __restrict__ ep,
                        const float* __restrict__ fb, float* __restrict__ out,
                        const float* __restrict__ cw0, const float* __restrict__ dw0,
                        const float* __restrict__ cw1, const float* __restrict__ dw1,
                        const float* __restrict__ cw2, const float* __restrict__ dw2,
                        const float* __restrict__ fw,
                        const float* __restrict__ x, const float* __restrict__ gw) {
    int id = blockIdx.x * blockDim.x + threadIdx.x;
    if (id < P0) {
        g_x0[id] = 0.0f;
        if (id < N_NODES) g_deg[id] = 1.0f;
    } else if (id < P1) {
        int i = id - P0;
        out[i] = fb[i % FCO];
    } else if (id < P2) {
        int i = id - P1;
        long long v = ((const long long*)ep)[i];
        if (v < 0 || v >= N_NODES) atomicOr(g_eflag, 1);
    } else if (id < Q0) {
        int t = id - P2;
        int oc = t % 128;
        int r  = t / 128;
        int j  = r % 4;
        int ic = r / 4;
        g_wt0[t] = (j < 3) ? cw0[(oc * 12 + ic) * 3 + j] : dw0[oc * 12 + ic];
    } else if (id < Q1) {
        int t = id - Q0;
        int oc = t / 384, r = t % 384, j = r / 128, ic = r % 128;
        g_wc1[t] = __float2half_rn(cw1[(oc * 128 + ic) * 3 + j]);
    } else if (id < Q2) {
        int t = id - Q1;
        g_wd1[t] = __float2half_rn(dw1[t]);
    } else if (id < Q3) {
        int t = id - Q2;
        int oc = t / 1536, r = t % 1536, j = r / 512, ic = r % 512;
        g_wc2[t] = __float2half_rn(cw2[(oc * 512 + ic) * 3 + j]);
    } else if (id < Q4) {
        int t = id - Q3;
        g_wd2[t] = __float2half_rn(dw2[t]);
    } else if (id < Q5) {
        int t  = id - Q4;       // [o_row][k'], k' = tt*128 + oc; src f = oc*30 + tt
        int kp = t % FCF;
        int o  = t / FCF;
        int oc = kp % 128;
        int tt = kp / 128;
        g_fcwh[t] = (o < FCO) ? __float2half_rn(fw[o * FCF + oc * 30 + tt])
                              : __half(0.0f);
    } else if (id < Q6) {
        int n = id - Q5;        // h[n][12] = x[n] @ gw^T (deg-independent)
        const float4* xp = (const float4*)(x + (size_t)n * 12);
        float4 a = xp[0], b = xp[1], c = xp[2];
        float xv[12] = {a.x,a.y,a.z,a.w, b.x,b.y,b.z,b.w, c.x,c.y,c.z,c.w};
        #pragma unroll
        for (int o = 0; o < 12; ++o) {
            float acc = 0.0f;
            #pragma unroll
            for (int i = 0; i < 12; ++i)
                acc = fmaf(xv[i], __ldg(&gw[o * 12 + i]), acc);
            g_h[n * 12 + o] = acc;
        }
    }
}

// ---------------- GCN edge kernels ----------------
__global__ void k_deg(const void* __restrict__ ep) {
    int t = blockIdx.x * blockDim.x + threadIdx.x;
    if (t * 4 >= NEDGE) return;
    int d0, d1, d2, d3;
    if (g_eflag[0]) {
        const int4* p = (const int4*)((const int*)ep + NEDGE);
        int4 v = p[t];
        d0 = v.x; d1 = v.y; d2 = v.z; d3 = v.w;
    } else {
        const longlong2* p = (const longlong2*)((const long long*)ep + NEDGE);
        longlong2 a = p[2 * t], b = p[2 * t + 1];
        d0 = (int)a.x; d1 = (int)a.y; d2 = (int)b.x; d3 = (int)b.y;
    }
    atomicAdd(&g_deg[d0], 1.0f);
    atomicAdd(&g_deg[d1], 1.0f);
    atomicAdd(&g_deg[d2], 1.0f);
    atomicAdd(&g_deg[d3], 1.0f);
}

// scatter adds rsqrt(deg[s]) * h[s]; dinv[d] factor deferred to tcn0.
__global__ void k_scatter(const void* __restrict__ ep) {
    int e0 = (blockIdx.x * blockDim.x + threadIdx.x) * 2;
    if (e0 >= NEDGE) return;
    int s0, d0, s1, d1;
    load_edge(ep, e0,     s0, d0);
    load_edge(ep, e0 + 1, s1, d1);
    float nm0 = rsqrtf(g_deg[s0]);
    float nm1 = rsqrtf(g_deg[s1]);
    const float4* hp0 = (const float4*)(g_h + (size_t)s0 * 12);
    const float4* hp1 = (const float4*)(g_h + (size_t)s1 * 12);
    float4 a0 = hp0[0], b0 = hp0[1], c0 = hp0[2];
    float4 a1 = hp1[0], b1 = hp1[1], c1 = hp1[2];
    float* base0 = g_x0 + (size_t)d0 * 12;
    float* base1 = g_x0 + (size_t)d1 * 12;
    RED_V4(base0,     nm0 * a0.x, nm0 * a0.y, nm0 * a0.z, nm0 * a0.w);
    RED_V4(base0 + 4, nm0 * b0.x, nm0 * b0.y, nm0 * b0.z, nm0 * b0.w);
    RED_V4(base0 + 8, nm0 * c0.x, nm0 * c0.y, nm0 * c0.z, nm0 * c0.w);
    RED_V4(base1,     nm1 * a1.x, nm1 * a1.y, nm1 * a1.z, nm1 * a1.w);
    RED_V4(base1 + 4, nm1 * b1.x, nm1 * b1.y, nm1 * b1.z, nm1 * b1.w);
    RED_V4(base1 + 8, nm1 * c1.x, nm1 * c1.y, nm1 * c1.z, nm1 * c1.w);
}

// ---------------- block 0: scalar TCN (GCN finalize fused) -> fp16 [n][128] ----------------
__global__ __launch_bounds__(128)
void tcn0_kernel(const float* __restrict__ Xin, const float* __restrict__ wt,
                 const float* __restrict__ gb,
                 const float* __restrict__ cb, const float* __restrict__ db,
                 __half* __restrict__ X1h) {
    __shared__ float xs[12 * TT];
    __shared__ __half st[TT * 128];
    int b  = blockIdx.x;
    int oc = threadIdx.x;

    // x0 = sum dinv_s*h_s; finalize GCN: xs = di*(x0 + di*h) + gcn_b, transpose into xs[ic][t]
    if (threadIdx.x < 90) {
        int nd = threadIdx.x / 3, q = threadIdx.x - nd * 3;
        int node = b * TT + nd;
        float di = rsqrtf(g_deg[node]);
        float4 xv = ((const float4*)(Xin + (size_t)node * 12))[q];
        float4 hv = ((const float4*)(g_h + (size_t)node * 12))[q];
        const float* xf = (const float*)&xv;
        const float* hf = (const float*)&hv;
        #pragma unroll
        for (int c = 0; c < 4; ++c) {
            int ic = q * 4 + c;
            xs[ic * TT + nd] = di * (xf[c] + di * hf[c]) + __ldg(&gb[ic]);
        }
    }
    __syncthreads();

    float accC[TT], accR[TT];
    #pragma unroll
    for (int t = 0; t < TT; ++t) { accC[t] = 0.0f; accR[t] = 0.0f; }

    #pragma unroll
    for (int ic = 0; ic < 12; ++ic) {
        const float* wp = wt + (size_t)(ic * 4) * 128 + oc;
        float w0 = __ldg(wp);
        float w1 = __ldg(wp + 128);
        float w2 = __ldg(wp + 256);
        float wd = __ldg(wp + 384);
        #pragma unroll
        for (int t = 0; t < TT; ++t) {
            float xv = xs[ic * TT + t];
            accC[t] = fmaf(w2, xv, accC[t]);
            if (t + 1 < TT) accC[t + 1] = fmaf(w1, xv, accC[t + 1]);
            if (t + 2 < TT) accC[t + 2] = fmaf(w0, xv, accC[t + 2]);
            accR[t] = fmaf(wd, xv, accR[t]);
        }
    }
    float bc = __ldg(&cb[oc]);
    float bd = __ldg(&db[oc]);
    #pragma unroll
    for (int t = 0; t < TT; ++t) {
        float o1 = fmaxf(accC[t] + bc, 0.0f);
        st[t * 128 + oc] = __float2half_rn(fmaxf(o1 + accR[t] + bd, 0.0f));
    }
    __syncthreads();
    const uint32_t* sp = (const uint32_t*)st;
    uint32_t* dp = (uint32_t*)(X1h + (size_t)b * TT * 128);
    for (int i = threadIdx.x; i < TT * 64; i += 128) dp[i] = sp[i];
}

// ---------------- TCN blocks 1/2: 3-stage pipelined fp16 mma GEMM ----------------
template<int IC, int DIL, int OCTOT, int NT>
__global__ __launch_bounds__(256, 1)
void tcn_mma_kernel(const __half* __restrict__ Act,
                    const __half* __restrict__ Wc, const __half* __restrict__ Wd,
                    const float* __restrict__ cb, const float* __restrict__ db,
                    __half* __restrict__ Xout) {
    extern __shared__ char smem[];
    const uint32_t sb = smem_u32(smem);
    const int tid  = threadIdx.x;
    const int wid  = tid >> 5;
    const int lane = tid & 31;

    constexpr int KC  = 3 * IC;
    constexpr int NCH = KC / 64;
    constexpr int J2  = 2 * IC / 64;
    constexpr int GN  = NT / 32;
    constexpr int FN  = NT / 16;
    constexpr uint32_t OFF_B  = 16384;
    constexpr uint32_t OFF_AD = 16384 + NT * 128;
    constexpr uint32_t STAGE  = OFF_AD + 16384;
    const uint32_t AUX = 3 * STAGE;

    const int n0    = blockIdx.x * NT;
    const int mtile = blockIdx.y;

    float* bcS = (float*)(smem + AUX);
    float* bdS = (float*)(smem + AUX + 512);
    if (tid < 128) {
        bcS[tid] = cb[mtile * 128 + tid];
        bdS[tid] = db[mtile * 128 + tid];
    }

    const int frow = tid >> 3;
    const int fc16 = tid & 7;

    auto fill = [&](int ch, int stg) {
        const uint32_t base = sb + stg * STAGE;
        const int k0 = ch * 64;
        const int j  = k0 / IC;
        const int ic0 = k0 - j * IC;
        const int shift = (2 - j) * DIL;
        {
            const __half* Wp = Wc + (size_t)(mtile * 128) * KC + k0 + fc16 * 8;
            #pragma unroll
            for (int r2 = 0; r2 < 4; ++r2) {
                int row = frow + r2 * 32;
                CP_ASYNC16(base + SWZ(row, fc16), Wp + (size_t)row * KC);
            }
        }
        {
            #pragma unroll
            for (int r2 = 0; r2 < NT / 32; ++r2) {
                int row  = frow + r2 * 32;
                int ncol = n0 + row;
                int bb   = ncol / 30;
                int tt   = ncol - bb * 30;
                int tsrc = tt - shift;
                uint32_t sz = (tsrc >= 0) ? 16u : 0u;
                int ts = tsrc >= 0 ? tsrc : 0;
                const __half* s = Act + ((size_t)(bb * 30 + ts) * IC + ic0 + fc16 * 8);
                CP_ASYNC16Z(base + OFF_B + SWZ(row, fc16), s, sz);
            }
        }
        if (ch >= J2) {
            const int kd0 = k0 - 2 * IC;
            const __half* Wp = Wd + (size_t)(mtile * 128) * IC + kd0 + fc16 * 8;
            #pragma unroll
            for (int r2 = 0; r2 < 4; ++r2) {
                int row = frow + r2 * 32;
                CP_ASYNC16(base + OFF_AD + SWZ(row, fc16), Wp + (size_t)row * IC);
            }
        }
    };

    float accC[2][FN][4], accD[2][FN][4];
    #pragma unroll
    for (int i = 0; i < 2; ++i)
        #pragma unroll
        for (int j = 0; j < FN; ++j)
            #pragma unroll
            for (int r = 0; r < 4; ++r) { accC[i][j][r] = 0.0f; accD[i][j][r] = 0.0f; }

    const int warpM = wid & 3;
    const int warpN = wid >> 2;
    const int arL = lane & 15;
    const int acL = lane >> 4;
    const int brL = (lane & 7) + ((lane >> 4) << 3);
    const int bcL = (lane >> 3) & 1;

    fill(0, 0);
    CP_COMMIT();
    if (NCH > 1) fill(1, 1);
    CP_COMMIT();

    int stg = 0;
    #pragma unroll 1
    for (int ch = 0; ch < NCH; ++ch) {
        if (ch + 2 < NCH) {
            int s2 = stg + 2; if (s2 >= 3) s2 -= 3;
            fill(ch + 2, s2);
        }
        CP_COMMIT();
        CP_WAIT2();
        __syncthreads();

        const uint32_t base = sb + stg * STAGE;
        const bool dn = (ch >= J2);

        #pragma unroll
        for (int ks = 0; ks < 4; ++ks) {
            uint32_t aq[2][4];
            #pragma unroll
            for (int fm = 0; fm < 2; ++fm) {
                int r = warpM * 32 + fm * 16 + arL;
                uint32_t ad = base + SWZ(r, ks * 2 + acL);
                LDSM_X4(aq[fm][0], aq[fm][1], aq[fm][2], aq[fm][3], ad);
            }
            uint32_t bq[GN][4];
            #pragma unroll
            for (int gn = 0; gn < GN; ++gn) {
                int r = warpN * (NT / 2) + gn * 16 + brL;
                uint32_t bd_ = base + OFF_B + SWZ(r, ks * 2 + bcL);
                LDSM_X4(bq[gn][0], bq[gn][1], bq[gn][2], bq[gn][3], bd_);
            }
            #pragma unroll
            for (int fm = 0; fm < 2; ++fm)
                #pragma unroll
                for (int gn = 0; gn < GN; ++gn) {
                    MMA_F16(accC[fm][2 * gn],     aq[fm], bq[gn][0], bq[gn][1]);
                    MMA_F16(accC[fm][2 * gn + 1], aq[fm], bq[gn][2], bq[gn][3]);
                }
            if (dn) {
                uint32_t dq[2][4];
                #pragma unroll
                for (int fm = 0; fm < 2; ++fm) {
                    int r = warpM * 32 + fm * 16 + arL;
                    uint32_t ad = base + OFF_AD + SWZ(r, ks * 2 + acL);
                    LDSM_X4(dq[fm][0], dq[fm][1], dq[fm][2], dq[fm][3], ad);
                }
                #pragma unroll
                for (int fm = 0; fm < 2; ++fm)
                    #pragma unroll
                    for (int gn = 0; gn < GN; ++gn) {
                        MMA_F16(accD[fm][2 * gn],     dq[fm], bq[gn][0], bq[gn][1]);
                        MMA_F16(accD[fm][2 * gn + 1], dq[fm], bq[gn][2], bq[gn][3]);
                    }
            }
        }
        __syncthreads();
        if (++stg == 3) stg = 0;
    }

    // ---- epilogue: regs -> smem [n][oc] -> coalesced fp16 STG ----
    float* resBuf = (float*)smem;  // [NT n][129 pitch]
    #pragma unroll
    for (int fm = 0; fm < 2; ++fm) {
        int mloc = warpM * 32 + fm * 16 + (lane >> 2);
        #pragma unroll
        for (int fn = 0; fn < FN; ++fn) {
            int nloc = warpN * (NT / 2) + fn * 8 + ((lane & 3) << 1);
            #pragma unroll
            for (int r = 0; r < 4; ++r) {
                int m = mloc + ((r >> 1) << 3);
                int n = nloc + (r & 1);
                float c = fmaxf(accC[fm][fn][r] + bcS[m], 0.0f);
                float v = fmaxf(c + accD[fm][fn][r] + bdS[m], 0.0f);
                resBuf[n * 129 + m] = v;
            }
        }
    }
    __syncthreads();
    const int ocg0 = mtile * 128;
    #pragma unroll 1
    for (int idx = tid; idx < NT * 64; idx += 256) {
        int n = idx >> 6, op = idx & 63;
        __half2 h = __floats2half2_rn(resBuf[n * 129 + 2 * op], resBuf[n * 129 + 2 * op + 1]);
        *(__half2*)(Xout + ((size_t)(n0 + n) * OCTOT + ocg0 + 2 * op)) = h;
    }
}

// ---------------- FC via fp16 MMA ----------------
#define FC_KSEG 320
__global__ __launch_bounds__(320)
void fc_mma_kernel(const __half* __restrict__ X, const __half* __restrict__ W,
                   float* __restrict__ out) {
    extern __shared__ char smem[];
    const uint32_t sb = smem_u32(smem);
    const uint32_t OFF_BX = 80 * 128;
    const int tid  = threadIdx.x;
    const int wid  = tid >> 5;
    const int lane = tid & 31;

    const int n0 = blockIdx.x * 128;
    const int kbase = blockIdx.y * FC_KSEG;

    const int warpM = wid % 5;
    const int warpN = wid / 5;
    const int arL = lane & 15;
    const int acL = lane >> 4;
    const int brL = (lane & 7) + ((lane >> 4) << 3);
    const int bcL = (lane >> 3) & 1;

    float acc[8][4];
    #pragma unroll
    for (int j = 0; j < 8; ++j)
        #pragma unroll
        for (int r = 0; r < 4; ++r) acc[j][r] = 0.0f;

    #pragma unroll 1
    for (int ch = 0; ch < 5; ++ch) {
        const int k0 = kbase + ch * 64;
        __syncthreads();
        for (int s = tid; s < 80 * 8; s += 320) {
            int row = s >> 3, c16 = s & 7;
            CP_ASYNC16(sb + SWZ(row, c16), W + (size_t)row * FCF + k0 + c16 * 8);
        }
        for (int s = tid; s < 128 * 8; s += 320) {
            int row = s >> 3, c16 = s & 7;
            CP_ASYNC16(sb + OFF_BX + SWZ(row, c16),
                       X + (size_t)(n0 + row) * FCF + k0 + c16 * 8);
        }
        CP_COMMIT();
        CP_WAIT0();
        __syncthreads();

        #pragma unroll
        for (int ks = 0; ks < 4; ++ks) {
            uint32_t aq[4];
            {
                int r = warpM * 16 + arL;
                uint32_t ad = sb + SWZ(r, ks * 2 + acL);
                LDSM_X4(aq[0], aq[1], aq[2], aq[3], ad);
            }
            uint32_t bq[4][4];
            #pragma unroll
            for (int gn = 0; gn < 4; ++gn) {
                int r = warpN * 64 + gn * 16 + brL;
                uint32_t bd_ = sb + OFF_BX + SWZ(r, ks * 2 + bcL);
                LDSM_X4(bq[gn][0], bq[gn][1], bq[gn][2], bq[gn][3], bd_);
            }
            #pragma unroll
            for (int gn = 0; gn < 4; ++gn) {
                MMA_F16(acc[2 * gn],     aq, bq[gn][0], bq[gn][1]);
                MMA_F16(acc[2 * gn + 1], aq, bq[gn][2], bq[gn][3]);
            }
        }
    }

    #pragma unroll
    for (int fn = 0; fn < 8; ++fn) {
        int nloc = warpN * 64 + fn * 8 + ((lane & 3) << 1);
        #pragma unroll
        for (int r = 0; r < 4; ++r) {
            int m = warpM * 16 + (lane >> 2) + ((r >> 1) << 3);
            int n = nloc + (r & 1);
            if (m < FCO)
                atomicAdd(&out[(size_t)(n0 + n) * FCO + m], acc[fn][r]);
        }
    }
}

// ---------------- launch ----------------
extern "C" void kernel_launch(void* const* d_in, const int* in_sizes, int n_in,
                              void* d_out, int out_size) {
    const float* x       = (const float*)d_in[0];
    const void*  eidx    = d_in[1];
    const float* gcn_w   = (const float*)d_in[2];
    const float* gcn_b   = (const float*)d_in[3];
    const float* conv_w0 = (const float*)d_in[4];
    const float* conv_b0 = (const float*)d_in[5];
    const float* down_w0 = (const float*)d_in[6];
    const float* down_b0 = (const float*)d_in[7];
    const float* conv_w1 = (const float*)d_in[8];
    const float* conv_b1 = (const float*)d_in[9];
    const float* down_w1 = (const float*)d_in[10];
    const float* down_b1 = (const float*)d_in[11];
    const float* conv_w2 = (const float*)d_in[12];
    const float* conv_b2 = (const float*)d_in[13];
    const float* down_w2 = (const float*)d_in[14];
    const float* down_b2 = (const float*)d_in[15];
    const float* fc_w    = (const float*)d_in[16];
    const float* fc_b    = (const float*)d_in[17];
    float* out = (float*)d_out;

    float *p_wt0, *p_x0;
    cudaGetSymbolAddress((void**)&p_wt0, g_wt0);
    cudaGetSymbolAddress((void**)&p_x0, g_x0);
    __half *p_x1h, *p_x2h, *p_x3h, *p_fcwh;
    cudaGetSymbolAddress((void**)&p_x1h, g_x1h);
    cudaGetSymbolAddress((void**)&p_x2h, g_x2h);
    cudaGetSymbolAddress((void**)&p_x3h, g_x3h);
    cudaGetSymbolAddress((void**)&p_fcwh, g_fcwh);
    __half *wc1, *wd1, *wc2, *wd2;
    cudaGetSymbolAddress((void**)&wc1, g_wc1);
    cudaGetSymbolAddress((void**)&wd1, g_wd1);
    cudaGetSymbolAddress((void**)&wc2, g_wc2);
    cudaGetSymbolAddress((void**)&wd2, g_wd2);

    const int SM1 = 3 * (16384 + 128 * 128 + 16384) + 1024;  // NT=128
    const int SM2 = 3 * (16384 + 64 * 128 + 16384) + 1024;   // NT=64
    const int SMF = 80 * 128 + 128 * 128;
    cudaFuncSetAttribute(tcn_mma_kernel<128, 3, 512, 128>,
                         cudaFuncAttributeMaxDynamicSharedMemorySize, SM1);
    cudaFuncSetAttribute(tcn_mma_kernel<512, 9, 128, 64>,
                         cudaFuncAttributeMaxDynamicSharedMemorySize, SM2);
    cudaFuncSetAttribute(fc_mma_kernel,
                         cudaFuncAttributeMaxDynamicSharedMemorySize, SMF);

    // one fused setup launch (init + detect + out bias + weight prep + GCN h)
    k_setup<<<(Q6 + 255) / 256, 256>>>(eidx, fc_b, out,
                                       conv_w0, down_w0, conv_w1, down_w1,
                                       conv_w2, down_w2, fc_w, x, gcn_w);

    k_deg<<<(NEDGE / 4 + 255) / 256, 256>>>(eidx);
    k_scatter<<<(NEDGE / 2 + 255) / 256, 256>>>(eidx);

    tcn0_kernel<<<BATCH, 128>>>(p_x0, p_wt0, gcn_b, conv_b0, down_b0, p_x1h);
    tcn_mma_kernel<128, 3, 512, 128><<<dim3(NTOT / 128, 4), 256, SM1>>>(
        p_x1h, wc1, wd1, conv_b1, down_b1, p_x2h);
    tcn_mma_kernel<512, 9, 128, 64><<<dim3(NTOT / 64, 1), 256, SM2>>>(
        p_x2h, wc2, wd2, conv_b2, down_b2, p_x3h);

    fc_mma_kernel<<<dim3(BATCH / 128, FCF / FC_KSEG), 320, SMF>>>(p_x3h, p_fcwh, out);
}